// round 11
// baseline (speedup 1.0000x reference)
#include <cuda_runtime.h>
#include <cuda_bf16.h>
#include <math.h>
#include <stdint.h>

// Problem constants
#define B_    2
#define S_    2048
#define DIM_  2048
#define NH_   32
#define NKV_  8
#define HD_   64
#define M_    (B_ * S_)        // 4096 rows
#define KT_   64               // K tiles (2048/32)
#define TILE_E 5120            // elems per packed 128x32 tile (LDA=40 pitch)

#define WK_OFF ((size_t)16 * KT_ * TILE_E)
#define WV_OFF ((size_t)20 * KT_ * TILE_E)

// ---------------------------------------------------------------------------
// Scratch (static device globals — no allocation allowed)
// ---------------------------------------------------------------------------
__device__ int g_dstart[B_ * 8];

// packed-tile bf16 hi/lo GEMM operands  [tile][128*40]
__device__ __nv_bfloat16 g_xph[32 * KT_ * TILE_E], g_xpl[32 * KT_ * TILE_E];
__device__ __nv_bfloat16 g_wph[24 * KT_ * TILE_E], g_wpl[24 * KT_ * TILE_E];
__device__ __nv_bfloat16 g_woph[16 * KT_ * TILE_E], g_wopl[16 * KT_ * TILE_E];
__device__ __nv_bfloat16 g_cph[32 * KT_ * TILE_E], g_cpl[32 * KT_ * TILE_E];
// flash inputs (row-major bf16 hi/lo, post-rope)
__device__ __nv_bfloat16 g_qbh[M_ * 2048], g_qbl[M_ * 2048];
__device__ __nv_bfloat16 g_kbh[M_ * 512],  g_kbl[M_ * 512];
__device__ __nv_bfloat16 g_vbh[M_ * 512],  g_vbl[M_ * 512];

// ---------------------------------------------------------------------------
// PTX helpers
// ---------------------------------------------------------------------------
__device__ __forceinline__ uint32_t smem_u32(const void* p) {
    uint32_t a;
    asm("{ .reg .u64 t; cvta.to.shared.u64 t, %1; cvt.u32.u64 %0, t; }"
        : "=r"(a) : "l"(p));
    return a;
}
__device__ __forceinline__ void cp16(uint32_t dst, const void* src) {
    asm volatile("cp.async.cg.shared.global [%0], [%1], 16;"
                 :: "r"(dst), "l"(src));
}
__device__ __forceinline__ void cp_commit() {
    asm volatile("cp.async.commit_group;");
}
template<int N>
__device__ __forceinline__ void cp_wait() {
    asm volatile("cp.async.wait_group %0;" :: "n"(N));
}
__device__ __forceinline__ void ldm4(uint32_t* r, uint32_t a) {
    asm volatile("ldmatrix.sync.aligned.m8n8.x4.shared.b16 {%0,%1,%2,%3}, [%4];"
        : "=r"(r[0]), "=r"(r[1]), "=r"(r[2]), "=r"(r[3]) : "r"(a));
}
__device__ __forceinline__ void ldm4t(uint32_t* r, uint32_t a) {
    asm volatile("ldmatrix.sync.aligned.m8n8.x4.trans.shared.b16 {%0,%1,%2,%3}, [%4];"
        : "=r"(r[0]), "=r"(r[1]), "=r"(r[2]), "=r"(r[3]) : "r"(a));
}
__device__ __forceinline__ void mma16816(float* c, const uint32_t* a,
                                         uint32_t b0, uint32_t b1) {
    asm volatile(
        "mma.sync.aligned.m16n8k16.row.col.f32.bf16.bf16.f32 "
        "{%0,%1,%2,%3}, {%4,%5,%6,%7}, {%8,%9}, {%0,%1,%2,%3};"
        : "+f"(c[0]), "+f"(c[1]), "+f"(c[2]), "+f"(c[3])
        : "r"(a[0]), "r"(a[1]), "r"(a[2]), "r"(a[3]), "r"(b0), "r"(b1));
}
__device__ __forceinline__ void mbar_init(uint32_t mbar, uint32_t cnt) {
    asm volatile("mbarrier.init.shared.b64 [%0], %1;" :: "r"(mbar), "r"(cnt) : "memory");
}
__device__ __forceinline__ void mbar_expect(uint32_t mbar, uint32_t bytes) {
    asm volatile("mbarrier.arrive.expect_tx.shared.b64 _, [%0], %1;"
                 :: "r"(mbar), "r"(bytes) : "memory");
}
__device__ __forceinline__ void mbar_wait(uint32_t mbar, uint32_t phase) {
    asm volatile(
        "{\n .reg .pred P;\n"
        "W_%=:\n"
        " mbarrier.try_wait.parity.acquire.cta.shared::cta.b64 P, [%0], %1, 0x989680;\n"
        " @P bra.uni D_%=;\n bra.uni W_%=;\n"
        "D_%=:\n}"
        :: "r"(mbar), "r"(phase) : "memory");
}
__device__ __forceinline__ void bulk_g2s(uint32_t dst, const void* src,
                                         uint32_t bytes, uint32_t mbar) {
    asm volatile(
        "cp.async.bulk.shared::cluster.global.mbarrier::complete_tx::bytes "
        "[%0], [%1], %2, [%3];"
        :: "r"(dst), "l"(src), "r"(bytes), "r"(mbar) : "memory");
}
__device__ __forceinline__ void fence_proxy_async_cta() {
    asm volatile("fence.proxy.async.shared::cta;" ::: "memory");
}
union BF2U { __nv_bfloat162 b; uint32_t u; };
__device__ __forceinline__ uint32_t packsplit(float x, float y, uint32_t& lo) {
    __nv_bfloat16 hx = __float2bfloat16(x), hy = __float2bfloat16(y);
    BF2U H, L;
    H.b.x = hx; H.b.y = hy;
    L.b.x = __float2bfloat16(x - __bfloat162float(hx));
    L.b.y = __float2bfloat16(y - __bfloat162float(hy));
    lo = L.u;
    return H.u;
}

// ---------------------------------------------------------------------------
// Fused pack: fp32 [R,2048] row-major -> packed-tile bf16 hi/lo, 5 tensors,
// plus doc-start scan.
// ---------------------------------------------------------------------------
__global__ void pack_all(const float* __restrict__ x,
                         const float* __restrict__ wq,
                         const float* __restrict__ wk,
                         const float* __restrict__ wv,
                         const float* __restrict__ wo,
                         const int* __restrict__ doc,
                         __nv_bfloat16* __restrict__ xph, __nv_bfloat16* __restrict__ xpl,
                         __nv_bfloat16* __restrict__ wph, __nv_bfloat16* __restrict__ wpl,
                         __nv_bfloat16* __restrict__ woph, __nv_bfloat16* __restrict__ wopl)
{
    int i = blockIdx.x * blockDim.x + threadIdx.x;
    const float* src;
    __nv_bfloat16 *hi, *lo;
    int li;
    if (i < 1048576)      { src = x;  hi = xph;           lo = xpl;           li = i; }
    else if (i < 1572864) { src = wq; hi = wph;           lo = wpl;           li = i - 1048576; }
    else if (i < 1703936) { src = wk; hi = wph + WK_OFF;  lo = wpl + WK_OFF;  li = i - 1572864; }
    else if (i < 1835008) { src = wv; hi = wph + WV_OFF;  lo = wpl + WV_OFF;  li = i - 1703936; }
    else if (i < 2359296) { src = wo; hi = woph;          lo = wopl;          li = i - 1835008; }
    else if (i < 2359296 + B_ * S_) {
        int li2 = i - 2359296;
        int s = li2 & (S_ - 1);
        int d = doc[li2];
        if (s == 0 || doc[li2 - 1] != d) g_dstart[(li2 >> 11) * 8 + d] = s;
        return;
    } else return;

    int r  = li >> 8;          // kchunks = 256
    int kc = li & 255;
    const float4* s = (const float4*)src + (size_t)li * 2;
    float4 v0 = s[0], v1 = s[1];
    uint32_t l0, l1, l2, l3;
    uint32_t h0 = packsplit(v0.x, v0.y, l0);
    uint32_t h1 = packsplit(v0.z, v0.w, l1);
    uint32_t h2 = packsplit(v1.x, v1.y, l2);
    uint32_t h3 = packsplit(v1.z, v1.w, l3);
    size_t off = ((size_t)(r >> 7) * KT_ + (kc >> 2)) * TILE_E
               + (r & 127) * 40 + (kc & 3) * 8;
    *(uint4*)(hi + off) = make_uint4(h0, h1, h2, h3);
    *(uint4*)(lo + off) = make_uint4(l0, l1, l2, l3);
}

// ---------------------------------------------------------------------------
// Packed-tile bf16-split GEMM: C = A*B^T.
// CTA tile 256(M) x 128(N), 256 threads, 8 warps of 64x64 (wm=w&3, wn=w>>2).
// 3-stage cp.async.bulk pipeline (stage = Ah x2 | Al x2 | Bh | Bl = 60KB).
// MODE 0: fp32 row-major C (O projection).
// MODE 1: fused QKV epilogue (RoPE + scale + hi/lo split, row-major out).
// ---------------------------------------------------------------------------
#define STG_E (6 * TILE_E)     // stage elems

template<int MODE>
__global__ __launch_bounds__(256, 1) void gemm_pk(
    const __nv_bfloat16* __restrict__ Ah, const __nv_bfloat16* __restrict__ Al,
    const __nv_bfloat16* __restrict__ Bh, const __nv_bfloat16* __restrict__ Bl,
    float* __restrict__ C, int N, int Ktiles,
    const float* __restrict__ cs, const float* __restrict__ sn,
    __nv_bfloat16* __restrict__ qbh, __nv_bfloat16* __restrict__ qbl,
    __nv_bfloat16* __restrict__ kbh, __nv_bfloat16* __restrict__ kbl,
    __nv_bfloat16* __restrict__ vbh, __nv_bfloat16* __restrict__ vbl)
{
    extern __shared__ __align__(128) __nv_bfloat16 smd[];   // 3 * STG_E
    __shared__ __align__(8) uint64_t mb[3];

    const int tid = threadIdx.x, lane = tid & 31, w = tid >> 5;
    const int wm = w & 3, wn = w >> 2;     // 4 m-warps x 2 n-warps (64x64 tiles)

    const uint32_t mbar[3] = { smem_u32(&mb[0]), smem_u32(&mb[1]), smem_u32(&mb[2]) };
    if (tid == 0) { mbar_init(mbar[0], 1); mbar_init(mbar[1], 1); mbar_init(mbar[2], 1); }
    __syncthreads();

    const size_t tA0 = (size_t)(blockIdx.y * 2)     * Ktiles;
    const size_t tA1 = (size_t)(blockIdx.y * 2 + 1) * Ktiles;
    const size_t tB  = (size_t)blockIdx.x * Ktiles;

    auto issue = [&](int kt, int buf) {
        uint32_t s0 = smem_u32(smd + buf * STG_E);
        const uint32_t TB = TILE_E * 2;    // bytes per tile
        mbar_expect(mbar[buf], 6 * TB);
        bulk_g2s(s0,          Ah + (tA0 + kt) * TILE_E, TB, mbar[buf]);
        bulk_g2s(s0 + TB,     Ah + (tA1 + kt) * TILE_E, TB, mbar[buf]);
        bulk_g2s(s0 + 2 * TB, Al + (tA0 + kt) * TILE_E, TB, mbar[buf]);
        bulk_g2s(s0 + 3 * TB, Al + (tA1 + kt) * TILE_E, TB, mbar[buf]);
        bulk_g2s(s0 + 4 * TB, Bh + (tB  + kt) * TILE_E, TB, mbar[buf]);
        bulk_g2s(s0 + 5 * TB, Bl + (tB  + kt) * TILE_E, TB, mbar[buf]);
    };
    if (tid == 0) { issue(0, 0); issue(1, 1); issue(2, 2); }

    float acc[4][8][4];
#pragma unroll
    for (int i = 0; i < 4; ++i)
#pragma unroll
        for (int j = 0; j < 8; ++j)
#pragma unroll
            for (int e = 0; e < 4; ++e) acc[i][j][e] = 0.f;

    int ph[3] = {0, 0, 0};
    int buf = 0;

    for (int kt = 0; kt < Ktiles; ++kt) {
        if (buf == 0)      { mbar_wait(mbar[0], ph[0]); ph[0] ^= 1; }
        else if (buf == 1) { mbar_wait(mbar[1], ph[1]); ph[1] ^= 1; }
        else               { mbar_wait(mbar[2], ph[2]); ph[2] ^= 1; }

        const __nv_bfloat16* st = smd + buf * STG_E;
        const __nv_bfloat16* A0 = st;                  // Ah (2 tiles)
        const __nv_bfloat16* A1 = st + 2 * TILE_E;     // Al (2 tiles)
        const __nv_bfloat16* B0 = st + 4 * TILE_E;     // Bh
        const __nv_bfloat16* B1 = st + 5 * TILE_E;     // Bl

#pragma unroll
        for (int kk = 0; kk < 2; ++kk) {
            const int achk = kk * 2 + (lane >> 4);
            uint32_t ah[4][4], al[4][4];
#pragma unroll
            for (int mt = 0; mt < 4; ++mt) {
                int arow = wm * 64 + mt * 16 + (lane & 15);
                int at = arow >> 7, ar = arow & 127;
                ldm4(ah[mt], smem_u32(A0 + at * TILE_E + ar * 40 + achk * 8));
                ldm4(al[mt], smem_u32(A1 + at * TILE_E + ar * 40 + achk * 8));
            }
            const int brow = wn * 64 + (lane & 15);
#pragma unroll
            for (int nt = 0; nt < 4; ++nt) {
                uint32_t bh[4], bl[4];
                ldm4(bh, smem_u32(B0 + (brow + nt * 16) * 40 + achk * 8));
                ldm4(bl, smem_u32(B1 + (brow + nt * 16) * 40 + achk * 8));
#pragma unroll
                for (int mt = 0; mt < 4; ++mt) {
                    mma16816(acc[mt][2 * nt],     ah[mt], bh[0], bh[2]);
                    mma16816(acc[mt][2 * nt],     ah[mt], bl[0], bl[2]);
                    mma16816(acc[mt][2 * nt],     al[mt], bh[0], bh[2]);
                    mma16816(acc[mt][2 * nt + 1], ah[mt], bh[1], bh[3]);
                    mma16816(acc[mt][2 * nt + 1], ah[mt], bl[1], bl[3]);
                    mma16816(acc[mt][2 * nt + 1], al[mt], bh[1], bh[3]);
                }
            }
        }
        __syncthreads();
        if (kt + 3 < Ktiles && tid == 0) {
            fence_proxy_async_cta();
            issue(kt + 3, buf);
        }
        buf = (buf == 2) ? 0 : buf + 1;
    }

    const int brow = blockIdx.y * 256 + wm * 64;
    const int bcol = blockIdx.x * 128 + wn * 64;

    if (MODE == 0) {
        // fp32 row-major
#pragma unroll
        for (int mt = 0; mt < 4; ++mt) {
            int r0 = brow + mt * 16 + (lane >> 2);
#pragma unroll
            for (int j = 0; j < 8; ++j) {
                int col = bcol + j * 8 + (lane & 3) * 2;
                *(float2*)(C + (size_t)r0 * N + col) =
                    make_float2(acc[mt][j][0], acc[mt][j][1]);
                *(float2*)(C + (size_t)(r0 + 8) * N + col) =
                    make_float2(acc[mt][j][2], acc[mt][j][3]);
            }
        }
    } else {
        // fused QKV epilogue: rope + scale + hi/lo split, row-major out.
        __nv_bfloat16 *dh, *dl;
        int cstride, cbase;
        float scale;
        bool rope;
        if (bcol < 2048)      { dh = qbh; dl = qbl; cstride = 2048; cbase = bcol;        scale = 0.125f; rope = true; }
        else if (bcol < 2560) { dh = kbh; dl = kbl; cstride = 512;  cbase = bcol - 2048; scale = 1.0f;   rope = true; }
        else                  { dh = vbh; dl = vbl; cstride = 512;  cbase = bcol - 2560; scale = 1.0f;   rope = false; }

#pragma unroll
        for (int mt = 0; mt < 4; ++mt) {
#pragma unroll
            for (int half = 0; half < 2; ++half) {
                int row = brow + mt * 16 + (lane >> 2) + half * 8;
                int e = half * 2;                    // acc elems e, e+1
                int s = row & (S_ - 1);
                size_t obase = (size_t)row * cstride + cbase;
                if (rope) {
#pragma unroll
                    for (int j = 0; j < 4; ++j) {
                        int d = j * 8 + (lane & 3) * 2;
                        float c0  = cs[s * 32 + d],     c1  = cs[s * 32 + d + 1];
                        float sv0 = sn[s * 32 + d],     sv1 = sn[s * 32 + d + 1];
                        float x1a = acc[mt][j][e],      x1b = acc[mt][j][e + 1];
                        float x2a = acc[mt][j + 4][e],  x2b = acc[mt][j + 4][e + 1];
                        float y1a = (x1a * c0 - x2a * sv0) * scale;
                        float y1b = (x1b * c1 - x2b * sv1) * scale;
                        float y2a = (x2a * c0 + x1a * sv0) * scale;
                        float y2b = (x2b * c1 + x1b * sv1) * scale;
                        uint32_t lo;
                        uint32_t hi = packsplit(y1a, y1b, lo);
                        *(uint32_t*)(dh + obase + d) = hi;
                        *(uint32_t*)(dl + obase + d) = lo;
                        hi = packsplit(y2a, y2b, lo);
                        *(uint32_t*)(dh + obase + d + 32) = hi;
                        *(uint32_t*)(dl + obase + d + 32) = lo;
                    }
                } else {
#pragma unroll
                    for (int j = 0; j < 8; ++j) {
                        int d = j * 8 + (lane & 3) * 2;
                        uint32_t lo;
                        uint32_t hi = packsplit(acc[mt][j][e], acc[mt][j][e + 1], lo);
                        *(uint32_t*)(dh + obase + d) = hi;
                        *(uint32_t*)(dl + obase + d) = lo;
                    }
                }
            }
        }
    }
}

// ---------------------------------------------------------------------------
// Tensor-core flash attention (R8 config). Q parked in stage-1 smem -> 72KB
// -> 3 CTAs/SM.
// ---------------------------------------------------------------------------
#define LDK 72

__global__ __launch_bounds__(128, 3) void flash_tc(
    const int* __restrict__ doc,
    const __nv_bfloat16* __restrict__ qhi, const __nv_bfloat16* __restrict__ qlo,
    const __nv_bfloat16* __restrict__ khi, const __nv_bfloat16* __restrict__ klo,
    const __nv_bfloat16* __restrict__ vhi, const __nv_bfloat16* __restrict__ vlo,
    __nv_bfloat16* __restrict__ cph, __nv_bfloat16* __restrict__ cpl)
{
    extern __shared__ __align__(16) char smraw[];
    __nv_bfloat16* sT  = (__nv_bfloat16*)smraw;      // 2 stages x (Kh|Kl|Vh|Vl)
    __shared__ int qdoc[64];
    __shared__ int kdoc[2][64];

    const int tid  = threadIdx.x;
    const int lane = tid & 31;
    const int w    = tid >> 5;
    const int qb = blockIdx.x, h = blockIdx.y, b = blockIdx.z;
    const int kvh = h >> 2;
    const int q0  = qb * 64;
    const int TILE = 64 * LDK;

    __nv_bfloat16* sQh = sT + 4 * TILE;
    __nv_bfloat16* sQl = sT + 5 * TILE;

    {
        const __nv_bfloat16* srch = qhi + ((size_t)(b * S_ + q0)) * 2048 + h * 64;
        const __nv_bfloat16* srcl = qlo + ((size_t)(b * S_ + q0)) * 2048 + h * 64;
        uint32_t dh = smem_u32(sQh), dl = smem_u32(sQl);
        for (int i = tid; i < 512; i += 128) {
            int r = i >> 3, c = i & 7;
            uint32_t off = (uint32_t)(r * LDK + c * 8) * 2;
            cp16(dh + off, srch + (size_t)r * 2048 + c * 8);
            cp16(dl + off, srcl + (size_t)r * 2048 + c * 8);
        }
        if (tid < 64) qdoc[tid] = doc[b * S_ + q0 + tid];
    }
    cp_commit();

    const int kb0 = g_dstart[b * 8 + doc[b * S_ + q0]] >> 6;

    auto load_kv = [&](int kb, int buf) {
        const size_t row0 = (size_t)(b * S_ + kb * 64);
        const __nv_bfloat16* s0 = khi + row0 * 512 + kvh * 64;
        const __nv_bfloat16* s1 = klo + row0 * 512 + kvh * 64;
        const __nv_bfloat16* s2 = vhi + row0 * 512 + kvh * 64;
        const __nv_bfloat16* s3 = vlo + row0 * 512 + kvh * 64;
        uint32_t d0 = smem_u32(sT + buf * 4 * TILE);
        const uint32_t tb = (uint32_t)TILE * 2;
        for (int i = tid; i < 512; i += 128) {
            int r = i >> 3, c = i & 7;
            uint32_t off = (uint32_t)(r * LDK + c * 8) * 2;
            size_t go = (size_t)r * 512 + c * 8;
            cp16(d0 + off,          s0 + go);
            cp16(d0 + tb + off,     s1 + go);
            cp16(d0 + 2 * tb + off, s2 + go);
            cp16(d0 + 3 * tb + off, s3 + go);
        }
        if (tid < 64) kdoc[buf][tid] = doc[b * S_ + kb * 64 + tid];
    };

    load_kv(kb0, 0);
    cp_commit();
    cp_wait<1>();
    __syncthreads();

    uint32_t qah[4][4], qal[4][4];
    {
        int row = w * 16 + (lane & 15);
        int col = (lane >> 4) * 8;
#pragma unroll
        for (int s = 0; s < 4; ++s) {
            ldm4(qah[s], smem_u32(sQh + row * LDK + col + s * 16));
            ldm4(qal[s], smem_u32(sQl + row * LDK + col + s * 16));
        }
    }
    __syncthreads();   // all warps have Q frags; stage-1 may be overwritten

    const int g   = lane >> 2;
    const int r0g = q0 + w * 16 + g;
    const int r1g = r0g + 8;
    const int qd0 = qdoc[w * 16 + g];
    const int qd1 = qdoc[w * 16 + g + 8];

    float m0 = -1e30f, m1 = -1e30f, l0 = 0.f, l1 = 0.f;
    float O[8][4];
#pragma unroll
    for (int j = 0; j < 8; ++j)
#pragma unroll
        for (int e = 0; e < 4; ++e) O[j][e] = 0.f;

    for (int kb = kb0; kb <= qb; ++kb) {
        const int buf = (kb - kb0) & 1;
        cp_wait<0>();
        __syncthreads();
        if (kb < qb) { load_kv(kb + 1, buf ^ 1); cp_commit(); }

        const __nv_bfloat16* Kh = sT + buf * 4 * TILE;
        const __nv_bfloat16* Kl = Kh + TILE;
        const __nv_bfloat16* Vh = Kl + TILE;
        const __nv_bfloat16* Vl = Vh + TILE;

        float Sf[8][4];
#pragma unroll
        for (int j = 0; j < 8; ++j) {
            Sf[j][0] = Sf[j][1] = Sf[j][2] = Sf[j][3] = 0.f;
            uint32_t bh[2][4], bl[2][4];
            int row = j * 8 + (lane & 7);
            int col = (lane >> 3) * 8;
            ldm4(bh[0], smem_u32(Kh + row * LDK + col));
            ldm4(bh[1], smem_u32(Kh + row * LDK + col + 32));
            ldm4(bl[0], smem_u32(Kl + row * LDK + col));
            ldm4(bl[1], smem_u32(Kl + row * LDK + col + 32));
#pragma unroll
            for (int s = 0; s < 4; ++s) {
                int ch = s >> 1, wh = (s & 1) * 2;
                mma16816(Sf[j], qah[s], bh[ch][wh], bh[ch][wh + 1]);
                mma16816(Sf[j], qah[s], bl[ch][wh], bl[ch][wh + 1]);
                mma16816(Sf[j], qal[s], bh[ch][wh], bh[ch][wh + 1]);
            }
        }

        const int kbase = kb * 64;
#pragma unroll
        for (int j = 0; j < 8; ++j) {
            int cl  = j * 8 + (lane & 3) * 2;
            int c0g = kbase + cl, c1g = c0g + 1;
            int kd0 = kdoc[buf][cl], kd1 = kdoc[buf][cl + 1];
            if (c0g > r0g || kd0 != qd0) Sf[j][0] = -1e30f;
            if (c1g > r0g || kd1 != qd0) Sf[j][1] = -1e30f;
            if (c0g > r1g || kd0 != qd1) Sf[j][2] = -1e30f;
            if (c1g > r1g || kd1 != qd1) Sf[j][3] = -1e30f;
        }

        float t0 = -1e30f, t1 = -1e30f;
#pragma unroll
        for (int j = 0; j < 8; ++j) {
            t0 = fmaxf(t0, fmaxf(Sf[j][0], Sf[j][1]));
            t1 = fmaxf(t1, fmaxf(Sf[j][2], Sf[j][3]));
        }
        t0 = fmaxf(t0, __shfl_xor_sync(0xffffffffu, t0, 1));
        t0 = fmaxf(t0, __shfl_xor_sync(0xffffffffu, t0, 2));
        t1 = fmaxf(t1, __shfl_xor_sync(0xffffffffu, t1, 1));
        t1 = fmaxf(t1, __shfl_xor_sync(0xffffffffu, t1, 2));
        float mn0 = fmaxf(m0, t0), mn1 = fmaxf(m1, t1);
        float corr0 = __expf(m0 - mn0), corr1 = __expf(m1 - mn1);
        m0 = mn0; m1 = mn1;
        float rs0 = 0.f, rs1 = 0.f;
#pragma unroll
        for (int j = 0; j < 8; ++j) {
            Sf[j][0] = __expf(Sf[j][0] - mn0);
            Sf[j][1] = __expf(Sf[j][1] - mn0);
            Sf[j][2] = __expf(Sf[j][2] - mn1);
            Sf[j][3] = __expf(Sf[j][3] - mn1);
            rs0 += Sf[j][0] + Sf[j][1];
            rs1 += Sf[j][2] + Sf[j][3];
        }
        rs0 += __shfl_xor_sync(0xffffffffu, rs0, 1);
        rs0 += __shfl_xor_sync(0xffffffffu, rs0, 2);
        rs1 += __shfl_xor_sync(0xffffffffu, rs1, 1);
        rs1 += __shfl_xor_sync(0xffffffffu, rs1, 2);
        l0 = l0 * corr0 + rs0;
        l1 = l1 * corr1 + rs1;
#pragma unroll
        for (int j = 0; j < 8; ++j) {
            O[j][0] *= corr0; O[j][1] *= corr0;
            O[j][2] *= corr1; O[j][3] *= corr1;
        }

        uint32_t pah[4][4], pal[4][4];
#pragma unroll
        for (int s = 0; s < 4; ++s) {
            pah[s][0] = packsplit(Sf[2 * s][0],     Sf[2 * s][1],     pal[s][0]);
            pah[s][1] = packsplit(Sf[2 * s][2],     Sf[2 * s][3],     pal[s][1]);
            pah[s][2] = packsplit(Sf[2 * s + 1][0], Sf[2 * s + 1][1], pal[s][2]);
            pah[s][3] = packsplit(Sf[2 * s + 1][2], Sf[2 * s + 1][3], pal[s][3]);
        }

#pragma unroll
        for (int j = 0; j < 8; ++j) {
            uint32_t bvh[2][4], bvl[2][4];
            int vr = lane & 31;
            ldm4t(bvh[0], smem_u32(Vh + vr * LDK + j * 8));
            ldm4t(bvh[1], smem_u32(Vh + (32 + vr) * LDK + j * 8));
            ldm4t(bvl[0], smem_u32(Vl + vr * LDK + j * 8));
            ldm4t(bvl[1], smem_u32(Vl + (32 + vr) * LDK + j * 8));
#pragma unroll
            for (int s = 0; s < 4; ++s) {
                int ch = s >> 1, wh = (s & 1) * 2;
                mma16816(O[j], pah[s], bvh[ch][wh], bvh[ch][wh + 1]);
                mma16816(O[j], pah[s], bvl[ch][wh], bvl[ch][wh + 1]);
                mma16816(O[j], pal[s], bvh[ch][wh], bvh[ch][wh + 1]);
            }
        }
    }

    // ---- epilogue: write ctx in packed-tile layout ----
    float inv0 = 1.0f / l0, inv1 = 1.0f / l1;
    int grow0 = b * S_ + r0g;
    int grow1 = grow0 + 8;
#pragma unroll
    for (int j = 0; j < 8; ++j) {
        int col = h * 64 + j * 8 + (lane & 3) * 2;
        size_t tbase = ((size_t)(grow0 >> 7) * KT_ + (col >> 5)) * TILE_E
                     + ((col >> 3) & 3) * 8 + (col & 7);
        size_t o0 = tbase + (grow0 & 127) * 40;
        size_t o1 = tbase + (grow1 & 127) * 40;
        uint32_t lo0, lo1;
        uint32_t hi0 = packsplit(O[j][0] * inv0, O[j][1] * inv0, lo0);
        uint32_t hi1 = packsplit(O[j][2] * inv1, O[j][3] * inv1, lo1);
        *(uint32_t*)(cph + o0) = hi0;
        *(uint32_t*)(cpl + o0) = lo0;
        *(uint32_t*)(cph + o1) = hi1;
        *(uint32_t*)(cpl + o1) = lo1;
    }
}

// ---------------------------------------------------------------------------
// Host launcher
// ---------------------------------------------------------------------------
extern "C" void kernel_launch(void* const* d_in, const int* in_sizes, int n_in,
                              void* d_out, int out_size)
{
    const float* x   = (const float*)d_in[0];
    const float* rc  = (const float*)d_in[1];
    const float* rs  = (const float*)d_in[2];
    const int*   doc = (const int*)d_in[3];
    const float* Wq  = (const float*)d_in[4];
    const float* Wk  = (const float*)d_in[5];
    const float* Wv  = (const float*)d_in[6];
    const float* Wo  = (const float*)d_in[7];
    float* out = (float*)d_out;

    __nv_bfloat16 *xph, *xpl, *wph, *wpl, *woph, *wopl, *cph, *cpl,
                  *qbh, *qbl, *kbh, *kbl, *vbh, *vbl;
    cudaGetSymbolAddress((void**)&xph, g_xph);   cudaGetSymbolAddress((void**)&xpl, g_xpl);
    cudaGetSymbolAddress((void**)&wph, g_wph);   cudaGetSymbolAddress((void**)&wpl, g_wpl);
    cudaGetSymbolAddress((void**)&woph, g_woph); cudaGetSymbolAddress((void**)&wopl, g_wopl);
    cudaGetSymbolAddress((void**)&cph, g_cph);   cudaGetSymbolAddress((void**)&cpl, g_cpl);
    cudaGetSymbolAddress((void**)&qbh, g_qbh);   cudaGetSymbolAddress((void**)&qbl, g_qbl);
    cudaGetSymbolAddress((void**)&kbh, g_kbh);   cudaGetSymbolAddress((void**)&kbl, g_kbl);
    cudaGetSymbolAddress((void**)&vbh, g_vbh);   cudaGetSymbolAddress((void**)&vbl, g_vbl);

    const int flash_smem = 2 * 4 * 64 * LDK * (int)sizeof(__nv_bfloat16);  // 73728
    cudaFuncSetAttribute(flash_tc,
                         cudaFuncAttributeMaxDynamicSharedMemorySize, flash_smem);

    const int gemm_smem = 3 * STG_E * (int)sizeof(__nv_bfloat16);          // 184320
    cudaFuncSetAttribute(gemm_pk<0>,
                         cudaFuncAttributeMaxDynamicSharedMemorySize, gemm_smem);
    cudaFuncSetAttribute(gemm_pk<1>,
                         cudaFuncAttributeMaxDynamicSharedMemorySize, gemm_smem);

    // 1. Pack inputs + doc-start scan (one launch)
    pack_all<<<9232, 256>>>(x, Wq, Wk, Wv, Wo, doc,
                            xph, xpl, wph, wpl, woph, wopl);

    // 2. Fused QKV projection with fused RoPE/split epilogue
    {
        dim3 g(3072 / 128, M_ / 256);  // (24, 16)
        gemm_pk<1><<<g, 256, gemm_smem>>>(xph, xpl, wph, wpl, nullptr, 3072, KT_,
                                          rc, rs, qbh, qbl, kbh, kbl, vbh, vbl);
    }

    // 3. Tensor-core flash attention -> packed ctx
    {
        dim3 g(S_ / 64, NH_, B_);
        flash_tc<<<g, 128, flash_smem>>>(doc, qbh, qbl, kbh, kbl, vbh, vbl, cph, cpl);
    }

    // 4. Output projection: out = ctx @ Wo^T
    {
        dim3 g(2048 / 128, M_ / 256);  // (16, 16)
        gemm_pk<0><<<g, 256, gemm_smem>>>(cph, cpl, woph, wopl, out, 2048, KT_,
                                          nullptr, nullptr,
                                          nullptr, nullptr, nullptr, nullptr,
                                          nullptr, nullptr);
    }
}

// round 12
// speedup vs baseline: 1.0509x; 1.0509x over previous
#include <cuda_runtime.h>
#include <cuda_bf16.h>
#include <math.h>
#include <stdint.h>

// Problem constants
#define B_    2
#define S_    2048
#define DIM_  2048
#define NH_   32
#define NKV_  8
#define HD_   64
#define M_    (B_ * S_)        // 4096 rows
#define KT_   64               // K tiles (2048/32)
#define TILE_E 5120            // elems per packed 128x32 tile (LDA=40 pitch)

#define WK_OFF ((size_t)16 * KT_ * TILE_E)
#define WV_OFF ((size_t)20 * KT_ * TILE_E)

// ---------------------------------------------------------------------------
// Scratch (static device globals — no allocation allowed)
// ---------------------------------------------------------------------------
__device__ int g_dstart[B_ * 8];

// packed-tile bf16 hi/lo GEMM operands  [tile][128*40]
__device__ __nv_bfloat16 g_xph[32 * KT_ * TILE_E], g_xpl[32 * KT_ * TILE_E];
__device__ __nv_bfloat16 g_wph[24 * KT_ * TILE_E], g_wpl[24 * KT_ * TILE_E];
__device__ __nv_bfloat16 g_woph[16 * KT_ * TILE_E], g_wopl[16 * KT_ * TILE_E];
__device__ __nv_bfloat16 g_cph[32 * KT_ * TILE_E], g_cpl[32 * KT_ * TILE_E];
// flash inputs (row-major bf16 hi/lo, post-rope)
__device__ __nv_bfloat16 g_qbh[M_ * 2048], g_qbl[M_ * 2048];
__device__ __nv_bfloat16 g_kbh[M_ * 512],  g_kbl[M_ * 512];
__device__ __nv_bfloat16 g_vbh[M_ * 512],  g_vbl[M_ * 512];

// ---------------------------------------------------------------------------
// PTX helpers
// ---------------------------------------------------------------------------
__device__ __forceinline__ uint32_t smem_u32(const void* p) {
    uint32_t a;
    asm("{ .reg .u64 t; cvta.to.shared.u64 t, %1; cvt.u32.u64 %0, t; }"
        : "=r"(a) : "l"(p));
    return a;
}
__device__ __forceinline__ void cp16(uint32_t dst, const void* src) {
    asm volatile("cp.async.cg.shared.global [%0], [%1], 16;"
                 :: "r"(dst), "l"(src));
}
__device__ __forceinline__ void cp_commit() {
    asm volatile("cp.async.commit_group;");
}
template<int N>
__device__ __forceinline__ void cp_wait() {
    asm volatile("cp.async.wait_group %0;" :: "n"(N));
}
__device__ __forceinline__ void ldm4(uint32_t* r, uint32_t a) {
    asm volatile("ldmatrix.sync.aligned.m8n8.x4.shared.b16 {%0,%1,%2,%3}, [%4];"
        : "=r"(r[0]), "=r"(r[1]), "=r"(r[2]), "=r"(r[3]) : "r"(a));
}
__device__ __forceinline__ void ldm4t(uint32_t* r, uint32_t a) {
    asm volatile("ldmatrix.sync.aligned.m8n8.x4.trans.shared.b16 {%0,%1,%2,%3}, [%4];"
        : "=r"(r[0]), "=r"(r[1]), "=r"(r[2]), "=r"(r[3]) : "r"(a));
}
__device__ __forceinline__ void mma16816(float* c, const uint32_t* a,
                                         uint32_t b0, uint32_t b1) {
    asm volatile(
        "mma.sync.aligned.m16n8k16.row.col.f32.bf16.bf16.f32 "
        "{%0,%1,%2,%3}, {%4,%5,%6,%7}, {%8,%9}, {%0,%1,%2,%3};"
        : "+f"(c[0]), "+f"(c[1]), "+f"(c[2]), "+f"(c[3])
        : "r"(a[0]), "r"(a[1]), "r"(a[2]), "r"(a[3]), "r"(b0), "r"(b1));
}
__device__ __forceinline__ void mbar_init(uint32_t mbar, uint32_t cnt) {
    asm volatile("mbarrier.init.shared.b64 [%0], %1;" :: "r"(mbar), "r"(cnt) : "memory");
}
__device__ __forceinline__ void mbar_expect(uint32_t mbar, uint32_t bytes) {
    asm volatile("mbarrier.arrive.expect_tx.shared.b64 _, [%0], %1;"
                 :: "r"(mbar), "r"(bytes) : "memory");
}
__device__ __forceinline__ void mbar_wait(uint32_t mbar, uint32_t phase) {
    asm volatile(
        "{\n .reg .pred P;\n"
        "W_%=:\n"
        " mbarrier.try_wait.parity.acquire.cta.shared::cta.b64 P, [%0], %1, 0x989680;\n"
        " @P bra.uni D_%=;\n bra.uni W_%=;\n"
        "D_%=:\n}"
        :: "r"(mbar), "r"(phase) : "memory");
}
__device__ __forceinline__ void bulk_g2s(uint32_t dst, const void* src,
                                         uint32_t bytes, uint32_t mbar) {
    asm volatile(
        "cp.async.bulk.shared::cluster.global.mbarrier::complete_tx::bytes "
        "[%0], [%1], %2, [%3];"
        :: "r"(dst), "l"(src), "r"(bytes), "r"(mbar) : "memory");
}
__device__ __forceinline__ void fence_proxy_async_cta() {
    asm volatile("fence.proxy.async.shared::cta;" ::: "memory");
}
union BF2U { __nv_bfloat162 b; uint32_t u; };
__device__ __forceinline__ uint32_t packsplit(float x, float y, uint32_t& lo) {
    __nv_bfloat16 hx = __float2bfloat16(x), hy = __float2bfloat16(y);
    BF2U H, L;
    H.b.x = hx; H.b.y = hy;
    L.b.x = __float2bfloat16(x - __bfloat162float(hx));
    L.b.y = __float2bfloat16(y - __bfloat162float(hy));
    lo = L.u;
    return H.u;
}

// ---------------------------------------------------------------------------
// Fused pack: fp32 [R,2048] row-major -> packed-tile bf16 hi/lo, 5 tensors,
// plus doc-start scan.
// ---------------------------------------------------------------------------
__global__ void pack_all(const float* __restrict__ x,
                         const float* __restrict__ wq,
                         const float* __restrict__ wk,
                         const float* __restrict__ wv,
                         const float* __restrict__ wo,
                         const int* __restrict__ doc,
                         __nv_bfloat16* __restrict__ xph, __nv_bfloat16* __restrict__ xpl,
                         __nv_bfloat16* __restrict__ wph, __nv_bfloat16* __restrict__ wpl,
                         __nv_bfloat16* __restrict__ woph, __nv_bfloat16* __restrict__ wopl)
{
    int i = blockIdx.x * blockDim.x + threadIdx.x;
    const float* src;
    __nv_bfloat16 *hi, *lo;
    int li;
    if (i < 1048576)      { src = x;  hi = xph;           lo = xpl;           li = i; }
    else if (i < 1572864) { src = wq; hi = wph;           lo = wpl;           li = i - 1048576; }
    else if (i < 1703936) { src = wk; hi = wph + WK_OFF;  lo = wpl + WK_OFF;  li = i - 1572864; }
    else if (i < 1835008) { src = wv; hi = wph + WV_OFF;  lo = wpl + WV_OFF;  li = i - 1703936; }
    else if (i < 2359296) { src = wo; hi = woph;          lo = wopl;          li = i - 1835008; }
    else if (i < 2359296 + B_ * S_) {
        int li2 = i - 2359296;
        int s = li2 & (S_ - 1);
        int d = doc[li2];
        if (s == 0 || doc[li2 - 1] != d) g_dstart[(li2 >> 11) * 8 + d] = s;
        return;
    } else return;

    int r  = li >> 8;          // kchunks = 256
    int kc = li & 255;
    const float4* s = (const float4*)src + (size_t)li * 2;
    float4 v0 = s[0], v1 = s[1];
    uint32_t l0, l1, l2, l3;
    uint32_t h0 = packsplit(v0.x, v0.y, l0);
    uint32_t h1 = packsplit(v0.z, v0.w, l1);
    uint32_t h2 = packsplit(v1.x, v1.y, l2);
    uint32_t h3 = packsplit(v1.z, v1.w, l3);
    size_t off = ((size_t)(r >> 7) * KT_ + (kc >> 2)) * TILE_E
               + (r & 127) * 40 + (kc & 3) * 8;
    *(uint4*)(hi + off) = make_uint4(h0, h1, h2, h3);
    *(uint4*)(lo + off) = make_uint4(l0, l1, l2, l3);
}

// ---------------------------------------------------------------------------
// Packed-tile bf16-split GEMM: C = A*B^T.
// 256 threads, 8 warps: warp tile 32(M) x 64(N); wm = w&3, wn = w>>2.
// 2-stage cp.async.bulk pipeline (R10 shell).
// MMA issue order is PASS-MAJOR: same-accumulator RAW chains spaced 4 apart
// instead of back-to-back (hides HMMA latency).
// MODE 0: fp32 row-major C (O projection).
// MODE 1: fused QKV epilogue (RoPE + scale + hi/lo split, row-major out).
// ---------------------------------------------------------------------------
template<int MODE>
__global__ __launch_bounds__(256, 2) void gemm_pk(
    const __nv_bfloat16* __restrict__ Ah, const __nv_bfloat16* __restrict__ Al,
    const __nv_bfloat16* __restrict__ Bh, const __nv_bfloat16* __restrict__ Bl,
    float* __restrict__ C, int N, int Ktiles,
    const float* __restrict__ cs, const float* __restrict__ sn,
    __nv_bfloat16* __restrict__ qbh, __nv_bfloat16* __restrict__ qbl,
    __nv_bfloat16* __restrict__ kbh, __nv_bfloat16* __restrict__ kbl,
    __nv_bfloat16* __restrict__ vbh, __nv_bfloat16* __restrict__ vbl)
{
    __shared__ __align__(128) __nv_bfloat16 sm[2][4][TILE_E];
    __shared__ __align__(8) uint64_t mb[2];

    const int tid = threadIdx.x, lane = tid & 31, w = tid >> 5;
    const int wm = w & 3, wn = w >> 2;     // 4 m-tiles x 2 n-tiles

    const uint32_t mbar0 = smem_u32(&mb[0]);
    const uint32_t mbar1 = smem_u32(&mb[1]);
    if (tid == 0) { mbar_init(mbar0, 1); mbar_init(mbar1, 1); }
    __syncthreads();

    const size_t tA = (size_t)blockIdx.y * Ktiles;
    const size_t tB = (size_t)blockIdx.x * Ktiles;

    auto issue = [&](int kt, int buf) {
        uint32_t mbar = buf ? mbar1 : mbar0;
        mbar_expect(mbar, 4 * TILE_E * 2);
        bulk_g2s(smem_u32(sm[buf][0]), Ah + (tA + kt) * TILE_E, TILE_E * 2, mbar);
        bulk_g2s(smem_u32(sm[buf][1]), Al + (tA + kt) * TILE_E, TILE_E * 2, mbar);
        bulk_g2s(smem_u32(sm[buf][2]), Bh + (tB + kt) * TILE_E, TILE_E * 2, mbar);
        bulk_g2s(smem_u32(sm[buf][3]), Bl + (tB + kt) * TILE_E, TILE_E * 2, mbar);
    };
    if (tid == 0) { issue(0, 0); issue(1, 1); }

    float acc[2][8][4];
#pragma unroll
    for (int i = 0; i < 2; ++i)
#pragma unroll
        for (int j = 0; j < 8; ++j)
#pragma unroll
            for (int e = 0; e < 4; ++e) acc[i][j][e] = 0.f;

    int ph0 = 0, ph1 = 0;

    for (int kt = 0; kt < Ktiles; ++kt) {
        const int buf = kt & 1;
        if (buf == 0) { mbar_wait(mbar0, ph0); ph0 ^= 1; }
        else          { mbar_wait(mbar1, ph1); ph1 ^= 1; }

        const __nv_bfloat16* A0 = sm[buf][0];
        const __nv_bfloat16* A1 = sm[buf][1];
        const __nv_bfloat16* B0 = sm[buf][2];
        const __nv_bfloat16* B1 = sm[buf][3];

#pragma unroll
        for (int kk = 0; kk < 2; ++kk) {
            const int achk = kk * 2 + (lane >> 4);
            const int arow = wm * 32 + (lane & 15);
            uint32_t ah[2][4], al[2][4];
#pragma unroll
            for (int mt = 0; mt < 2; ++mt) {
                ldm4(ah[mt], smem_u32(A0 + (arow + mt * 16) * 40 + achk * 8));
                ldm4(al[mt], smem_u32(A1 + (arow + mt * 16) * 40 + achk * 8));
            }
            const int brow = wn * 64 + (lane & 15);
#pragma unroll
            for (int nt = 0; nt < 4; ++nt) {
                uint32_t bh[4], bl[4];
                ldm4(bh, smem_u32(B0 + (brow + nt * 16) * 40 + achk * 8));
                ldm4(bl, smem_u32(B1 + (brow + nt * 16) * 40 + achk * 8));
                // pass-major issue: 4 independent accumulators per pass,
                // same-acc dependency distance = 4 (was 1).
                // pass hh
                mma16816(acc[0][2 * nt],     ah[0], bh[0], bh[2]);
                mma16816(acc[0][2 * nt + 1], ah[0], bh[1], bh[3]);
                mma16816(acc[1][2 * nt],     ah[1], bh[0], bh[2]);
                mma16816(acc[1][2 * nt + 1], ah[1], bh[1], bh[3]);
                // pass hl
                mma16816(acc[0][2 * nt],     ah[0], bl[0], bl[2]);
                mma16816(acc[0][2 * nt + 1], ah[0], bl[1], bl[3]);
                mma16816(acc[1][2 * nt],     ah[1], bl[0], bl[2]);
                mma16816(acc[1][2 * nt + 1], ah[1], bl[1], bl[3]);
                // pass lh
                mma16816(acc[0][2 * nt],     al[0], bh[0], bh[2]);
                mma16816(acc[0][2 * nt + 1], al[0], bh[1], bh[3]);
                mma16816(acc[1][2 * nt],     al[1], bh[0], bh[2]);
                mma16816(acc[1][2 * nt + 1], al[1], bh[1], bh[3]);
            }
        }
        __syncthreads();
        if (kt + 2 < Ktiles && tid == 0) {
            fence_proxy_async_cta();
            issue(kt + 2, buf);
        }
    }

    const int brow = blockIdx.y * 128 + wm * 32;
    const int bcol = blockIdx.x * 128 + wn * 64;

    if (MODE == 0) {
        // fp32 row-major
#pragma unroll
        for (int mt = 0; mt < 2; ++mt) {
            int r0 = brow + mt * 16 + (lane >> 2);
#pragma unroll
            for (int j = 0; j < 8; ++j) {
                int col = bcol + j * 8 + (lane & 3) * 2;
                *(float2*)(C + (size_t)r0 * N + col) =
                    make_float2(acc[mt][j][0], acc[mt][j][1]);
                *(float2*)(C + (size_t)(r0 + 8) * N + col) =
                    make_float2(acc[mt][j][2], acc[mt][j][3]);
            }
        }
    } else {
        // fused QKV epilogue: rope + scale + hi/lo split, row-major out.
        __nv_bfloat16 *dh, *dl;
        int cstride, cbase;
        float scale;
        bool rope;
        if (bcol < 2048)      { dh = qbh; dl = qbl; cstride = 2048; cbase = bcol;        scale = 0.125f; rope = true; }
        else if (bcol < 2560) { dh = kbh; dl = kbl; cstride = 512;  cbase = bcol - 2048; scale = 1.0f;   rope = true; }
        else                  { dh = vbh; dl = vbl; cstride = 512;  cbase = bcol - 2560; scale = 1.0f;   rope = false; }

#pragma unroll
        for (int mt = 0; mt < 2; ++mt) {
#pragma unroll
            for (int half = 0; half < 2; ++half) {
                int row = brow + mt * 16 + (lane >> 2) + half * 8;
                int e = half * 2;                    // acc elems e, e+1
                int s = row & (S_ - 1);
                size_t obase = (size_t)row * cstride + cbase;
                if (rope) {
#pragma unroll
                    for (int j = 0; j < 4; ++j) {
                        int d = j * 8 + (lane & 3) * 2;
                        float c0  = cs[s * 32 + d],     c1  = cs[s * 32 + d + 1];
                        float sv0 = sn[s * 32 + d],     sv1 = sn[s * 32 + d + 1];
                        float x1a = acc[mt][j][e],      x1b = acc[mt][j][e + 1];
                        float x2a = acc[mt][j + 4][e],  x2b = acc[mt][j + 4][e + 1];
                        float y1a = (x1a * c0 - x2a * sv0) * scale;
                        float y1b = (x1b * c1 - x2b * sv1) * scale;
                        float y2a = (x2a * c0 + x1a * sv0) * scale;
                        float y2b = (x2b * c1 + x1b * sv1) * scale;
                        uint32_t lo;
                        uint32_t hi = packsplit(y1a, y1b, lo);
                        *(uint32_t*)(dh + obase + d) = hi;
                        *(uint32_t*)(dl + obase + d) = lo;
                        hi = packsplit(y2a, y2b, lo);
                        *(uint32_t*)(dh + obase + d + 32) = hi;
                        *(uint32_t*)(dl + obase + d + 32) = lo;
                    }
                } else {
#pragma unroll
                    for (int j = 0; j < 8; ++j) {
                        int d = j * 8 + (lane & 3) * 2;
                        uint32_t lo;
                        uint32_t hi = packsplit(acc[mt][j][e], acc[mt][j][e + 1], lo);
                        *(uint32_t*)(dh + obase + d) = hi;
                        *(uint32_t*)(dl + obase + d) = lo;
                    }
                }
            }
        }
    }
}

// ---------------------------------------------------------------------------
// Tensor-core flash attention (R8 config). Q parked in stage-1 smem -> 72KB
// -> 3 CTAs/SM.
// ---------------------------------------------------------------------------
#define LDK 72

__global__ __launch_bounds__(128, 3) void flash_tc(
    const int* __restrict__ doc,
    const __nv_bfloat16* __restrict__ qhi, const __nv_bfloat16* __restrict__ qlo,
    const __nv_bfloat16* __restrict__ khi, const __nv_bfloat16* __restrict__ klo,
    const __nv_bfloat16* __restrict__ vhi, const __nv_bfloat16* __restrict__ vlo,
    __nv_bfloat16* __restrict__ cph, __nv_bfloat16* __restrict__ cpl)
{
    extern __shared__ __align__(16) char smraw[];
    __nv_bfloat16* sT  = (__nv_bfloat16*)smraw;      // 2 stages x (Kh|Kl|Vh|Vl)
    __shared__ int qdoc[64];
    __shared__ int kdoc[2][64];

    const int tid  = threadIdx.x;
    const int lane = tid & 31;
    const int w    = tid >> 5;
    const int qb = blockIdx.x, h = blockIdx.y, b = blockIdx.z;
    const int kvh = h >> 2;
    const int q0  = qb * 64;
    const int TILE = 64 * LDK;

    __nv_bfloat16* sQh = sT + 4 * TILE;
    __nv_bfloat16* sQl = sT + 5 * TILE;

    {
        const __nv_bfloat16* srch = qhi + ((size_t)(b * S_ + q0)) * 2048 + h * 64;
        const __nv_bfloat16* srcl = qlo + ((size_t)(b * S_ + q0)) * 2048 + h * 64;
        uint32_t dh = smem_u32(sQh), dl = smem_u32(sQl);
        for (int i = tid; i < 512; i += 128) {
            int r = i >> 3, c = i & 7;
            uint32_t off = (uint32_t)(r * LDK + c * 8) * 2;
            cp16(dh + off, srch + (size_t)r * 2048 + c * 8);
            cp16(dl + off, srcl + (size_t)r * 2048 + c * 8);
        }
        if (tid < 64) qdoc[tid] = doc[b * S_ + q0 + tid];
    }
    cp_commit();

    const int kb0 = g_dstart[b * 8 + doc[b * S_ + q0]] >> 6;

    auto load_kv = [&](int kb, int buf) {
        const size_t row0 = (size_t)(b * S_ + kb * 64);
        const __nv_bfloat16* s0 = khi + row0 * 512 + kvh * 64;
        const __nv_bfloat16* s1 = klo + row0 * 512 + kvh * 64;
        const __nv_bfloat16* s2 = vhi + row0 * 512 + kvh * 64;
        const __nv_bfloat16* s3 = vlo + row0 * 512 + kvh * 64;
        uint32_t d0 = smem_u32(sT + buf * 4 * TILE);
        const uint32_t tb = (uint32_t)TILE * 2;
        for (int i = tid; i < 512; i += 128) {
            int r = i >> 3, c = i & 7;
            uint32_t off = (uint32_t)(r * LDK + c * 8) * 2;
            size_t go = (size_t)r * 512 + c * 8;
            cp16(d0 + off,          s0 + go);
            cp16(d0 + tb + off,     s1 + go);
            cp16(d0 + 2 * tb + off, s2 + go);
            cp16(d0 + 3 * tb + off, s3 + go);
        }
        if (tid < 64) kdoc[buf][tid] = doc[b * S_ + kb * 64 + tid];
    };

    load_kv(kb0, 0);
    cp_commit();
    cp_wait<1>();
    __syncthreads();

    uint32_t qah[4][4], qal[4][4];
    {
        int row = w * 16 + (lane & 15);
        int col = (lane >> 4) * 8;
#pragma unroll
        for (int s = 0; s < 4; ++s) {
            ldm4(qah[s], smem_u32(sQh + row * LDK + col + s * 16));
            ldm4(qal[s], smem_u32(sQl + row * LDK + col + s * 16));
        }
    }
    __syncthreads();   // all warps have Q frags; stage-1 may be overwritten

    const int g   = lane >> 2;
    const int r0g = q0 + w * 16 + g;
    const int r1g = r0g + 8;
    const int qd0 = qdoc[w * 16 + g];
    const int qd1 = qdoc[w * 16 + g + 8];

    float m0 = -1e30f, m1 = -1e30f, l0 = 0.f, l1 = 0.f;
    float O[8][4];
#pragma unroll
    for (int j = 0; j < 8; ++j)
#pragma unroll
        for (int e = 0; e < 4; ++e) O[j][e] = 0.f;

    for (int kb = kb0; kb <= qb; ++kb) {
        const int buf = (kb - kb0) & 1;
        cp_wait<0>();
        __syncthreads();
        if (kb < qb) { load_kv(kb + 1, buf ^ 1); cp_commit(); }

        const __nv_bfloat16* Kh = sT + buf * 4 * TILE;
        const __nv_bfloat16* Kl = Kh + TILE;
        const __nv_bfloat16* Vh = Kl + TILE;
        const __nv_bfloat16* Vl = Vh + TILE;

        float Sf[8][4];
#pragma unroll
        for (int j = 0; j < 8; ++j) {
            Sf[j][0] = Sf[j][1] = Sf[j][2] = Sf[j][3] = 0.f;
            uint32_t bh[2][4], bl[2][4];
            int row = j * 8 + (lane & 7);
            int col = (lane >> 3) * 8;
            ldm4(bh[0], smem_u32(Kh + row * LDK + col));
            ldm4(bh[1], smem_u32(Kh + row * LDK + col + 32));
            ldm4(bl[0], smem_u32(Kl + row * LDK + col));
            ldm4(bl[1], smem_u32(Kl + row * LDK + col + 32));
#pragma unroll
            for (int s = 0; s < 4; ++s) {
                int ch = s >> 1, wh = (s & 1) * 2;
                mma16816(Sf[j], qah[s], bh[ch][wh], bh[ch][wh + 1]);
                mma16816(Sf[j], qah[s], bl[ch][wh], bl[ch][wh + 1]);
                mma16816(Sf[j], qal[s], bh[ch][wh], bh[ch][wh + 1]);
            }
        }

        const int kbase = kb * 64;
#pragma unroll
        for (int j = 0; j < 8; ++j) {
            int cl  = j * 8 + (lane & 3) * 2;
            int c0g = kbase + cl, c1g = c0g + 1;
            int kd0 = kdoc[buf][cl], kd1 = kdoc[buf][cl + 1];
            if (c0g > r0g || kd0 != qd0) Sf[j][0] = -1e30f;
            if (c1g > r0g || kd1 != qd0) Sf[j][1] = -1e30f;
            if (c0g > r1g || kd0 != qd1) Sf[j][2] = -1e30f;
            if (c1g > r1g || kd1 != qd1) Sf[j][3] = -1e30f;
        }

        float t0 = -1e30f, t1 = -1e30f;
#pragma unroll
        for (int j = 0; j < 8; ++j) {
            t0 = fmaxf(t0, fmaxf(Sf[j][0], Sf[j][1]));
            t1 = fmaxf(t1, fmaxf(Sf[j][2], Sf[j][3]));
        }
        t0 = fmaxf(t0, __shfl_xor_sync(0xffffffffu, t0, 1));
        t0 = fmaxf(t0, __shfl_xor_sync(0xffffffffu, t0, 2));
        t1 = fmaxf(t1, __shfl_xor_sync(0xffffffffu, t1, 1));
        t1 = fmaxf(t1, __shfl_xor_sync(0xffffffffu, t1, 2));
        float mn0 = fmaxf(m0, t0), mn1 = fmaxf(m1, t1);
        float corr0 = __expf(m0 - mn0), corr1 = __expf(m1 - mn1);
        m0 = mn0; m1 = mn1;
        float rs0 = 0.f, rs1 = 0.f;
#pragma unroll
        for (int j = 0; j < 8; ++j) {
            Sf[j][0] = __expf(Sf[j][0] - mn0);
            Sf[j][1] = __expf(Sf[j][1] - mn0);
            Sf[j][2] = __expf(Sf[j][2] - mn1);
            Sf[j][3] = __expf(Sf[j][3] - mn1);
            rs0 += Sf[j][0] + Sf[j][1];
            rs1 += Sf[j][2] + Sf[j][3];
        }
        rs0 += __shfl_xor_sync(0xffffffffu, rs0, 1);
        rs0 += __shfl_xor_sync(0xffffffffu, rs0, 2);
        rs1 += __shfl_xor_sync(0xffffffffu, rs1, 1);
        rs1 += __shfl_xor_sync(0xffffffffu, rs1, 2);
        l0 = l0 * corr0 + rs0;
        l1 = l1 * corr1 + rs1;
#pragma unroll
        for (int j = 0; j < 8; ++j) {
            O[j][0] *= corr0; O[j][1] *= corr0;
            O[j][2] *= corr1; O[j][3] *= corr1;
        }

        uint32_t pah[4][4], pal[4][4];
#pragma unroll
        for (int s = 0; s < 4; ++s) {
            pah[s][0] = packsplit(Sf[2 * s][0],     Sf[2 * s][1],     pal[s][0]);
            pah[s][1] = packsplit(Sf[2 * s][2],     Sf[2 * s][3],     pal[s][1]);
            pah[s][2] = packsplit(Sf[2 * s + 1][0], Sf[2 * s + 1][1], pal[s][2]);
            pah[s][3] = packsplit(Sf[2 * s + 1][2], Sf[2 * s + 1][3], pal[s][3]);
        }

#pragma unroll
        for (int j = 0; j < 8; ++j) {
            uint32_t bvh[2][4], bvl[2][4];
            int vr = lane & 31;
            ldm4t(bvh[0], smem_u32(Vh + vr * LDK + j * 8));
            ldm4t(bvh[1], smem_u32(Vh + (32 + vr) * LDK + j * 8));
            ldm4t(bvl[0], smem_u32(Vl + vr * LDK + j * 8));
            ldm4t(bvl[1], smem_u32(Vl + (32 + vr) * LDK + j * 8));
#pragma unroll
            for (int s = 0; s < 4; ++s) {
                int ch = s >> 1, wh = (s & 1) * 2;
                mma16816(O[j], pah[s], bvh[ch][wh], bvh[ch][wh + 1]);
                mma16816(O[j], pah[s], bvl[ch][wh], bvl[ch][wh + 1]);
                mma16816(O[j], pal[s], bvh[ch][wh], bvh[ch][wh + 1]);
            }
        }
    }

    // ---- epilogue: write ctx in packed-tile layout ----
    float inv0 = 1.0f / l0, inv1 = 1.0f / l1;
    int grow0 = b * S_ + r0g;
    int grow1 = grow0 + 8;
#pragma unroll
    for (int j = 0; j < 8; ++j) {
        int col = h * 64 + j * 8 + (lane & 3) * 2;
        size_t tbase = ((size_t)(grow0 >> 7) * KT_ + (col >> 5)) * TILE_E
                     + ((col >> 3) & 3) * 8 + (col & 7);
        size_t o0 = tbase + (grow0 & 127) * 40;
        size_t o1 = tbase + (grow1 & 127) * 40;
        uint32_t lo0, lo1;
        uint32_t hi0 = packsplit(O[j][0] * inv0, O[j][1] * inv0, lo0);
        uint32_t hi1 = packsplit(O[j][2] * inv1, O[j][3] * inv1, lo1);
        *(uint32_t*)(cph + o0) = hi0;
        *(uint32_t*)(cpl + o0) = lo0;
        *(uint32_t*)(cph + o1) = hi1;
        *(uint32_t*)(cpl + o1) = lo1;
    }
}

// ---------------------------------------------------------------------------
// Host launcher
// ---------------------------------------------------------------------------
extern "C" void kernel_launch(void* const* d_in, const int* in_sizes, int n_in,
                              void* d_out, int out_size)
{
    const float* x   = (const float*)d_in[0];
    const float* rc  = (const float*)d_in[1];
    const float* rs  = (const float*)d_in[2];
    const int*   doc = (const int*)d_in[3];
    const float* Wq  = (const float*)d_in[4];
    const float* Wk  = (const float*)d_in[5];
    const float* Wv  = (const float*)d_in[6];
    const float* Wo  = (const float*)d_in[7];
    float* out = (float*)d_out;

    __nv_bfloat16 *xph, *xpl, *wph, *wpl, *woph, *wopl, *cph, *cpl,
                  *qbh, *qbl, *kbh, *kbl, *vbh, *vbl;
    cudaGetSymbolAddress((void**)&xph, g_xph);   cudaGetSymbolAddress((void**)&xpl, g_xpl);
    cudaGetSymbolAddress((void**)&wph, g_wph);   cudaGetSymbolAddress((void**)&wpl, g_wpl);
    cudaGetSymbolAddress((void**)&woph, g_woph); cudaGetSymbolAddress((void**)&wopl, g_wopl);
    cudaGetSymbolAddress((void**)&cph, g_cph);   cudaGetSymbolAddress((void**)&cpl, g_cpl);
    cudaGetSymbolAddress((void**)&qbh, g_qbh);   cudaGetSymbolAddress((void**)&qbl, g_qbl);
    cudaGetSymbolAddress((void**)&kbh, g_kbh);   cudaGetSymbolAddress((void**)&kbl, g_kbl);
    cudaGetSymbolAddress((void**)&vbh, g_vbh);   cudaGetSymbolAddress((void**)&vbl, g_vbl);

    const int flash_smem = 2 * 4 * 64 * LDK * (int)sizeof(__nv_bfloat16);  // 73728
    cudaFuncSetAttribute(flash_tc,
                         cudaFuncAttributeMaxDynamicSharedMemorySize, flash_smem);

    // 1. Pack inputs + doc-start scan (one launch)
    pack_all<<<9232, 256>>>(x, Wq, Wk, Wv, Wo, doc,
                            xph, xpl, wph, wpl, woph, wopl);

    // 2. Fused QKV projection with fused RoPE/split epilogue
    {
        dim3 g(3072 / 128, M_ / 128);  // (24, 32)
        gemm_pk<1><<<g, 256>>>(xph, xpl, wph, wpl, nullptr, 3072, KT_,
                               rc, rs, qbh, qbl, kbh, kbl, vbh, vbl);
    }

    // 3. Tensor-core flash attention -> packed ctx
    {
        dim3 g(S_ / 64, NH_, B_);
        flash_tc<<<g, 128, flash_smem>>>(doc, qbh, qbl, kbh, kbl, vbh, vbl, cph, cpl);
    }

    // 4. Output projection: out = ctx @ Wo^T
    {
        dim3 g(2048 / 128, M_ / 128);  // (16, 32)
        gemm_pk<0><<<g, 256>>>(cph, cpl, woph, wopl, out, 2048, KT_,
                               nullptr, nullptr,
                               nullptr, nullptr, nullptr, nullptr, nullptr, nullptr);
    }
}

// round 13
// speedup vs baseline: 1.4862x; 1.4142x over previous
#include <cuda_runtime.h>
#include <cuda_fp16.h>
#include <math.h>
#include <stdint.h>

// Problem constants
#define B_    2
#define S_    2048
#define DIM_  2048
#define NH_   32
#define NKV_  8
#define HD_   64
#define M_    (B_ * S_)        // 4096 rows
#define KT_   64               // K tiles (2048/32)
#define TILE_E 5120            // elems per packed 128x32 tile (40-elem pitch)

#define WK_OFF ((size_t)16 * KT_ * TILE_E)
#define WV_OFF ((size_t)20 * KT_ * TILE_E)

// ---------------------------------------------------------------------------
// Scratch (static device globals — no allocation allowed)
// ---------------------------------------------------------------------------
__device__ int g_dstart[B_ * 8];

// packed-tile fp16 GEMM operands  [tile][128*40]
__device__ __half g_xp[32 * KT_ * TILE_E];                       // x (hi only)
__device__ __half g_wph[24 * KT_ * TILE_E], g_wpl[24 * KT_ * TILE_E];
__device__ __half g_woph[16 * KT_ * TILE_E], g_wopl[16 * KT_ * TILE_E];
__device__ __half g_cp[32 * KT_ * TILE_E];                       // ctx (hi only)
// flash inputs (row-major fp16 hi/lo, post-rope)
__device__ __half g_qbh[M_ * 2048], g_qbl[M_ * 2048];
__device__ __half g_kbh[M_ * 512],  g_kbl[M_ * 512];
__device__ __half g_vbh[M_ * 512],  g_vbl[M_ * 512];

// ---------------------------------------------------------------------------
// PTX helpers
// ---------------------------------------------------------------------------
__device__ __forceinline__ uint32_t smem_u32(const void* p) {
    uint32_t a;
    asm("{ .reg .u64 t; cvta.to.shared.u64 t, %1; cvt.u32.u64 %0, t; }"
        : "=r"(a) : "l"(p));
    return a;
}
__device__ __forceinline__ void cp16(uint32_t dst, const void* src) {
    asm volatile("cp.async.cg.shared.global [%0], [%1], 16;"
                 :: "r"(dst), "l"(src));
}
__device__ __forceinline__ void cp_commit() {
    asm volatile("cp.async.commit_group;");
}
template<int N>
__device__ __forceinline__ void cp_wait() {
    asm volatile("cp.async.wait_group %0;" :: "n"(N));
}
__device__ __forceinline__ void ldm4(uint32_t* r, uint32_t a) {
    asm volatile("ldmatrix.sync.aligned.m8n8.x4.shared.b16 {%0,%1,%2,%3}, [%4];"
        : "=r"(r[0]), "=r"(r[1]), "=r"(r[2]), "=r"(r[3]) : "r"(a));
}
__device__ __forceinline__ void ldm4t(uint32_t* r, uint32_t a) {
    asm volatile("ldmatrix.sync.aligned.m8n8.x4.trans.shared.b16 {%0,%1,%2,%3}, [%4];"
        : "=r"(r[0]), "=r"(r[1]), "=r"(r[2]), "=r"(r[3]) : "r"(a));
}
// fp16 mma, fp32 accumulate
__device__ __forceinline__ void mma16816(float* c, const uint32_t* a,
                                         uint32_t b0, uint32_t b1) {
    asm volatile(
        "mma.sync.aligned.m16n8k16.row.col.f32.f16.f16.f32 "
        "{%0,%1,%2,%3}, {%4,%5,%6,%7}, {%8,%9}, {%0,%1,%2,%3};"
        : "+f"(c[0]), "+f"(c[1]), "+f"(c[2]), "+f"(c[3])
        : "r"(a[0]), "r"(a[1]), "r"(a[2]), "r"(a[3]), "r"(b0), "r"(b1));
}
__device__ __forceinline__ void mbar_init(uint32_t mbar, uint32_t cnt) {
    asm volatile("mbarrier.init.shared.b64 [%0], %1;" :: "r"(mbar), "r"(cnt) : "memory");
}
__device__ __forceinline__ void mbar_expect(uint32_t mbar, uint32_t bytes) {
    asm volatile("mbarrier.arrive.expect_tx.shared.b64 _, [%0], %1;"
                 :: "r"(mbar), "r"(bytes) : "memory");
}
__device__ __forceinline__ void mbar_wait(uint32_t mbar, uint32_t phase) {
    asm volatile(
        "{\n .reg .pred P;\n"
        "W_%=:\n"
        " mbarrier.try_wait.parity.acquire.cta.shared::cta.b64 P, [%0], %1, 0x989680;\n"
        " @P bra.uni D_%=;\n bra.uni W_%=;\n"
        "D_%=:\n}"
        :: "r"(mbar), "r"(phase) : "memory");
}
__device__ __forceinline__ void bulk_g2s(uint32_t dst, const void* src,
                                         uint32_t bytes, uint32_t mbar) {
    asm volatile(
        "cp.async.bulk.shared::cluster.global.mbarrier::complete_tx::bytes "
        "[%0], [%1], %2, [%3];"
        :: "r"(dst), "l"(src), "r"(bytes), "r"(mbar) : "memory");
}
__device__ __forceinline__ void fence_proxy_async_cta() {
    asm volatile("fence.proxy.async.shared::cta;" ::: "memory");
}
union H2U { __half2 h; uint32_t u; };
__device__ __forceinline__ uint32_t packsplit_h(float x, float y, uint32_t& lo) {
    __half hx = __float2half_rn(x), hy = __float2half_rn(y);
    H2U H, L;
    H.h = __halves2half2(hx, hy);
    L.h = __halves2half2(__float2half_rn(x - __half2float(hx)),
                         __float2half_rn(y - __half2float(hy)));
    lo = L.u;
    return H.u;
}
__device__ __forceinline__ uint32_t packh(float x, float y) {
    H2U H;
    H.h = __halves2half2(__float2half_rn(x), __float2half_rn(y));
    return H.u;
}

// ---------------------------------------------------------------------------
// Fused pack: fp32 [R,2048] row-major -> packed-tile fp16 (hi, optional lo),
// 5 tensors, plus doc-start scan.
// ---------------------------------------------------------------------------
__global__ void pack_all(const float* __restrict__ x,
                         const float* __restrict__ wq,
                         const float* __restrict__ wk,
                         const float* __restrict__ wv,
                         const float* __restrict__ wo,
                         const int* __restrict__ doc,
                         __half* __restrict__ xp,
                         __half* __restrict__ wph, __half* __restrict__ wpl,
                         __half* __restrict__ woph, __half* __restrict__ wopl)
{
    int i = blockIdx.x * blockDim.x + threadIdx.x;
    const float* src;
    __half *hi, *lo;
    int li;
    if (i < 1048576)      { src = x;  hi = xp;            lo = nullptr;       li = i; }
    else if (i < 1572864) { src = wq; hi = wph;           lo = wpl;           li = i - 1048576; }
    else if (i < 1703936) { src = wk; hi = wph + WK_OFF;  lo = wpl + WK_OFF;  li = i - 1572864; }
    else if (i < 1835008) { src = wv; hi = wph + WV_OFF;  lo = wpl + WV_OFF;  li = i - 1703936; }
    else if (i < 2359296) { src = wo; hi = woph;          lo = wopl;          li = i - 1835008; }
    else if (i < 2359296 + B_ * S_) {
        int li2 = i - 2359296;
        int s = li2 & (S_ - 1);
        int d = doc[li2];
        if (s == 0 || doc[li2 - 1] != d) g_dstart[(li2 >> 11) * 8 + d] = s;
        return;
    } else return;

    int r  = li >> 8;          // kchunks = 256
    int kc = li & 255;
    const float4* s = (const float4*)src + (size_t)li * 2;
    float4 v0 = s[0], v1 = s[1];
    uint32_t l0, l1, l2, l3;
    uint32_t h0 = packsplit_h(v0.x, v0.y, l0);
    uint32_t h1 = packsplit_h(v0.z, v0.w, l1);
    uint32_t h2 = packsplit_h(v1.x, v1.y, l2);
    uint32_t h3 = packsplit_h(v1.z, v1.w, l3);
    size_t off = ((size_t)(r >> 7) * KT_ + (kc >> 2)) * TILE_E
               + (r & 127) * 40 + (kc & 3) * 8;
    *(uint4*)(hi + off) = make_uint4(h0, h1, h2, h3);
    if (lo) *(uint4*)(lo + off) = make_uint4(l0, l1, l2, l3);
}

// ---------------------------------------------------------------------------
// Packed-tile fp16 2-pass GEMM: C = A*B^T ≈ Ah*Bh + Ah*Bl  (A fp16-quantized,
// B split hi/lo; error ~2^-12 rel).
// 256 threads, 8 warps: warp tile 32(M) x 64(N). 2-stage bulk-copy pipeline.
// MODE 0: fp32 row-major C (O projection).
// MODE 1: fused QKV epilogue (RoPE + scale + fp16 hi/lo split outputs).
// ---------------------------------------------------------------------------
template<int MODE>
__global__ __launch_bounds__(256, 2) void gemm_pk(
    const __half* __restrict__ Ah,
    const __half* __restrict__ Bh, const __half* __restrict__ Bl,
    float* __restrict__ C, int N, int Ktiles,
    const float* __restrict__ cs, const float* __restrict__ sn,
    __half* __restrict__ qbh, __half* __restrict__ qbl,
    __half* __restrict__ kbh, __half* __restrict__ kbl,
    __half* __restrict__ vbh, __half* __restrict__ vbl)
{
    __shared__ __align__(128) __half sm[2][3][TILE_E];
    __shared__ __align__(8) uint64_t mb[2];

    const int tid = threadIdx.x, lane = tid & 31, w = tid >> 5;
    const int wm = w & 3, wn = w >> 2;     // 4 m-tiles x 2 n-tiles

    const uint32_t mbar0 = smem_u32(&mb[0]);
    const uint32_t mbar1 = smem_u32(&mb[1]);
    if (tid == 0) { mbar_init(mbar0, 1); mbar_init(mbar1, 1); }
    __syncthreads();

    const size_t tA = (size_t)blockIdx.y * Ktiles;
    const size_t tB = (size_t)blockIdx.x * Ktiles;

    auto issue = [&](int kt, int buf) {
        uint32_t mbar = buf ? mbar1 : mbar0;
        mbar_expect(mbar, 3 * TILE_E * 2);
        bulk_g2s(smem_u32(sm[buf][0]), Ah + (tA + kt) * TILE_E, TILE_E * 2, mbar);
        bulk_g2s(smem_u32(sm[buf][1]), Bh + (tB + kt) * TILE_E, TILE_E * 2, mbar);
        bulk_g2s(smem_u32(sm[buf][2]), Bl + (tB + kt) * TILE_E, TILE_E * 2, mbar);
    };
    if (tid == 0) { issue(0, 0); issue(1, 1); }

    float acc[2][8][4];
#pragma unroll
    for (int i = 0; i < 2; ++i)
#pragma unroll
        for (int j = 0; j < 8; ++j)
#pragma unroll
            for (int e = 0; e < 4; ++e) acc[i][j][e] = 0.f;

    int ph0 = 0, ph1 = 0;

    for (int kt = 0; kt < Ktiles; ++kt) {
        const int buf = kt & 1;
        if (buf == 0) { mbar_wait(mbar0, ph0); ph0 ^= 1; }
        else          { mbar_wait(mbar1, ph1); ph1 ^= 1; }

        const __half* A0 = sm[buf][0];
        const __half* B0 = sm[buf][1];
        const __half* B1 = sm[buf][2];

#pragma unroll
        for (int kk = 0; kk < 2; ++kk) {
            const int achk = kk * 2 + (lane >> 4);
            const int arow = wm * 32 + (lane & 15);
            uint32_t ah[2][4];
#pragma unroll
            for (int mt = 0; mt < 2; ++mt)
                ldm4(ah[mt], smem_u32(A0 + (arow + mt * 16) * 40 + achk * 8));
            const int brow = wn * 64 + (lane & 15);
#pragma unroll
            for (int nt = 0; nt < 4; ++nt) {
                uint32_t bh[4], bl[4];
                ldm4(bh, smem_u32(B0 + (brow + nt * 16) * 40 + achk * 8));
                ldm4(bl, smem_u32(B1 + (brow + nt * 16) * 40 + achk * 8));
                // pass h*h  (4 independent accumulators)
                mma16816(acc[0][2 * nt],     ah[0], bh[0], bh[2]);
                mma16816(acc[0][2 * nt + 1], ah[0], bh[1], bh[3]);
                mma16816(acc[1][2 * nt],     ah[1], bh[0], bh[2]);
                mma16816(acc[1][2 * nt + 1], ah[1], bh[1], bh[3]);
                // pass h*l
                mma16816(acc[0][2 * nt],     ah[0], bl[0], bl[2]);
                mma16816(acc[0][2 * nt + 1], ah[0], bl[1], bl[3]);
                mma16816(acc[1][2 * nt],     ah[1], bl[0], bl[2]);
                mma16816(acc[1][2 * nt + 1], ah[1], bl[1], bl[3]);
            }
        }
        __syncthreads();
        if (kt + 2 < Ktiles && tid == 0) {
            fence_proxy_async_cta();
            issue(kt + 2, buf);
        }
    }

    const int brow = blockIdx.y * 128 + wm * 32;
    const int bcol = blockIdx.x * 128 + wn * 64;

    if (MODE == 0) {
        // fp32 row-major
#pragma unroll
        for (int mt = 0; mt < 2; ++mt) {
            int r0 = brow + mt * 16 + (lane >> 2);
#pragma unroll
            for (int j = 0; j < 8; ++j) {
                int col = bcol + j * 8 + (lane & 3) * 2;
                *(float2*)(C + (size_t)r0 * N + col) =
                    make_float2(acc[mt][j][0], acc[mt][j][1]);
                *(float2*)(C + (size_t)(r0 + 8) * N + col) =
                    make_float2(acc[mt][j][2], acc[mt][j][3]);
            }
        }
    } else {
        // fused QKV epilogue: rope + scale + fp16 hi/lo split, row-major out.
        __half *dh, *dl;
        int cstride, cbase;
        float scale;
        bool rope;
        if (bcol < 2048)      { dh = qbh; dl = qbl; cstride = 2048; cbase = bcol;        scale = 0.125f; rope = true; }
        else if (bcol < 2560) { dh = kbh; dl = kbl; cstride = 512;  cbase = bcol - 2048; scale = 1.0f;   rope = true; }
        else                  { dh = vbh; dl = vbl; cstride = 512;  cbase = bcol - 2560; scale = 1.0f;   rope = false; }

#pragma unroll
        for (int mt = 0; mt < 2; ++mt) {
#pragma unroll
            for (int half = 0; half < 2; ++half) {
                int row = brow + mt * 16 + (lane >> 2) + half * 8;
                int e = half * 2;                    // acc elems e, e+1
                int s = row & (S_ - 1);
                size_t obase = (size_t)row * cstride + cbase;
                if (rope) {
#pragma unroll
                    for (int j = 0; j < 4; ++j) {
                        int d = j * 8 + (lane & 3) * 2;
                        float c0  = cs[s * 32 + d],     c1  = cs[s * 32 + d + 1];
                        float sv0 = sn[s * 32 + d],     sv1 = sn[s * 32 + d + 1];
                        float x1a = acc[mt][j][e],      x1b = acc[mt][j][e + 1];
                        float x2a = acc[mt][j + 4][e],  x2b = acc[mt][j + 4][e + 1];
                        float y1a = (x1a * c0 - x2a * sv0) * scale;
                        float y1b = (x1b * c1 - x2b * sv1) * scale;
                        float y2a = (x2a * c0 + x1a * sv0) * scale;
                        float y2b = (x2b * c1 + x1b * sv1) * scale;
                        uint32_t lo;
                        uint32_t hi = packsplit_h(y1a, y1b, lo);
                        *(uint32_t*)(dh + obase + d) = hi;
                        *(uint32_t*)(dl + obase + d) = lo;
                        hi = packsplit_h(y2a, y2b, lo);
                        *(uint32_t*)(dh + obase + d + 32) = hi;
                        *(uint32_t*)(dl + obase + d + 32) = lo;
                    }
                } else {
#pragma unroll
                    for (int j = 0; j < 8; ++j) {
                        int d = j * 8 + (lane & 3) * 2;
                        uint32_t lo;
                        uint32_t hi = packsplit_h(acc[mt][j][e], acc[mt][j][e + 1], lo);
                        *(uint32_t*)(dh + obase + d) = hi;
                        *(uint32_t*)(dl + obase + d) = lo;
                    }
                }
            }
        }
    }
}

// ---------------------------------------------------------------------------
// Tensor-core flash attention (fp16 hi/lo, 3-pass — error 2^-22).
// Q parked in stage-1 smem -> 72KB -> 3 CTAs/SM. ctx written fp16 hi only.
// ---------------------------------------------------------------------------
#define LDK 72

__global__ __launch_bounds__(128, 3) void flash_tc(
    const int* __restrict__ doc,
    const __half* __restrict__ qhi, const __half* __restrict__ qlo,
    const __half* __restrict__ khi, const __half* __restrict__ klo,
    const __half* __restrict__ vhi, const __half* __restrict__ vlo,
    __half* __restrict__ cp)
{
    extern __shared__ __align__(16) char smraw[];
    __half* sT  = (__half*)smraw;      // 2 stages x (Kh|Kl|Vh|Vl)
    __shared__ int qdoc[64];
    __shared__ int kdoc[2][64];

    const int tid  = threadIdx.x;
    const int lane = tid & 31;
    const int w    = tid >> 5;
    const int qb = blockIdx.x, h = blockIdx.y, b = blockIdx.z;
    const int kvh = h >> 2;
    const int q0  = qb * 64;
    const int TILE = 64 * LDK;

    __half* sQh = sT + 4 * TILE;
    __half* sQl = sT + 5 * TILE;

    {
        const __half* srch = qhi + ((size_t)(b * S_ + q0)) * 2048 + h * 64;
        const __half* srcl = qlo + ((size_t)(b * S_ + q0)) * 2048 + h * 64;
        uint32_t dh = smem_u32(sQh), dl = smem_u32(sQl);
        for (int i = tid; i < 512; i += 128) {
            int r = i >> 3, c = i & 7;
            uint32_t off = (uint32_t)(r * LDK + c * 8) * 2;
            cp16(dh + off, srch + (size_t)r * 2048 + c * 8);
            cp16(dl + off, srcl + (size_t)r * 2048 + c * 8);
        }
        if (tid < 64) qdoc[tid] = doc[b * S_ + q0 + tid];
    }
    cp_commit();

    const int kb0 = g_dstart[b * 8 + doc[b * S_ + q0]] >> 6;

    auto load_kv = [&](int kb, int buf) {
        const size_t row0 = (size_t)(b * S_ + kb * 64);
        const __half* s0 = khi + row0 * 512 + kvh * 64;
        const __half* s1 = klo + row0 * 512 + kvh * 64;
        const __half* s2 = vhi + row0 * 512 + kvh * 64;
        const __half* s3 = vlo + row0 * 512 + kvh * 64;
        uint32_t d0 = smem_u32(sT + buf * 4 * TILE);
        const uint32_t tb = (uint32_t)TILE * 2;
        for (int i = tid; i < 512; i += 128) {
            int r = i >> 3, c = i & 7;
            uint32_t off = (uint32_t)(r * LDK + c * 8) * 2;
            size_t go = (size_t)r * 512 + c * 8;
            cp16(d0 + off,          s0 + go);
            cp16(d0 + tb + off,     s1 + go);
            cp16(d0 + 2 * tb + off, s2 + go);
            cp16(d0 + 3 * tb + off, s3 + go);
        }
        if (tid < 64) kdoc[buf][tid] = doc[b * S_ + kb * 64 + tid];
    };

    load_kv(kb0, 0);
    cp_commit();
    cp_wait<1>();
    __syncthreads();

    uint32_t qah[4][4], qal[4][4];
    {
        int row = w * 16 + (lane & 15);
        int col = (lane >> 4) * 8;
#pragma unroll
        for (int s = 0; s < 4; ++s) {
            ldm4(qah[s], smem_u32(sQh + row * LDK + col + s * 16));
            ldm4(qal[s], smem_u32(sQl + row * LDK + col + s * 16));
        }
    }
    __syncthreads();   // all warps have Q frags; stage-1 may be overwritten

    const int g   = lane >> 2;
    const int r0g = q0 + w * 16 + g;
    const int r1g = r0g + 8;
    const int qd0 = qdoc[w * 16 + g];
    const int qd1 = qdoc[w * 16 + g + 8];

    float m0 = -1e30f, m1 = -1e30f, l0 = 0.f, l1 = 0.f;
    float O[8][4];
#pragma unroll
    for (int j = 0; j < 8; ++j)
#pragma unroll
        for (int e = 0; e < 4; ++e) O[j][e] = 0.f;

    for (int kb = kb0; kb <= qb; ++kb) {
        const int buf = (kb - kb0) & 1;
        cp_wait<0>();
        __syncthreads();
        if (kb < qb) { load_kv(kb + 1, buf ^ 1); cp_commit(); }

        const __half* Kh = sT + buf * 4 * TILE;
        const __half* Kl = Kh + TILE;
        const __half* Vh = Kl + TILE;
        const __half* Vl = Vh + TILE;

        float Sf[8][4];
#pragma unroll
        for (int j = 0; j < 8; ++j) {
            Sf[j][0] = Sf[j][1] = Sf[j][2] = Sf[j][3] = 0.f;
            uint32_t bh[2][4], bl[2][4];
            int row = j * 8 + (lane & 7);
            int col = (lane >> 3) * 8;
            ldm4(bh[0], smem_u32(Kh + row * LDK + col));
            ldm4(bh[1], smem_u32(Kh + row * LDK + col + 32));
            ldm4(bl[0], smem_u32(Kl + row * LDK + col));
            ldm4(bl[1], smem_u32(Kl + row * LDK + col + 32));
#pragma unroll
            for (int s = 0; s < 4; ++s) {
                int ch = s >> 1, wh = (s & 1) * 2;
                mma16816(Sf[j], qah[s], bh[ch][wh], bh[ch][wh + 1]);
                mma16816(Sf[j], qah[s], bl[ch][wh], bl[ch][wh + 1]);
                mma16816(Sf[j], qal[s], bh[ch][wh], bh[ch][wh + 1]);
            }
        }

        const int kbase = kb * 64;
#pragma unroll
        for (int j = 0; j < 8; ++j) {
            int cl  = j * 8 + (lane & 3) * 2;
            int c0g = kbase + cl, c1g = c0g + 1;
            int kd0 = kdoc[buf][cl], kd1 = kdoc[buf][cl + 1];
            if (c0g > r0g || kd0 != qd0) Sf[j][0] = -1e30f;
            if (c1g > r0g || kd1 != qd0) Sf[j][1] = -1e30f;
            if (c0g > r1g || kd0 != qd1) Sf[j][2] = -1e30f;
            if (c1g > r1g || kd1 != qd1) Sf[j][3] = -1e30f;
        }

        float t0 = -1e30f, t1 = -1e30f;
#pragma unroll
        for (int j = 0; j < 8; ++j) {
            t0 = fmaxf(t0, fmaxf(Sf[j][0], Sf[j][1]));
            t1 = fmaxf(t1, fmaxf(Sf[j][2], Sf[j][3]));
        }
        t0 = fmaxf(t0, __shfl_xor_sync(0xffffffffu, t0, 1));
        t0 = fmaxf(t0, __shfl_xor_sync(0xffffffffu, t0, 2));
        t1 = fmaxf(t1, __shfl_xor_sync(0xffffffffu, t1, 1));
        t1 = fmaxf(t1, __shfl_xor_sync(0xffffffffu, t1, 2));
        float mn0 = fmaxf(m0, t0), mn1 = fmaxf(m1, t1);
        float corr0 = __expf(m0 - mn0), corr1 = __expf(m1 - mn1);
        m0 = mn0; m1 = mn1;
        float rs0 = 0.f, rs1 = 0.f;
#pragma unroll
        for (int j = 0; j < 8; ++j) {
            Sf[j][0] = __expf(Sf[j][0] - mn0);
            Sf[j][1] = __expf(Sf[j][1] - mn0);
            Sf[j][2] = __expf(Sf[j][2] - mn1);
            Sf[j][3] = __expf(Sf[j][3] - mn1);
            rs0 += Sf[j][0] + Sf[j][1];
            rs1 += Sf[j][2] + Sf[j][3];
        }
        rs0 += __shfl_xor_sync(0xffffffffu, rs0, 1);
        rs0 += __shfl_xor_sync(0xffffffffu, rs0, 2);
        rs1 += __shfl_xor_sync(0xffffffffu, rs1, 1);
        rs1 += __shfl_xor_sync(0xffffffffu, rs1, 2);
        l0 = l0 * corr0 + rs0;
        l1 = l1 * corr1 + rs1;
#pragma unroll
        for (int j = 0; j < 8; ++j) {
            O[j][0] *= corr0; O[j][1] *= corr0;
            O[j][2] *= corr1; O[j][3] *= corr1;
        }

        uint32_t pah[4][4], pal[4][4];
#pragma unroll
        for (int s = 0; s < 4; ++s) {
            pah[s][0] = packsplit_h(Sf[2 * s][0],     Sf[2 * s][1],     pal[s][0]);
            pah[s][1] = packsplit_h(Sf[2 * s][2],     Sf[2 * s][3],     pal[s][1]);
            pah[s][2] = packsplit_h(Sf[2 * s + 1][0], Sf[2 * s + 1][1], pal[s][2]);
            pah[s][3] = packsplit_h(Sf[2 * s + 1][2], Sf[2 * s + 1][3], pal[s][3]);
        }

#pragma unroll
        for (int j = 0; j < 8; ++j) {
            uint32_t bvh[2][4], bvl[2][4];
            int vr = lane & 31;
            ldm4t(bvh[0], smem_u32(Vh + vr * LDK + j * 8));
            ldm4t(bvh[1], smem_u32(Vh + (32 + vr) * LDK + j * 8));
            ldm4t(bvl[0], smem_u32(Vl + vr * LDK + j * 8));
            ldm4t(bvl[1], smem_u32(Vl + (32 + vr) * LDK + j * 8));
#pragma unroll
            for (int s = 0; s < 4; ++s) {
                int ch = s >> 1, wh = (s & 1) * 2;
                mma16816(O[j], pah[s], bvh[ch][wh], bvh[ch][wh + 1]);
                mma16816(O[j], pah[s], bvl[ch][wh], bvl[ch][wh + 1]);
                mma16816(O[j], pal[s], bvh[ch][wh], bvh[ch][wh + 1]);
            }
        }
    }

    // ---- epilogue: write ctx in packed-tile layout (fp16 hi only) ----
    float inv0 = 1.0f / l0, inv1 = 1.0f / l1;
    int grow0 = b * S_ + r0g;
    int grow1 = grow0 + 8;
#pragma unroll
    for (int j = 0; j < 8; ++j) {
        int col = h * 64 + j * 8 + (lane & 3) * 2;
        size_t tbase = ((size_t)(grow0 >> 7) * KT_ + (col >> 5)) * TILE_E
                     + ((col >> 3) & 3) * 8 + (col & 7);
        size_t o0 = tbase + (grow0 & 127) * 40;
        size_t o1 = tbase + (grow1 & 127) * 40;
        *(uint32_t*)(cp + o0) = packh(O[j][0] * inv0, O[j][1] * inv0);
        *(uint32_t*)(cp + o1) = packh(O[j][2] * inv1, O[j][3] * inv1);
    }
}

// ---------------------------------------------------------------------------
// Host launcher
// ---------------------------------------------------------------------------
extern "C" void kernel_launch(void* const* d_in, const int* in_sizes, int n_in,
                              void* d_out, int out_size)
{
    const float* x   = (const float*)d_in[0];
    const float* rc  = (const float*)d_in[1];
    const float* rs  = (const float*)d_in[2];
    const int*   doc = (const int*)d_in[3];
    const float* Wq  = (const float*)d_in[4];
    const float* Wk  = (const float*)d_in[5];
    const float* Wv  = (const float*)d_in[6];
    const float* Wo  = (const float*)d_in[7];
    float* out = (float*)d_out;

    __half *xp, *wph, *wpl, *woph, *wopl, *cp,
           *qbh, *qbl, *kbh, *kbl, *vbh, *vbl;
    cudaGetSymbolAddress((void**)&xp, g_xp);
    cudaGetSymbolAddress((void**)&wph, g_wph);   cudaGetSymbolAddress((void**)&wpl, g_wpl);
    cudaGetSymbolAddress((void**)&woph, g_woph); cudaGetSymbolAddress((void**)&wopl, g_wopl);
    cudaGetSymbolAddress((void**)&cp, g_cp);
    cudaGetSymbolAddress((void**)&qbh, g_qbh);   cudaGetSymbolAddress((void**)&qbl, g_qbl);
    cudaGetSymbolAddress((void**)&kbh, g_kbh);   cudaGetSymbolAddress((void**)&kbl, g_kbl);
    cudaGetSymbolAddress((void**)&vbh, g_vbh);   cudaGetSymbolAddress((void**)&vbl, g_vbl);

    const int flash_smem = 2 * 4 * 64 * LDK * (int)sizeof(__half);  // 73728
    cudaFuncSetAttribute(flash_tc,
                         cudaFuncAttributeMaxDynamicSharedMemorySize, flash_smem);

    // 1. Pack inputs + doc-start scan (one launch)
    pack_all<<<9232, 256>>>(x, Wq, Wk, Wv, Wo, doc,
                            xp, wph, wpl, woph, wopl);

    // 2. Fused QKV projection with fused RoPE/split epilogue
    {
        dim3 g(3072 / 128, M_ / 128);  // (24, 32)
        gemm_pk<1><<<g, 256>>>(xp, wph, wpl, nullptr, 3072, KT_,
                               rc, rs, qbh, qbl, kbh, kbl, vbh, vbl);
    }

    // 3. Tensor-core flash attention -> packed ctx (fp16 hi)
    {
        dim3 g(S_ / 64, NH_, B_);
        flash_tc<<<g, 128, flash_smem>>>(doc, qbh, qbl, kbh, kbl, vbh, vbl, cp);
    }

    // 4. Output projection: out = ctx @ Wo^T
    {
        dim3 g(2048 / 128, M_ / 128);  // (16, 32)
        gemm_pk<0><<<g, 256>>>(cp, woph, wopl, out, 2048, KT_,
                               nullptr, nullptr,
                               nullptr, nullptr, nullptr, nullptr, nullptr, nullptr);
    }
}

// round 14
// speedup vs baseline: 2.1815x; 1.4679x over previous
#include <cuda_runtime.h>
#include <cuda_fp16.h>
#include <math.h>
#include <stdint.h>

// Problem constants
#define B_    2
#define S_    2048
#define DIM_  2048
#define NH_   32
#define NKV_  8
#define HD_   64
#define M_    (B_ * S_)        // 4096 rows
#define KT_   64               // K tiles (2048/32)
#define TILE_E 5120            // elems per packed 128x32 tile (40-elem pitch)

#define WK_OFF ((size_t)16 * KT_ * TILE_E)
#define WV_OFF ((size_t)20 * KT_ * TILE_E)

// ---------------------------------------------------------------------------
// Scratch (static device globals — no allocation allowed)
// ---------------------------------------------------------------------------
__device__ int g_dstart[B_ * 8];

// packed-tile fp16 GEMM operands  [tile][128*40]  (all hi-only now)
__device__ __half g_xp[32 * KT_ * TILE_E];
__device__ __half g_wp[24 * KT_ * TILE_E];
__device__ __half g_wop[16 * KT_ * TILE_E];
__device__ __half g_cp[32 * KT_ * TILE_E];
// flash inputs (row-major fp16 hi/lo, post-rope)
__device__ __half g_qbh[M_ * 2048], g_qbl[M_ * 2048];
__device__ __half g_kbh[M_ * 512],  g_kbl[M_ * 512];
__device__ __half g_vbh[M_ * 512],  g_vbl[M_ * 512];

// ---------------------------------------------------------------------------
// PTX helpers
// ---------------------------------------------------------------------------
__device__ __forceinline__ uint32_t smem_u32(const void* p) {
    uint32_t a;
    asm("{ .reg .u64 t; cvta.to.shared.u64 t, %1; cvt.u32.u64 %0, t; }"
        : "=r"(a) : "l"(p));
    return a;
}
__device__ __forceinline__ void cp16(uint32_t dst, const void* src) {
    asm volatile("cp.async.cg.shared.global [%0], [%1], 16;"
                 :: "r"(dst), "l"(src));
}
__device__ __forceinline__ void cp_commit() {
    asm volatile("cp.async.commit_group;");
}
template<int N>
__device__ __forceinline__ void cp_wait() {
    asm volatile("cp.async.wait_group %0;" :: "n"(N));
}
__device__ __forceinline__ void ldm4(uint32_t* r, uint32_t a) {
    asm volatile("ldmatrix.sync.aligned.m8n8.x4.shared.b16 {%0,%1,%2,%3}, [%4];"
        : "=r"(r[0]), "=r"(r[1]), "=r"(r[2]), "=r"(r[3]) : "r"(a));
}
__device__ __forceinline__ void ldm4t(uint32_t* r, uint32_t a) {
    asm volatile("ldmatrix.sync.aligned.m8n8.x4.trans.shared.b16 {%0,%1,%2,%3}, [%4];"
        : "=r"(r[0]), "=r"(r[1]), "=r"(r[2]), "=r"(r[3]) : "r"(a));
}
// fp16 mma, fp32 accumulate
__device__ __forceinline__ void mma16816(float* c, const uint32_t* a,
                                         uint32_t b0, uint32_t b1) {
    asm volatile(
        "mma.sync.aligned.m16n8k16.row.col.f32.f16.f16.f32 "
        "{%0,%1,%2,%3}, {%4,%5,%6,%7}, {%8,%9}, {%0,%1,%2,%3};"
        : "+f"(c[0]), "+f"(c[1]), "+f"(c[2]), "+f"(c[3])
        : "r"(a[0]), "r"(a[1]), "r"(a[2]), "r"(a[3]), "r"(b0), "r"(b1));
}
__device__ __forceinline__ void mbar_init(uint32_t mbar, uint32_t cnt) {
    asm volatile("mbarrier.init.shared.b64 [%0], %1;" :: "r"(mbar), "r"(cnt) : "memory");
}
__device__ __forceinline__ void mbar_expect(uint32_t mbar, uint32_t bytes) {
    asm volatile("mbarrier.arrive.expect_tx.shared.b64 _, [%0], %1;"
                 :: "r"(mbar), "r"(bytes) : "memory");
}
__device__ __forceinline__ void mbar_wait(uint32_t mbar, uint32_t phase) {
    asm volatile(
        "{\n .reg .pred P;\n"
        "W_%=:\n"
        " mbarrier.try_wait.parity.acquire.cta.shared::cta.b64 P, [%0], %1, 0x989680;\n"
        " @P bra.uni D_%=;\n bra.uni W_%=;\n"
        "D_%=:\n}"
        :: "r"(mbar), "r"(phase) : "memory");
}
__device__ __forceinline__ void bulk_g2s(uint32_t dst, const void* src,
                                         uint32_t bytes, uint32_t mbar) {
    asm volatile(
        "cp.async.bulk.shared::cluster.global.mbarrier::complete_tx::bytes "
        "[%0], [%1], %2, [%3];"
        :: "r"(dst), "l"(src), "r"(bytes), "r"(mbar) : "memory");
}
__device__ __forceinline__ void fence_proxy_async_cta() {
    asm volatile("fence.proxy.async.shared::cta;" ::: "memory");
}
union H2U { __half2 h; uint32_t u; };
__device__ __forceinline__ uint32_t packsplit_h(float x, float y, uint32_t& lo) {
    __half hx = __float2half_rn(x), hy = __float2half_rn(y);
    H2U H, L;
    H.h = __halves2half2(hx, hy);
    L.h = __halves2half2(__float2half_rn(x - __half2float(hx)),
                         __float2half_rn(y - __half2float(hy)));
    lo = L.u;
    return H.u;
}
__device__ __forceinline__ uint32_t packh(float x, float y) {
    H2U H;
    H.h = __halves2half2(__float2half_rn(x), __float2half_rn(y));
    return H.u;
}

// ---------------------------------------------------------------------------
// Fused pack: fp32 [R,2048] row-major -> packed-tile fp16 (hi only),
// 5 tensors, plus doc-start scan.
// ---------------------------------------------------------------------------
__global__ void pack_all(const float* __restrict__ x,
                         const float* __restrict__ wq,
                         const float* __restrict__ wk,
                         const float* __restrict__ wv,
                         const float* __restrict__ wo,
                         const int* __restrict__ doc,
                         __half* __restrict__ xp,
                         __half* __restrict__ wp,
                         __half* __restrict__ wop)
{
    int i = blockIdx.x * blockDim.x + threadIdx.x;
    const float* src;
    __half* hi;
    int li;
    if (i < 1048576)      { src = x;  hi = xp;           li = i; }
    else if (i < 1572864) { src = wq; hi = wp;           li = i - 1048576; }
    else if (i < 1703936) { src = wk; hi = wp + WK_OFF;  li = i - 1572864; }
    else if (i < 1835008) { src = wv; hi = wp + WV_OFF;  li = i - 1703936; }
    else if (i < 2359296) { src = wo; hi = wop;          li = i - 1835008; }
    else if (i < 2359296 + B_ * S_) {
        int li2 = i - 2359296;
        int s = li2 & (S_ - 1);
        int d = doc[li2];
        if (s == 0 || doc[li2 - 1] != d) g_dstart[(li2 >> 11) * 8 + d] = s;
        return;
    } else return;

    int r  = li >> 8;          // kchunks = 256
    int kc = li & 255;
    const float4* s = (const float4*)src + (size_t)li * 2;
    float4 v0 = s[0], v1 = s[1];
    uint32_t h0 = packh(v0.x, v0.y);
    uint32_t h1 = packh(v0.z, v0.w);
    uint32_t h2 = packh(v1.x, v1.y);
    uint32_t h3 = packh(v1.z, v1.w);
    size_t off = ((size_t)(r >> 7) * KT_ + (kc >> 2)) * TILE_E
               + (r & 127) * 40 + (kc & 3) * 8;
    *(uint4*)(hi + off) = make_uint4(h0, h1, h2, h3);
}

// ---------------------------------------------------------------------------
// Packed-tile fp16 single-pass GEMM: C = A*B^T  (A, B fp16-quantized).
// 256 threads, 8 warps: warp tile 32(M) x 64(N). 2-stage bulk-copy pipeline.
// MODE 0: fp32 row-major C (O projection).
// MODE 1: fused QKV epilogue (RoPE + scale + fp16 hi/lo split outputs).
// ---------------------------------------------------------------------------
template<int MODE>
__global__ __launch_bounds__(256, 2) void gemm_pk(
    const __half* __restrict__ Ah,
    const __half* __restrict__ Bh,
    float* __restrict__ C, int N, int Ktiles,
    const float* __restrict__ cs, const float* __restrict__ sn,
    __half* __restrict__ qbh, __half* __restrict__ qbl,
    __half* __restrict__ kbh, __half* __restrict__ kbl,
    __half* __restrict__ vbh, __half* __restrict__ vbl)
{
    __shared__ __align__(128) __half sm[2][2][TILE_E];
    __shared__ __align__(8) uint64_t mb[2];

    const int tid = threadIdx.x, lane = tid & 31, w = tid >> 5;
    const int wm = w & 3, wn = w >> 2;     // 4 m-tiles x 2 n-tiles

    const uint32_t mbar0 = smem_u32(&mb[0]);
    const uint32_t mbar1 = smem_u32(&mb[1]);
    if (tid == 0) { mbar_init(mbar0, 1); mbar_init(mbar1, 1); }
    __syncthreads();

    const size_t tA = (size_t)blockIdx.y * Ktiles;
    const size_t tB = (size_t)blockIdx.x * Ktiles;

    auto issue = [&](int kt, int buf) {
        uint32_t mbar = buf ? mbar1 : mbar0;
        mbar_expect(mbar, 2 * TILE_E * 2);
        bulk_g2s(smem_u32(sm[buf][0]), Ah + (tA + kt) * TILE_E, TILE_E * 2, mbar);
        bulk_g2s(smem_u32(sm[buf][1]), Bh + (tB + kt) * TILE_E, TILE_E * 2, mbar);
    };
    if (tid == 0) { issue(0, 0); issue(1, 1); }

    float acc[2][8][4];
#pragma unroll
    for (int i = 0; i < 2; ++i)
#pragma unroll
        for (int j = 0; j < 8; ++j)
#pragma unroll
            for (int e = 0; e < 4; ++e) acc[i][j][e] = 0.f;

    int ph0 = 0, ph1 = 0;

    for (int kt = 0; kt < Ktiles; ++kt) {
        const int buf = kt & 1;
        if (buf == 0) { mbar_wait(mbar0, ph0); ph0 ^= 1; }
        else          { mbar_wait(mbar1, ph1); ph1 ^= 1; }

        const __half* A0 = sm[buf][0];
        const __half* B0 = sm[buf][1];

#pragma unroll
        for (int kk = 0; kk < 2; ++kk) {
            const int achk = kk * 2 + (lane >> 4);
            const int arow = wm * 32 + (lane & 15);
            uint32_t ah[2][4];
#pragma unroll
            for (int mt = 0; mt < 2; ++mt)
                ldm4(ah[mt], smem_u32(A0 + (arow + mt * 16) * 40 + achk * 8));
            const int brow = wn * 64 + (lane & 15);
#pragma unroll
            for (int nt = 0; nt < 4; ++nt) {
                uint32_t bh[4];
                ldm4(bh, smem_u32(B0 + (brow + nt * 16) * 40 + achk * 8));
                // 4 independent accumulators (spacing 4)
                mma16816(acc[0][2 * nt],     ah[0], bh[0], bh[2]);
                mma16816(acc[0][2 * nt + 1], ah[0], bh[1], bh[3]);
                mma16816(acc[1][2 * nt],     ah[1], bh[0], bh[2]);
                mma16816(acc[1][2 * nt + 1], ah[1], bh[1], bh[3]);
            }
        }
        __syncthreads();
        if (kt + 2 < Ktiles && tid == 0) {
            fence_proxy_async_cta();
            issue(kt + 2, buf);
        }
    }

    const int brow = blockIdx.y * 128 + wm * 32;
    const int bcol = blockIdx.x * 128 + wn * 64;

    if (MODE == 0) {
        // fp32 row-major
#pragma unroll
        for (int mt = 0; mt < 2; ++mt) {
            int r0 = brow + mt * 16 + (lane >> 2);
#pragma unroll
            for (int j = 0; j < 8; ++j) {
                int col = bcol + j * 8 + (lane & 3) * 2;
                *(float2*)(C + (size_t)r0 * N + col) =
                    make_float2(acc[mt][j][0], acc[mt][j][1]);
                *(float2*)(C + (size_t)(r0 + 8) * N + col) =
                    make_float2(acc[mt][j][2], acc[mt][j][3]);
            }
        }
    } else {
        // fused QKV epilogue: rope + scale + fp16 hi/lo split, row-major out.
        __half *dh, *dl;
        int cstride, cbase;
        float scale;
        bool rope;
        if (bcol < 2048)      { dh = qbh; dl = qbl; cstride = 2048; cbase = bcol;        scale = 0.125f; rope = true; }
        else if (bcol < 2560) { dh = kbh; dl = kbl; cstride = 512;  cbase = bcol - 2048; scale = 1.0f;   rope = true; }
        else                  { dh = vbh; dl = vbl; cstride = 512;  cbase = bcol - 2560; scale = 1.0f;   rope = false; }

#pragma unroll
        for (int mt = 0; mt < 2; ++mt) {
#pragma unroll
            for (int half = 0; half < 2; ++half) {
                int row = brow + mt * 16 + (lane >> 2) + half * 8;
                int e = half * 2;                    // acc elems e, e+1
                int s = row & (S_ - 1);
                size_t obase = (size_t)row * cstride + cbase;
                if (rope) {
#pragma unroll
                    for (int j = 0; j < 4; ++j) {
                        int d = j * 8 + (lane & 3) * 2;
                        float c0  = cs[s * 32 + d],     c1  = cs[s * 32 + d + 1];
                        float sv0 = sn[s * 32 + d],     sv1 = sn[s * 32 + d + 1];
                        float x1a = acc[mt][j][e],      x1b = acc[mt][j][e + 1];
                        float x2a = acc[mt][j + 4][e],  x2b = acc[mt][j + 4][e + 1];
                        float y1a = (x1a * c0 - x2a * sv0) * scale;
                        float y1b = (x1b * c1 - x2b * sv1) * scale;
                        float y2a = (x2a * c0 + x1a * sv0) * scale;
                        float y2b = (x2b * c1 + x1b * sv1) * scale;
                        uint32_t lo;
                        uint32_t hi = packsplit_h(y1a, y1b, lo);
                        *(uint32_t*)(dh + obase + d) = hi;
                        *(uint32_t*)(dl + obase + d) = lo;
                        hi = packsplit_h(y2a, y2b, lo);
                        *(uint32_t*)(dh + obase + d + 32) = hi;
                        *(uint32_t*)(dl + obase + d + 32) = lo;
                    }
                } else {
#pragma unroll
                    for (int j = 0; j < 8; ++j) {
                        int d = j * 8 + (lane & 3) * 2;
                        uint32_t lo;
                        uint32_t hi = packsplit_h(acc[mt][j][e], acc[mt][j][e + 1], lo);
                        *(uint32_t*)(dh + obase + d) = hi;
                        *(uint32_t*)(dl + obase + d) = lo;
                    }
                }
            }
        }
    }
}

// ---------------------------------------------------------------------------
// Tensor-core flash attention (fp16 hi/lo, 3-pass — unchanged from R13).
// Q parked in stage-1 smem -> 72KB -> 3 CTAs/SM. ctx written fp16 hi only.
// ---------------------------------------------------------------------------
#define LDK 72

__global__ __launch_bounds__(128, 3) void flash_tc(
    const int* __restrict__ doc,
    const __half* __restrict__ qhi, const __half* __restrict__ qlo,
    const __half* __restrict__ khi, const __half* __restrict__ klo,
    const __half* __restrict__ vhi, const __half* __restrict__ vlo,
    __half* __restrict__ cp)
{
    extern __shared__ __align__(16) char smraw[];
    __half* sT  = (__half*)smraw;      // 2 stages x (Kh|Kl|Vh|Vl)
    __shared__ int qdoc[64];
    __shared__ int kdoc[2][64];

    const int tid  = threadIdx.x;
    const int lane = tid & 31;
    const int w    = tid >> 5;
    const int qb = blockIdx.x, h = blockIdx.y, b = blockIdx.z;
    const int kvh = h >> 2;
    const int q0  = qb * 64;
    const int TILE = 64 * LDK;

    __half* sQh = sT + 4 * TILE;
    __half* sQl = sT + 5 * TILE;

    {
        const __half* srch = qhi + ((size_t)(b * S_ + q0)) * 2048 + h * 64;
        const __half* srcl = qlo + ((size_t)(b * S_ + q0)) * 2048 + h * 64;
        uint32_t dh = smem_u32(sQh), dl = smem_u32(sQl);
        for (int i = tid; i < 512; i += 128) {
            int r = i >> 3, c = i & 7;
            uint32_t off = (uint32_t)(r * LDK + c * 8) * 2;
            cp16(dh + off, srch + (size_t)r * 2048 + c * 8);
            cp16(dl + off, srcl + (size_t)r * 2048 + c * 8);
        }
        if (tid < 64) qdoc[tid] = doc[b * S_ + q0 + tid];
    }
    cp_commit();

    const int kb0 = g_dstart[b * 8 + doc[b * S_ + q0]] >> 6;

    auto load_kv = [&](int kb, int buf) {
        const size_t row0 = (size_t)(b * S_ + kb * 64);
        const __half* s0 = khi + row0 * 512 + kvh * 64;
        const __half* s1 = klo + row0 * 512 + kvh * 64;
        const __half* s2 = vhi + row0 * 512 + kvh * 64;
        const __half* s3 = vlo + row0 * 512 + kvh * 64;
        uint32_t d0 = smem_u32(sT + buf * 4 * TILE);
        const uint32_t tb = (uint32_t)TILE * 2;
        for (int i = tid; i < 512; i += 128) {
            int r = i >> 3, c = i & 7;
            uint32_t off = (uint32_t)(r * LDK + c * 8) * 2;
            size_t go = (size_t)r * 512 + c * 8;
            cp16(d0 + off,          s0 + go);
            cp16(d0 + tb + off,     s1 + go);
            cp16(d0 + 2 * tb + off, s2 + go);
            cp16(d0 + 3 * tb + off, s3 + go);
        }
        if (tid < 64) kdoc[buf][tid] = doc[b * S_ + kb * 64 + tid];
    };

    load_kv(kb0, 0);
    cp_commit();
    cp_wait<1>();
    __syncthreads();

    uint32_t qah[4][4], qal[4][4];
    {
        int row = w * 16 + (lane & 15);
        int col = (lane >> 4) * 8;
#pragma unroll
        for (int s = 0; s < 4; ++s) {
            ldm4(qah[s], smem_u32(sQh + row * LDK + col + s * 16));
            ldm4(qal[s], smem_u32(sQl + row * LDK + col + s * 16));
        }
    }
    __syncthreads();   // all warps have Q frags; stage-1 may be overwritten

    const int g   = lane >> 2;
    const int r0g = q0 + w * 16 + g;
    const int r1g = r0g + 8;
    const int qd0 = qdoc[w * 16 + g];
    const int qd1 = qdoc[w * 16 + g + 8];

    float m0 = -1e30f, m1 = -1e30f, l0 = 0.f, l1 = 0.f;
    float O[8][4];
#pragma unroll
    for (int j = 0; j < 8; ++j)
#pragma unroll
        for (int e = 0; e < 4; ++e) O[j][e] = 0.f;

    for (int kb = kb0; kb <= qb; ++kb) {
        const int buf = (kb - kb0) & 1;
        cp_wait<0>();
        __syncthreads();
        if (kb < qb) { load_kv(kb + 1, buf ^ 1); cp_commit(); }

        const __half* Kh = sT + buf * 4 * TILE;
        const __half* Kl = Kh + TILE;
        const __half* Vh = Kl + TILE;
        const __half* Vl = Vh + TILE;

        float Sf[8][4];
#pragma unroll
        for (int j = 0; j < 8; ++j) {
            Sf[j][0] = Sf[j][1] = Sf[j][2] = Sf[j][3] = 0.f;
            uint32_t bh[2][4], bl[2][4];
            int row = j * 8 + (lane & 7);
            int col = (lane >> 3) * 8;
            ldm4(bh[0], smem_u32(Kh + row * LDK + col));
            ldm4(bh[1], smem_u32(Kh + row * LDK + col + 32));
            ldm4(bl[0], smem_u32(Kl + row * LDK + col));
            ldm4(bl[1], smem_u32(Kl + row * LDK + col + 32));
#pragma unroll
            for (int s = 0; s < 4; ++s) {
                int ch = s >> 1, wh = (s & 1) * 2;
                mma16816(Sf[j], qah[s], bh[ch][wh], bh[ch][wh + 1]);
                mma16816(Sf[j], qah[s], bl[ch][wh], bl[ch][wh + 1]);
                mma16816(Sf[j], qal[s], bh[ch][wh], bh[ch][wh + 1]);
            }
        }

        const int kbase = kb * 64;
#pragma unroll
        for (int j = 0; j < 8; ++j) {
            int cl  = j * 8 + (lane & 3) * 2;
            int c0g = kbase + cl, c1g = c0g + 1;
            int kd0 = kdoc[buf][cl], kd1 = kdoc[buf][cl + 1];
            if (c0g > r0g || kd0 != qd0) Sf[j][0] = -1e30f;
            if (c1g > r0g || kd1 != qd0) Sf[j][1] = -1e30f;
            if (c0g > r1g || kd0 != qd1) Sf[j][2] = -1e30f;
            if (c1g > r1g || kd1 != qd1) Sf[j][3] = -1e30f;
        }

        float t0 = -1e30f, t1 = -1e30f;
#pragma unroll
        for (int j = 0; j < 8; ++j) {
            t0 = fmaxf(t0, fmaxf(Sf[j][0], Sf[j][1]));
            t1 = fmaxf(t1, fmaxf(Sf[j][2], Sf[j][3]));
        }
        t0 = fmaxf(t0, __shfl_xor_sync(0xffffffffu, t0, 1));
        t0 = fmaxf(t0, __shfl_xor_sync(0xffffffffu, t0, 2));
        t1 = fmaxf(t1, __shfl_xor_sync(0xffffffffu, t1, 1));
        t1 = fmaxf(t1, __shfl_xor_sync(0xffffffffu, t1, 2));
        float mn0 = fmaxf(m0, t0), mn1 = fmaxf(m1, t1);
        float corr0 = __expf(m0 - mn0), corr1 = __expf(m1 - mn1);
        m0 = mn0; m1 = mn1;
        float rs0 = 0.f, rs1 = 0.f;
#pragma unroll
        for (int j = 0; j < 8; ++j) {
            Sf[j][0] = __expf(Sf[j][0] - mn0);
            Sf[j][1] = __expf(Sf[j][1] - mn0);
            Sf[j][2] = __expf(Sf[j][2] - mn1);
            Sf[j][3] = __expf(Sf[j][3] - mn1);
            rs0 += Sf[j][0] + Sf[j][1];
            rs1 += Sf[j][2] + Sf[j][3];
        }
        rs0 += __shfl_xor_sync(0xffffffffu, rs0, 1);
        rs0 += __shfl_xor_sync(0xffffffffu, rs0, 2);
        rs1 += __shfl_xor_sync(0xffffffffu, rs1, 1);
        rs1 += __shfl_xor_sync(0xffffffffu, rs1, 2);
        l0 = l0 * corr0 + rs0;
        l1 = l1 * corr1 + rs1;
#pragma unroll
        for (int j = 0; j < 8; ++j) {
            O[j][0] *= corr0; O[j][1] *= corr0;
            O[j][2] *= corr1; O[j][3] *= corr1;
        }

        uint32_t pah[4][4], pal[4][4];
#pragma unroll
        for (int s = 0; s < 4; ++s) {
            pah[s][0] = packsplit_h(Sf[2 * s][0],     Sf[2 * s][1],     pal[s][0]);
            pah[s][1] = packsplit_h(Sf[2 * s][2],     Sf[2 * s][3],     pal[s][1]);
            pah[s][2] = packsplit_h(Sf[2 * s + 1][0], Sf[2 * s + 1][1], pal[s][2]);
            pah[s][3] = packsplit_h(Sf[2 * s + 1][2], Sf[2 * s + 1][3], pal[s][3]);
        }

#pragma unroll
        for (int j = 0; j < 8; ++j) {
            uint32_t bvh[2][4], bvl[2][4];
            int vr = lane & 31;
            ldm4t(bvh[0], smem_u32(Vh + vr * LDK + j * 8));
            ldm4t(bvh[1], smem_u32(Vh + (32 + vr) * LDK + j * 8));
            ldm4t(bvl[0], smem_u32(Vl + vr * LDK + j * 8));
            ldm4t(bvl[1], smem_u32(Vl + (32 + vr) * LDK + j * 8));
#pragma unroll
            for (int s = 0; s < 4; ++s) {
                int ch = s >> 1, wh = (s & 1) * 2;
                mma16816(O[j], pah[s], bvh[ch][wh], bvh[ch][wh + 1]);
                mma16816(O[j], pah[s], bvl[ch][wh], bvl[ch][wh + 1]);
                mma16816(O[j], pal[s], bvh[ch][wh], bvh[ch][wh + 1]);
            }
        }
    }

    // ---- epilogue: write ctx in packed-tile layout (fp16 hi only) ----
    float inv0 = 1.0f / l0, inv1 = 1.0f / l1;
    int grow0 = b * S_ + r0g;
    int grow1 = grow0 + 8;
#pragma unroll
    for (int j = 0; j < 8; ++j) {
        int col = h * 64 + j * 8 + (lane & 3) * 2;
        size_t tbase = ((size_t)(grow0 >> 7) * KT_ + (col >> 5)) * TILE_E
                     + ((col >> 3) & 3) * 8 + (col & 7);
        size_t o0 = tbase + (grow0 & 127) * 40;
        size_t o1 = tbase + (grow1 & 127) * 40;
        *(uint32_t*)(cp + o0) = packh(O[j][0] * inv0, O[j][1] * inv0);
        *(uint32_t*)(cp + o1) = packh(O[j][2] * inv1, O[j][3] * inv1);
    }
}

// ---------------------------------------------------------------------------
// Host launcher
// ---------------------------------------------------------------------------
extern "C" void kernel_launch(void* const* d_in, const int* in_sizes, int n_in,
                              void* d_out, int out_size)
{
    const float* x   = (const float*)d_in[0];
    const float* rc  = (const float*)d_in[1];
    const float* rs  = (const float*)d_in[2];
    const int*   doc = (const int*)d_in[3];
    const float* Wq  = (const float*)d_in[4];
    const float* Wk  = (const float*)d_in[5];
    const float* Wv  = (const float*)d_in[6];
    const float* Wo  = (const float*)d_in[7];
    float* out = (float*)d_out;

    __half *xp, *wp, *wop, *cp, *qbh, *qbl, *kbh, *kbl, *vbh, *vbl;
    cudaGetSymbolAddress((void**)&xp, g_xp);
    cudaGetSymbolAddress((void**)&wp, g_wp);
    cudaGetSymbolAddress((void**)&wop, g_wop);
    cudaGetSymbolAddress((void**)&cp, g_cp);
    cudaGetSymbolAddress((void**)&qbh, g_qbh);   cudaGetSymbolAddress((void**)&qbl, g_qbl);
    cudaGetSymbolAddress((void**)&kbh, g_kbh);   cudaGetSymbolAddress((void**)&kbl, g_kbl);
    cudaGetSymbolAddress((void**)&vbh, g_vbh);   cudaGetSymbolAddress((void**)&vbl, g_vbl);

    const int flash_smem = 2 * 4 * 64 * LDK * (int)sizeof(__half);  // 73728
    cudaFuncSetAttribute(flash_tc,
                         cudaFuncAttributeMaxDynamicSharedMemorySize, flash_smem);

    // 1. Pack inputs + doc-start scan (one launch)
    pack_all<<<9232, 256>>>(x, Wq, Wk, Wv, Wo, doc, xp, wp, wop);

    // 2. Fused QKV projection with fused RoPE/split epilogue (single-pass)
    {
        dim3 g(3072 / 128, M_ / 128);  // (24, 32)
        gemm_pk<1><<<g, 256>>>(xp, wp, nullptr, 3072, KT_,
                               rc, rs, qbh, qbl, kbh, kbl, vbh, vbl);
    }

    // 3. Tensor-core flash attention -> packed ctx (fp16 hi)
    {
        dim3 g(S_ / 64, NH_, B_);
        flash_tc<<<g, 128, flash_smem>>>(doc, qbh, qbl, kbh, kbl, vbh, vbl, cp);
    }

    // 4. Output projection: out = ctx @ Wo^T (single-pass)
    {
        dim3 g(2048 / 128, M_ / 128);  // (16, 32)
        gemm_pk<0><<<g, 256>>>(cp, wop, out, 2048, KT_,
                               nullptr, nullptr,
                               nullptr, nullptr, nullptr, nullptr, nullptr, nullptr);
    }
}

// round 15
// speedup vs baseline: 2.2172x; 1.0164x over previous
#include <cuda_runtime.h>
#include <cuda_fp16.h>
#include <math.h>
#include <stdint.h>

// Problem constants
#define B_    2
#define S_    2048
#define DIM_  2048
#define NH_   32
#define NKV_  8
#define HD_   64
#define M_    (B_ * S_)        // 4096 rows
#define KT_   64               // K tiles (2048/32)
#define TILE_E 5120            // elems per packed 128x32 tile (40-elem pitch)

#define WK_OFF ((size_t)16 * KT_ * TILE_E)
#define WV_OFF ((size_t)20 * KT_ * TILE_E)

// ---------------------------------------------------------------------------
// Scratch (static device globals — no allocation allowed)
// ---------------------------------------------------------------------------
__device__ int g_dstart[B_ * 8];

// packed-tile fp16 GEMM operands  [tile][128*40]  (hi-only)
__device__ __half g_xp[32 * KT_ * TILE_E];
__device__ __half g_wp[24 * KT_ * TILE_E];
__device__ __half g_wop[16 * KT_ * TILE_E];
__device__ __half g_cp[32 * KT_ * TILE_E];
// flash inputs (row-major fp16 hi/lo, post-rope)
__device__ __half g_qbh[M_ * 2048], g_qbl[M_ * 2048];
__device__ __half g_kbh[M_ * 512],  g_kbl[M_ * 512];
__device__ __half g_vbh[M_ * 512],  g_vbl[M_ * 512];

// ---------------------------------------------------------------------------
// PTX helpers
// ---------------------------------------------------------------------------
__device__ __forceinline__ uint32_t smem_u32(const void* p) {
    uint32_t a;
    asm("{ .reg .u64 t; cvta.to.shared.u64 t, %1; cvt.u32.u64 %0, t; }"
        : "=r"(a) : "l"(p));
    return a;
}
__device__ __forceinline__ void cp16(uint32_t dst, const void* src) {
    asm volatile("cp.async.cg.shared.global [%0], [%1], 16;"
                 :: "r"(dst), "l"(src));
}
__device__ __forceinline__ void cp_commit() {
    asm volatile("cp.async.commit_group;");
}
template<int N>
__device__ __forceinline__ void cp_wait() {
    asm volatile("cp.async.wait_group %0;" :: "n"(N));
}
__device__ __forceinline__ void ldm4(uint32_t* r, uint32_t a) {
    asm volatile("ldmatrix.sync.aligned.m8n8.x4.shared.b16 {%0,%1,%2,%3}, [%4];"
        : "=r"(r[0]), "=r"(r[1]), "=r"(r[2]), "=r"(r[3]) : "r"(a));
}
__device__ __forceinline__ void ldm4t(uint32_t* r, uint32_t a) {
    asm volatile("ldmatrix.sync.aligned.m8n8.x4.trans.shared.b16 {%0,%1,%2,%3}, [%4];"
        : "=r"(r[0]), "=r"(r[1]), "=r"(r[2]), "=r"(r[3]) : "r"(a));
}
// fp16 mma, fp32 accumulate
__device__ __forceinline__ void mma16816(float* c, const uint32_t* a,
                                         uint32_t b0, uint32_t b1) {
    asm volatile(
        "mma.sync.aligned.m16n8k16.row.col.f32.f16.f16.f32 "
        "{%0,%1,%2,%3}, {%4,%5,%6,%7}, {%8,%9}, {%0,%1,%2,%3};"
        : "+f"(c[0]), "+f"(c[1]), "+f"(c[2]), "+f"(c[3])
        : "r"(a[0]), "r"(a[1]), "r"(a[2]), "r"(a[3]), "r"(b0), "r"(b1));
}
__device__ __forceinline__ void mbar_init(uint32_t mbar, uint32_t cnt) {
    asm volatile("mbarrier.init.shared.b64 [%0], %1;" :: "r"(mbar), "r"(cnt) : "memory");
}
__device__ __forceinline__ void mbar_expect(uint32_t mbar, uint32_t bytes) {
    asm volatile("mbarrier.arrive.expect_tx.shared.b64 _, [%0], %1;"
                 :: "r"(mbar), "r"(bytes) : "memory");
}
__device__ __forceinline__ void mbar_wait(uint32_t mbar, uint32_t phase) {
    asm volatile(
        "{\n .reg .pred P;\n"
        "W_%=:\n"
        " mbarrier.try_wait.parity.acquire.cta.shared::cta.b64 P, [%0], %1, 0x989680;\n"
        " @P bra.uni D_%=;\n bra.uni W_%=;\n"
        "D_%=:\n}"
        :: "r"(mbar), "r"(phase) : "memory");
}
__device__ __forceinline__ void bulk_g2s(uint32_t dst, const void* src,
                                         uint32_t bytes, uint32_t mbar) {
    asm volatile(
        "cp.async.bulk.shared::cluster.global.mbarrier::complete_tx::bytes "
        "[%0], [%1], %2, [%3];"
        :: "r"(dst), "l"(src), "r"(bytes), "r"(mbar) : "memory");
}
__device__ __forceinline__ void fence_proxy_async_cta() {
    asm volatile("fence.proxy.async.shared::cta;" ::: "memory");
}
union H2U { __half2 h; uint32_t u; };
__device__ __forceinline__ uint32_t packsplit_h(float x, float y, uint32_t& lo) {
    __half hx = __float2half_rn(x), hy = __float2half_rn(y);
    H2U H, L;
    H.h = __halves2half2(hx, hy);
    L.h = __halves2half2(__float2half_rn(x - __half2float(hx)),
                         __float2half_rn(y - __half2float(hy)));
    lo = L.u;
    return H.u;
}
__device__ __forceinline__ uint32_t packh(float x, float y) {
    H2U H;
    H.h = __halves2half2(__float2half_rn(x), __float2half_rn(y));
    return H.u;
}

// ---------------------------------------------------------------------------
// Fused pack: fp32 [R,2048] row-major -> packed-tile fp16 (hi only),
// 5 tensors, plus doc-start scan.
// ---------------------------------------------------------------------------
__global__ void pack_all(const float* __restrict__ x,
                         const float* __restrict__ wq,
                         const float* __restrict__ wk,
                         const float* __restrict__ wv,
                         const float* __restrict__ wo,
                         const int* __restrict__ doc,
                         __half* __restrict__ xp,
                         __half* __restrict__ wp,
                         __half* __restrict__ wop)
{
    int i = blockIdx.x * blockDim.x + threadIdx.x;
    const float* src;
    __half* hi;
    int li;
    if (i < 1048576)      { src = x;  hi = xp;           li = i; }
    else if (i < 1572864) { src = wq; hi = wp;           li = i - 1048576; }
    else if (i < 1703936) { src = wk; hi = wp + WK_OFF;  li = i - 1572864; }
    else if (i < 1835008) { src = wv; hi = wp + WV_OFF;  li = i - 1703936; }
    else if (i < 2359296) { src = wo; hi = wop;          li = i - 1835008; }
    else if (i < 2359296 + B_ * S_) {
        int li2 = i - 2359296;
        int s = li2 & (S_ - 1);
        int d = doc[li2];
        if (s == 0 || doc[li2 - 1] != d) g_dstart[(li2 >> 11) * 8 + d] = s;
        return;
    } else return;

    int r  = li >> 8;          // kchunks = 256
    int kc = li & 255;
    const float4* s = (const float4*)src + (size_t)li * 2;
    float4 v0 = s[0], v1 = s[1];
    uint32_t h0 = packh(v0.x, v0.y);
    uint32_t h1 = packh(v0.z, v0.w);
    uint32_t h2 = packh(v1.x, v1.y);
    uint32_t h3 = packh(v1.z, v1.w);
    size_t off = ((size_t)(r >> 7) * KT_ + (kc >> 2)) * TILE_E
               + (r & 127) * 40 + (kc & 3) * 8;
    *(uint4*)(hi + off) = make_uint4(h0, h1, h2, h3);
}

// ---------------------------------------------------------------------------
// Packed-tile fp16 single-pass GEMM: C = A*B^T.
// 256 threads, 8 warps: warp tile 32(M) x 64(N).
// 4-stage cp.async.bulk pipeline (3-iteration latency cover).
// MODE 0: fp32 row-major C (O projection).
// MODE 1: fused QKV epilogue (RoPE + scale + fp16 hi/lo split outputs).
// ---------------------------------------------------------------------------
#define NSTG 4
#define STG_E (2 * TILE_E)     // stage elems (A tile + B tile)

template<int MODE>
__global__ __launch_bounds__(256, 2) void gemm_pk(
    const __half* __restrict__ Ah,
    const __half* __restrict__ Bh,
    float* __restrict__ C, int N, int Ktiles,
    const float* __restrict__ cs, const float* __restrict__ sn,
    __half* __restrict__ qbh, __half* __restrict__ qbl,
    __half* __restrict__ kbh, __half* __restrict__ kbl,
    __half* __restrict__ vbh, __half* __restrict__ vbl)
{
    extern __shared__ __align__(128) __half smd[];    // NSTG * STG_E
    __shared__ __align__(8) uint64_t mb[NSTG];

    const int tid = threadIdx.x, lane = tid & 31, w = tid >> 5;
    const int wm = w & 3, wn = w >> 2;     // 4 m-tiles x 2 n-tiles

    const uint32_t mbar[NSTG] = { smem_u32(&mb[0]), smem_u32(&mb[1]),
                                  smem_u32(&mb[2]), smem_u32(&mb[3]) };
    if (tid == 0) {
#pragma unroll
        for (int s = 0; s < NSTG; ++s) mbar_init(mbar[s], 1);
    }
    __syncthreads();

    const size_t tA = (size_t)blockIdx.y * Ktiles;
    const size_t tB = (size_t)blockIdx.x * Ktiles;

    auto issue = [&](int kt, int buf) {
        uint32_t s0 = smem_u32(smd + buf * STG_E);
        mbar_expect(mbar[buf], 2 * TILE_E * 2);
        bulk_g2s(s0,              Ah + (tA + kt) * TILE_E, TILE_E * 2, mbar[buf]);
        bulk_g2s(s0 + TILE_E * 2, Bh + (tB + kt) * TILE_E, TILE_E * 2, mbar[buf]);
    };
    if (tid == 0) { issue(0, 0); issue(1, 1); issue(2, 2); issue(3, 3); }

    float acc[2][8][4];
#pragma unroll
    for (int i = 0; i < 2; ++i)
#pragma unroll
        for (int j = 0; j < 8; ++j)
#pragma unroll
            for (int e = 0; e < 4; ++e) acc[i][j][e] = 0.f;

    int ph[NSTG] = {0, 0, 0, 0};

    for (int kt = 0; kt < Ktiles; ++kt) {
        const int buf = kt & (NSTG - 1);
        if (buf == 0)      { mbar_wait(mbar[0], ph[0]); ph[0] ^= 1; }
        else if (buf == 1) { mbar_wait(mbar[1], ph[1]); ph[1] ^= 1; }
        else if (buf == 2) { mbar_wait(mbar[2], ph[2]); ph[2] ^= 1; }
        else               { mbar_wait(mbar[3], ph[3]); ph[3] ^= 1; }

        const __half* A0 = smd + buf * STG_E;
        const __half* B0 = A0 + TILE_E;

#pragma unroll
        for (int kk = 0; kk < 2; ++kk) {
            const int achk = kk * 2 + (lane >> 4);
            const int arow = wm * 32 + (lane & 15);
            uint32_t ah[2][4];
#pragma unroll
            for (int mt = 0; mt < 2; ++mt)
                ldm4(ah[mt], smem_u32(A0 + (arow + mt * 16) * 40 + achk * 8));
            const int brow = wn * 64 + (lane & 15);
#pragma unroll
            for (int nt = 0; nt < 4; ++nt) {
                uint32_t bh[4];
                ldm4(bh, smem_u32(B0 + (brow + nt * 16) * 40 + achk * 8));
                mma16816(acc[0][2 * nt],     ah[0], bh[0], bh[2]);
                mma16816(acc[0][2 * nt + 1], ah[0], bh[1], bh[3]);
                mma16816(acc[1][2 * nt],     ah[1], bh[0], bh[2]);
                mma16816(acc[1][2 * nt + 1], ah[1], bh[1], bh[3]);
            }
        }
        __syncthreads();
        if (kt + NSTG < Ktiles && tid == 0) {
            fence_proxy_async_cta();
            issue(kt + NSTG, buf);
        }
    }

    const int brow = blockIdx.y * 128 + wm * 32;
    const int bcol = blockIdx.x * 128 + wn * 64;

    if (MODE == 0) {
        // fp32 row-major
#pragma unroll
        for (int mt = 0; mt < 2; ++mt) {
            int r0 = brow + mt * 16 + (lane >> 2);
#pragma unroll
            for (int j = 0; j < 8; ++j) {
                int col = bcol + j * 8 + (lane & 3) * 2;
                *(float2*)(C + (size_t)r0 * N + col) =
                    make_float2(acc[mt][j][0], acc[mt][j][1]);
                *(float2*)(C + (size_t)(r0 + 8) * N + col) =
                    make_float2(acc[mt][j][2], acc[mt][j][3]);
            }
        }
    } else {
        // fused QKV epilogue: rope + scale + fp16 hi/lo split, row-major out.
        __half *dh, *dl;
        int cstride, cbase;
        float scale;
        bool rope;
        if (bcol < 2048)      { dh = qbh; dl = qbl; cstride = 2048; cbase = bcol;        scale = 0.125f; rope = true; }
        else if (bcol < 2560) { dh = kbh; dl = kbl; cstride = 512;  cbase = bcol - 2048; scale = 1.0f;   rope = true; }
        else                  { dh = vbh; dl = vbl; cstride = 512;  cbase = bcol - 2560; scale = 1.0f;   rope = false; }

#pragma unroll
        for (int mt = 0; mt < 2; ++mt) {
#pragma unroll
            for (int half = 0; half < 2; ++half) {
                int row = brow + mt * 16 + (lane >> 2) + half * 8;
                int e = half * 2;                    // acc elems e, e+1
                int s = row & (S_ - 1);
                size_t obase = (size_t)row * cstride + cbase;
                if (rope) {
#pragma unroll
                    for (int j = 0; j < 4; ++j) {
                        int d = j * 8 + (lane & 3) * 2;
                        float c0  = cs[s * 32 + d],     c1  = cs[s * 32 + d + 1];
                        float sv0 = sn[s * 32 + d],     sv1 = sn[s * 32 + d + 1];
                        float x1a = acc[mt][j][e],      x1b = acc[mt][j][e + 1];
                        float x2a = acc[mt][j + 4][e],  x2b = acc[mt][j + 4][e + 1];
                        float y1a = (x1a * c0 - x2a * sv0) * scale;
                        float y1b = (x1b * c1 - x2b * sv1) * scale;
                        float y2a = (x2a * c0 + x1a * sv0) * scale;
                        float y2b = (x2b * c1 + x1b * sv1) * scale;
                        uint32_t lo;
                        uint32_t hi = packsplit_h(y1a, y1b, lo);
                        *(uint32_t*)(dh + obase + d) = hi;
                        *(uint32_t*)(dl + obase + d) = lo;
                        hi = packsplit_h(y2a, y2b, lo);
                        *(uint32_t*)(dh + obase + d + 32) = hi;
                        *(uint32_t*)(dl + obase + d + 32) = lo;
                    }
                } else {
#pragma unroll
                    for (int j = 0; j < 8; ++j) {
                        int d = j * 8 + (lane & 3) * 2;
                        uint32_t lo;
                        uint32_t hi = packsplit_h(acc[mt][j][e], acc[mt][j][e + 1], lo);
                        *(uint32_t*)(dh + obase + d) = hi;
                        *(uint32_t*)(dl + obase + d) = lo;
                    }
                }
            }
        }
    }
}

// ---------------------------------------------------------------------------
// Tensor-core flash attention (fp16 hi/lo, 3-pass — unchanged).
// Q parked in stage-1 smem -> 72KB -> 3 CTAs/SM. ctx written fp16 hi only.
// ---------------------------------------------------------------------------
#define LDK 72

__global__ __launch_bounds__(128, 3) void flash_tc(
    const int* __restrict__ doc,
    const __half* __restrict__ qhi, const __half* __restrict__ qlo,
    const __half* __restrict__ khi, const __half* __restrict__ klo,
    const __half* __restrict__ vhi, const __half* __restrict__ vlo,
    __half* __restrict__ cp)
{
    extern __shared__ __align__(16) char smraw[];
    __half* sT  = (__half*)smraw;      // 2 stages x (Kh|Kl|Vh|Vl)
    __shared__ int qdoc[64];
    __shared__ int kdoc[2][64];

    const int tid  = threadIdx.x;
    const int lane = tid & 31;
    const int w    = tid >> 5;
    const int qb = blockIdx.x, h = blockIdx.y, b = blockIdx.z;
    const int kvh = h >> 2;
    const int q0  = qb * 64;
    const int TILE = 64 * LDK;

    __half* sQh = sT + 4 * TILE;
    __half* sQl = sT + 5 * TILE;

    {
        const __half* srch = qhi + ((size_t)(b * S_ + q0)) * 2048 + h * 64;
        const __half* srcl = qlo + ((size_t)(b * S_ + q0)) * 2048 + h * 64;
        uint32_t dh = smem_u32(sQh), dl = smem_u32(sQl);
        for (int i = tid; i < 512; i += 128) {
            int r = i >> 3, c = i & 7;
            uint32_t off = (uint32_t)(r * LDK + c * 8) * 2;
            cp16(dh + off, srch + (size_t)r * 2048 + c * 8);
            cp16(dl + off, srcl + (size_t)r * 2048 + c * 8);
        }
        if (tid < 64) qdoc[tid] = doc[b * S_ + q0 + tid];
    }
    cp_commit();

    const int kb0 = g_dstart[b * 8 + doc[b * S_ + q0]] >> 6;

    auto load_kv = [&](int kb, int buf) {
        const size_t row0 = (size_t)(b * S_ + kb * 64);
        const __half* s0 = khi + row0 * 512 + kvh * 64;
        const __half* s1 = klo + row0 * 512 + kvh * 64;
        const __half* s2 = vhi + row0 * 512 + kvh * 64;
        const __half* s3 = vlo + row0 * 512 + kvh * 64;
        uint32_t d0 = smem_u32(sT + buf * 4 * TILE);
        const uint32_t tb = (uint32_t)TILE * 2;
        for (int i = tid; i < 512; i += 128) {
            int r = i >> 3, c = i & 7;
            uint32_t off = (uint32_t)(r * LDK + c * 8) * 2;
            size_t go = (size_t)r * 512 + c * 8;
            cp16(d0 + off,          s0 + go);
            cp16(d0 + tb + off,     s1 + go);
            cp16(d0 + 2 * tb + off, s2 + go);
            cp16(d0 + 3 * tb + off, s3 + go);
        }
        if (tid < 64) kdoc[buf][tid] = doc[b * S_ + kb * 64 + tid];
    };

    load_kv(kb0, 0);
    cp_commit();
    cp_wait<1>();
    __syncthreads();

    uint32_t qah[4][4], qal[4][4];
    {
        int row = w * 16 + (lane & 15);
        int col = (lane >> 4) * 8;
#pragma unroll
        for (int s = 0; s < 4; ++s) {
            ldm4(qah[s], smem_u32(sQh + row * LDK + col + s * 16));
            ldm4(qal[s], smem_u32(sQl + row * LDK + col + s * 16));
        }
    }
    __syncthreads();   // all warps have Q frags; stage-1 may be overwritten

    const int g   = lane >> 2;
    const int r0g = q0 + w * 16 + g;
    const int r1g = r0g + 8;
    const int qd0 = qdoc[w * 16 + g];
    const int qd1 = qdoc[w * 16 + g + 8];

    float m0 = -1e30f, m1 = -1e30f, l0 = 0.f, l1 = 0.f;
    float O[8][4];
#pragma unroll
    for (int j = 0; j < 8; ++j)
#pragma unroll
        for (int e = 0; e < 4; ++e) O[j][e] = 0.f;

    for (int kb = kb0; kb <= qb; ++kb) {
        const int buf = (kb - kb0) & 1;
        cp_wait<0>();
        __syncthreads();
        if (kb < qb) { load_kv(kb + 1, buf ^ 1); cp_commit(); }

        const __half* Kh = sT + buf * 4 * TILE;
        const __half* Kl = Kh + TILE;
        const __half* Vh = Kl + TILE;
        const __half* Vl = Vh + TILE;

        float Sf[8][4];
#pragma unroll
        for (int j = 0; j < 8; ++j) {
            Sf[j][0] = Sf[j][1] = Sf[j][2] = Sf[j][3] = 0.f;
            uint32_t bh[2][4], bl[2][4];
            int row = j * 8 + (lane & 7);
            int col = (lane >> 3) * 8;
            ldm4(bh[0], smem_u32(Kh + row * LDK + col));
            ldm4(bh[1], smem_u32(Kh + row * LDK + col + 32));
            ldm4(bl[0], smem_u32(Kl + row * LDK + col));
            ldm4(bl[1], smem_u32(Kl + row * LDK + col + 32));
#pragma unroll
            for (int s = 0; s < 4; ++s) {
                int ch = s >> 1, wh = (s & 1) * 2;
                mma16816(Sf[j], qah[s], bh[ch][wh], bh[ch][wh + 1]);
                mma16816(Sf[j], qah[s], bl[ch][wh], bl[ch][wh + 1]);
                mma16816(Sf[j], qal[s], bh[ch][wh], bh[ch][wh + 1]);
            }
        }

        const int kbase = kb * 64;
#pragma unroll
        for (int j = 0; j < 8; ++j) {
            int cl  = j * 8 + (lane & 3) * 2;
            int c0g = kbase + cl, c1g = c0g + 1;
            int kd0 = kdoc[buf][cl], kd1 = kdoc[buf][cl + 1];
            if (c0g > r0g || kd0 != qd0) Sf[j][0] = -1e30f;
            if (c1g > r0g || kd1 != qd0) Sf[j][1] = -1e30f;
            if (c0g > r1g || kd0 != qd1) Sf[j][2] = -1e30f;
            if (c1g > r1g || kd1 != qd1) Sf[j][3] = -1e30f;
        }

        float t0 = -1e30f, t1 = -1e30f;
#pragma unroll
        for (int j = 0; j < 8; ++j) {
            t0 = fmaxf(t0, fmaxf(Sf[j][0], Sf[j][1]));
            t1 = fmaxf(t1, fmaxf(Sf[j][2], Sf[j][3]));
        }
        t0 = fmaxf(t0, __shfl_xor_sync(0xffffffffu, t0, 1));
        t0 = fmaxf(t0, __shfl_xor_sync(0xffffffffu, t0, 2));
        t1 = fmaxf(t1, __shfl_xor_sync(0xffffffffu, t1, 1));
        t1 = fmaxf(t1, __shfl_xor_sync(0xffffffffu, t1, 2));
        float mn0 = fmaxf(m0, t0), mn1 = fmaxf(m1, t1);
        float corr0 = __expf(m0 - mn0), corr1 = __expf(m1 - mn1);
        m0 = mn0; m1 = mn1;
        float rs0 = 0.f, rs1 = 0.f;
#pragma unroll
        for (int j = 0; j < 8; ++j) {
            Sf[j][0] = __expf(Sf[j][0] - mn0);
            Sf[j][1] = __expf(Sf[j][1] - mn0);
            Sf[j][2] = __expf(Sf[j][2] - mn1);
            Sf[j][3] = __expf(Sf[j][3] - mn1);
            rs0 += Sf[j][0] + Sf[j][1];
            rs1 += Sf[j][2] + Sf[j][3];
        }
        rs0 += __shfl_xor_sync(0xffffffffu, rs0, 1);
        rs0 += __shfl_xor_sync(0xffffffffu, rs0, 2);
        rs1 += __shfl_xor_sync(0xffffffffu, rs1, 1);
        rs1 += __shfl_xor_sync(0xffffffffu, rs1, 2);
        l0 = l0 * corr0 + rs0;
        l1 = l1 * corr1 + rs1;
#pragma unroll
        for (int j = 0; j < 8; ++j) {
            O[j][0] *= corr0; O[j][1] *= corr0;
            O[j][2] *= corr1; O[j][3] *= corr1;
        }

        uint32_t pah[4][4], pal[4][4];
#pragma unroll
        for (int s = 0; s < 4; ++s) {
            pah[s][0] = packsplit_h(Sf[2 * s][0],     Sf[2 * s][1],     pal[s][0]);
            pah[s][1] = packsplit_h(Sf[2 * s][2],     Sf[2 * s][3],     pal[s][1]);
            pah[s][2] = packsplit_h(Sf[2 * s + 1][0], Sf[2 * s + 1][1], pal[s][2]);
            pah[s][3] = packsplit_h(Sf[2 * s + 1][2], Sf[2 * s + 1][3], pal[s][3]);
        }

#pragma unroll
        for (int j = 0; j < 8; ++j) {
            uint32_t bvh[2][4], bvl[2][4];
            int vr = lane & 31;
            ldm4t(bvh[0], smem_u32(Vh + vr * LDK + j * 8));
            ldm4t(bvh[1], smem_u32(Vh + (32 + vr) * LDK + j * 8));
            ldm4t(bvl[0], smem_u32(Vl + vr * LDK + j * 8));
            ldm4t(bvl[1], smem_u32(Vl + (32 + vr) * LDK + j * 8));
#pragma unroll
            for (int s = 0; s < 4; ++s) {
                int ch = s >> 1, wh = (s & 1) * 2;
                mma16816(O[j], pah[s], bvh[ch][wh], bvh[ch][wh + 1]);
                mma16816(O[j], pah[s], bvl[ch][wh], bvl[ch][wh + 1]);
                mma16816(O[j], pal[s], bvh[ch][wh], bvh[ch][wh + 1]);
            }
        }
    }

    // ---- epilogue: write ctx in packed-tile layout (fp16 hi only) ----
    float inv0 = 1.0f / l0, inv1 = 1.0f / l1;
    int grow0 = b * S_ + r0g;
    int grow1 = grow0 + 8;
#pragma unroll
    for (int j = 0; j < 8; ++j) {
        int col = h * 64 + j * 8 + (lane & 3) * 2;
        size_t tbase = ((size_t)(grow0 >> 7) * KT_ + (col >> 5)) * TILE_E
                     + ((col >> 3) & 3) * 8 + (col & 7);
        size_t o0 = tbase + (grow0 & 127) * 40;
        size_t o1 = tbase + (grow1 & 127) * 40;
        *(uint32_t*)(cp + o0) = packh(O[j][0] * inv0, O[j][1] * inv0);
        *(uint32_t*)(cp + o1) = packh(O[j][2] * inv1, O[j][3] * inv1);
    }
}

// ---------------------------------------------------------------------------
// Host launcher
// ---------------------------------------------------------------------------
extern "C" void kernel_launch(void* const* d_in, const int* in_sizes, int n_in,
                              void* d_out, int out_size)
{
    const float* x   = (const float*)d_in[0];
    const float* rc  = (const float*)d_in[1];
    const float* rs  = (const float*)d_in[2];
    const int*   doc = (const int*)d_in[3];
    const float* Wq  = (const float*)d_in[4];
    const float* Wk  = (const float*)d_in[5];
    const float* Wv  = (const float*)d_in[6];
    const float* Wo  = (const float*)d_in[7];
    float* out = (float*)d_out;

    __half *xp, *wp, *wop, *cp, *qbh, *qbl, *kbh, *kbl, *vbh, *vbl;
    cudaGetSymbolAddress((void**)&xp, g_xp);
    cudaGetSymbolAddress((void**)&wp, g_wp);
    cudaGetSymbolAddress((void**)&wop, g_wop);
    cudaGetSymbolAddress((void**)&cp, g_cp);
    cudaGetSymbolAddress((void**)&qbh, g_qbh);   cudaGetSymbolAddress((void**)&qbl, g_qbl);
    cudaGetSymbolAddress((void**)&kbh, g_kbh);   cudaGetSymbolAddress((void**)&kbl, g_kbl);
    cudaGetSymbolAddress((void**)&vbh, g_vbh);   cudaGetSymbolAddress((void**)&vbl, g_vbl);

    const int flash_smem = 2 * 4 * 64 * LDK * (int)sizeof(__half);  // 73728
    cudaFuncSetAttribute(flash_tc,
                         cudaFuncAttributeMaxDynamicSharedMemorySize, flash_smem);

    const int gemm_smem = NSTG * STG_E * (int)sizeof(__half);       // 81920
    cudaFuncSetAttribute(gemm_pk<0>,
                         cudaFuncAttributeMaxDynamicSharedMemorySize, gemm_smem);
    cudaFuncSetAttribute(gemm_pk<1>,
                         cudaFuncAttributeMaxDynamicSharedMemorySize, gemm_smem);

    // 1. Pack inputs + doc-start scan (one launch)
    pack_all<<<9232, 256>>>(x, Wq, Wk, Wv, Wo, doc, xp, wp, wop);

    // 2. Fused QKV projection with fused RoPE/split epilogue (single-pass)
    {
        dim3 g(3072 / 128, M_ / 128);  // (24, 32)
        gemm_pk<1><<<g, 256, gemm_smem>>>(xp, wp, nullptr, 3072, KT_,
                                          rc, rs, qbh, qbl, kbh, kbl, vbh, vbl);
    }

    // 3. Tensor-core flash attention -> packed ctx (fp16 hi)
    {
        dim3 g(S_ / 64, NH_, B_);
        flash_tc<<<g, 128, flash_smem>>>(doc, qbh, qbl, kbh, kbl, vbh, vbl, cp);
    }

    // 4. Output projection: out = ctx @ Wo^T (single-pass)
    {
        dim3 g(2048 / 128, M_ / 128);  // (16, 32)
        gemm_pk<0><<<g, 256, gemm_smem>>>(cp, wop, out, 2048, KT_,
                                          nullptr, nullptr,
                                          nullptr, nullptr, nullptr, nullptr,
                                          nullptr, nullptr);
    }
}

// round 16
// speedup vs baseline: 2.2967x; 1.0359x over previous
#include <cuda_runtime.h>
#include <cuda_fp16.h>
#include <math.h>
#include <stdint.h>

// Problem constants
#define B_    2
#define S_    2048
#define DIM_  2048
#define NH_   32
#define NKV_  8
#define HD_   64
#define M_    (B_ * S_)        // 4096 rows
#define KT_   64               // K tiles (2048/32)
#define TILE_E 5120            // elems per packed 128x32 tile (40-elem pitch)

#define WK_OFF ((size_t)16 * KT_ * TILE_E)
#define WV_OFF ((size_t)20 * KT_ * TILE_E)

// ---------------------------------------------------------------------------
// Scratch (static device globals — no allocation allowed)
// ---------------------------------------------------------------------------
__device__ int g_dstart[B_ * 8];

// packed-tile fp16 GEMM operands  [tile][128*40]  (hi-only)
__device__ __half g_xp[32 * KT_ * TILE_E];
__device__ __half g_wp[24 * KT_ * TILE_E];
__device__ __half g_wop[16 * KT_ * TILE_E];
__device__ __half g_cp[32 * KT_ * TILE_E];
// flash inputs (row-major fp16 hi/lo, post-rope)
__device__ __half g_qbh[M_ * 2048], g_qbl[M_ * 2048];
__device__ __half g_kbh[M_ * 512],  g_kbl[M_ * 512];
__device__ __half g_vbh[M_ * 512],  g_vbl[M_ * 512];

// ---------------------------------------------------------------------------
// PTX helpers
// ---------------------------------------------------------------------------
__device__ __forceinline__ uint32_t smem_u32(const void* p) {
    uint32_t a;
    asm("{ .reg .u64 t; cvta.to.shared.u64 t, %1; cvt.u32.u64 %0, t; }"
        : "=r"(a) : "l"(p));
    return a;
}
__device__ __forceinline__ void cp16(uint32_t dst, const void* src) {
    asm volatile("cp.async.cg.shared.global [%0], [%1], 16;"
                 :: "r"(dst), "l"(src));
}
__device__ __forceinline__ void cp_commit() {
    asm volatile("cp.async.commit_group;");
}
template<int N>
__device__ __forceinline__ void cp_wait() {
    asm volatile("cp.async.wait_group %0;" :: "n"(N));
}
__device__ __forceinline__ void ldm4(uint32_t* r, uint32_t a) {
    asm volatile("ldmatrix.sync.aligned.m8n8.x4.shared.b16 {%0,%1,%2,%3}, [%4];"
        : "=r"(r[0]), "=r"(r[1]), "=r"(r[2]), "=r"(r[3]) : "r"(a));
}
__device__ __forceinline__ void ldm4t(uint32_t* r, uint32_t a) {
    asm volatile("ldmatrix.sync.aligned.m8n8.x4.trans.shared.b16 {%0,%1,%2,%3}, [%4];"
        : "=r"(r[0]), "=r"(r[1]), "=r"(r[2]), "=r"(r[3]) : "r"(a));
}
// fp16 mma, fp32 accumulate
__device__ __forceinline__ void mma16816(float* c, const uint32_t* a,
                                         uint32_t b0, uint32_t b1) {
    asm volatile(
        "mma.sync.aligned.m16n8k16.row.col.f32.f16.f16.f32 "
        "{%0,%1,%2,%3}, {%4,%5,%6,%7}, {%8,%9}, {%0,%1,%2,%3};"
        : "+f"(c[0]), "+f"(c[1]), "+f"(c[2]), "+f"(c[3])
        : "r"(a[0]), "r"(a[1]), "r"(a[2]), "r"(a[3]), "r"(b0), "r"(b1));
}
__device__ __forceinline__ void mbar_init(uint32_t mbar, uint32_t cnt) {
    asm volatile("mbarrier.init.shared.b64 [%0], %1;" :: "r"(mbar), "r"(cnt) : "memory");
}
__device__ __forceinline__ void mbar_expect(uint32_t mbar, uint32_t bytes) {
    asm volatile("mbarrier.arrive.expect_tx.shared.b64 _, [%0], %1;"
                 :: "r"(mbar), "r"(bytes) : "memory");
}
__device__ __forceinline__ void mbar_wait(uint32_t mbar, uint32_t phase) {
    asm volatile(
        "{\n .reg .pred P;\n"
        "W_%=:\n"
        " mbarrier.try_wait.parity.acquire.cta.shared::cta.b64 P, [%0], %1, 0x989680;\n"
        " @P bra.uni D_%=;\n bra.uni W_%=;\n"
        "D_%=:\n}"
        :: "r"(mbar), "r"(phase) : "memory");
}
__device__ __forceinline__ void bulk_g2s(uint32_t dst, const void* src,
                                         uint32_t bytes, uint32_t mbar) {
    asm volatile(
        "cp.async.bulk.shared::cluster.global.mbarrier::complete_tx::bytes "
        "[%0], [%1], %2, [%3];"
        :: "r"(dst), "l"(src), "r"(bytes), "r"(mbar) : "memory");
}
__device__ __forceinline__ void fence_proxy_async_cta() {
    asm volatile("fence.proxy.async.shared::cta;" ::: "memory");
}
union H2U { __half2 h; uint32_t u; };
__device__ __forceinline__ uint32_t packsplit_h(float x, float y, uint32_t& lo) {
    __half hx = __float2half_rn(x), hy = __float2half_rn(y);
    H2U H, L;
    H.h = __halves2half2(hx, hy);
    L.h = __halves2half2(__float2half_rn(x - __half2float(hx)),
                         __float2half_rn(y - __half2float(hy)));
    lo = L.u;
    return H.u;
}
__device__ __forceinline__ uint32_t packh(float x, float y) {
    H2U H;
    H.h = __halves2half2(__float2half_rn(x), __float2half_rn(y));
    return H.u;
}

// ---------------------------------------------------------------------------
// Fused pack: fp32 [R,2048] row-major -> packed-tile fp16 (hi only),
// 5 tensors, plus doc-start scan.
// ---------------------------------------------------------------------------
__global__ void pack_all(const float* __restrict__ x,
                         const float* __restrict__ wq,
                         const float* __restrict__ wk,
                         const float* __restrict__ wv,
                         const float* __restrict__ wo,
                         const int* __restrict__ doc,
                         __half* __restrict__ xp,
                         __half* __restrict__ wp,
                         __half* __restrict__ wop)
{
    int i = blockIdx.x * blockDim.x + threadIdx.x;
    const float* src;
    __half* hi;
    int li;
    if (i < 1048576)      { src = x;  hi = xp;           li = i; }
    else if (i < 1572864) { src = wq; hi = wp;           li = i - 1048576; }
    else if (i < 1703936) { src = wk; hi = wp + WK_OFF;  li = i - 1572864; }
    else if (i < 1835008) { src = wv; hi = wp + WV_OFF;  li = i - 1703936; }
    else if (i < 2359296) { src = wo; hi = wop;          li = i - 1835008; }
    else if (i < 2359296 + B_ * S_) {
        int li2 = i - 2359296;
        int s = li2 & (S_ - 1);
        int d = doc[li2];
        if (s == 0 || doc[li2 - 1] != d) g_dstart[(li2 >> 11) * 8 + d] = s;
        return;
    } else return;

    int r  = li >> 8;          // kchunks = 256
    int kc = li & 255;
    const float4* s = (const float4*)src + (size_t)li * 2;
    float4 v0 = s[0], v1 = s[1];
    uint32_t h0 = packh(v0.x, v0.y);
    uint32_t h1 = packh(v0.z, v0.w);
    uint32_t h2 = packh(v1.x, v1.y);
    uint32_t h3 = packh(v1.z, v1.w);
    size_t off = ((size_t)(r >> 7) * KT_ + (kc >> 2)) * TILE_E
               + (r & 127) * 40 + (kc & 3) * 8;
    *(uint4*)(hi + off) = make_uint4(h0, h1, h2, h3);
}

// ---------------------------------------------------------------------------
// Packed-tile fp16 single-pass GEMM: C = A*B^T.
// 256 threads, 8 warps: warp tile 32(M) x 64(N).
// 2-stage pipeline, K=64 per stage (2 contiguous packed k-tiles per bulk copy)
// -> halves per-iteration barrier/mbar overhead vs K=32 stages.
// MODE 0: fp32 row-major C (O projection).
// MODE 1: fused QKV epilogue (RoPE + scale + fp16 hi/lo split outputs).
// ---------------------------------------------------------------------------
#define NSTG 2
#define STG_E (4 * TILE_E)     // stage elems: A (2 k-tiles) + B (2 k-tiles)

template<int MODE>
__global__ __launch_bounds__(256, 2) void gemm_pk(
    const __half* __restrict__ Ah,
    const __half* __restrict__ Bh,
    float* __restrict__ C, int N, int Ktiles,
    const float* __restrict__ cs, const float* __restrict__ sn,
    __half* __restrict__ qbh, __half* __restrict__ qbl,
    __half* __restrict__ kbh, __half* __restrict__ kbl,
    __half* __restrict__ vbh, __half* __restrict__ vbl)
{
    extern __shared__ __align__(128) __half smd[];    // NSTG * STG_E
    __shared__ __align__(8) uint64_t mb[NSTG];

    const int tid = threadIdx.x, lane = tid & 31, w = tid >> 5;
    const int wm = w & 3, wn = w >> 2;     // 4 m-tiles x 2 n-tiles

    const uint32_t mbar0 = smem_u32(&mb[0]);
    const uint32_t mbar1 = smem_u32(&mb[1]);
    if (tid == 0) { mbar_init(mbar0, 1); mbar_init(mbar1, 1); }
    __syncthreads();

    const size_t tA = (size_t)blockIdx.y * Ktiles;
    const size_t tB = (size_t)blockIdx.x * Ktiles;
    const int NS = Ktiles >> 1;            // stages of K=64

    auto issue = [&](int ks, int buf) {
        uint32_t s0 = smem_u32(smd + buf * STG_E);
        uint32_t mbar = buf ? mbar1 : mbar0;
        mbar_expect(mbar, 4 * TILE_E * 2);
        bulk_g2s(s0,                  Ah + (tA + ks * 2) * TILE_E, 2 * TILE_E * 2, mbar);
        bulk_g2s(s0 + 2 * TILE_E * 2, Bh + (tB + ks * 2) * TILE_E, 2 * TILE_E * 2, mbar);
    };
    if (tid == 0) { issue(0, 0); issue(1, 1); }

    float acc[2][8][4];
#pragma unroll
    for (int i = 0; i < 2; ++i)
#pragma unroll
        for (int j = 0; j < 8; ++j)
#pragma unroll
            for (int e = 0; e < 4; ++e) acc[i][j][e] = 0.f;

    int ph0 = 0, ph1 = 0;

    for (int ks = 0; ks < NS; ++ks) {
        const int buf = ks & 1;
        if (buf == 0) { mbar_wait(mbar0, ph0); ph0 ^= 1; }
        else          { mbar_wait(mbar1, ph1); ph1 ^= 1; }

        const __half* stg = smd + buf * STG_E;

#pragma unroll
        for (int st = 0; st < 2; ++st) {
            const __half* A0 = stg + st * TILE_E;
            const __half* B0 = stg + 2 * TILE_E + st * TILE_E;
#pragma unroll
            for (int kk = 0; kk < 2; ++kk) {
                const int achk = kk * 2 + (lane >> 4);
                const int arow = wm * 32 + (lane & 15);
                uint32_t ah[2][4];
#pragma unroll
                for (int mt = 0; mt < 2; ++mt)
                    ldm4(ah[mt], smem_u32(A0 + (arow + mt * 16) * 40 + achk * 8));
                const int brow = wn * 64 + (lane & 15);
#pragma unroll
                for (int nt = 0; nt < 4; ++nt) {
                    uint32_t bh[4];
                    ldm4(bh, smem_u32(B0 + (brow + nt * 16) * 40 + achk * 8));
                    mma16816(acc[0][2 * nt],     ah[0], bh[0], bh[2]);
                    mma16816(acc[0][2 * nt + 1], ah[0], bh[1], bh[3]);
                    mma16816(acc[1][2 * nt],     ah[1], bh[0], bh[2]);
                    mma16816(acc[1][2 * nt + 1], ah[1], bh[1], bh[3]);
                }
            }
        }
        __syncthreads();
        if (ks + 2 < NS && tid == 0) {
            fence_proxy_async_cta();
            issue(ks + 2, buf);
        }
    }

    const int brow = blockIdx.y * 128 + wm * 32;
    const int bcol = blockIdx.x * 128 + wn * 64;

    if (MODE == 0) {
        // fp32 row-major
#pragma unroll
        for (int mt = 0; mt < 2; ++mt) {
            int r0 = brow + mt * 16 + (lane >> 2);
#pragma unroll
            for (int j = 0; j < 8; ++j) {
                int col = bcol + j * 8 + (lane & 3) * 2;
                *(float2*)(C + (size_t)r0 * N + col) =
                    make_float2(acc[mt][j][0], acc[mt][j][1]);
                *(float2*)(C + (size_t)(r0 + 8) * N + col) =
                    make_float2(acc[mt][j][2], acc[mt][j][3]);
            }
        }
    } else {
        // fused QKV epilogue: rope + scale + fp16 hi/lo split, row-major out.
        __half *dh, *dl;
        int cstride, cbase;
        float scale;
        bool rope;
        if (bcol < 2048)      { dh = qbh; dl = qbl; cstride = 2048; cbase = bcol;        scale = 0.125f; rope = true; }
        else if (bcol < 2560) { dh = kbh; dl = kbl; cstride = 512;  cbase = bcol - 2048; scale = 1.0f;   rope = true; }
        else                  { dh = vbh; dl = vbl; cstride = 512;  cbase = bcol - 2560; scale = 1.0f;   rope = false; }

#pragma unroll
        for (int mt = 0; mt < 2; ++mt) {
#pragma unroll
            for (int half = 0; half < 2; ++half) {
                int row = brow + mt * 16 + (lane >> 2) + half * 8;
                int e = half * 2;                    // acc elems e, e+1
                int s = row & (S_ - 1);
                size_t obase = (size_t)row * cstride + cbase;
                if (rope) {
#pragma unroll
                    for (int j = 0; j < 4; ++j) {
                        int d = j * 8 + (lane & 3) * 2;
                        float c0  = cs[s * 32 + d],     c1  = cs[s * 32 + d + 1];
                        float sv0 = sn[s * 32 + d],     sv1 = sn[s * 32 + d + 1];
                        float x1a = acc[mt][j][e],      x1b = acc[mt][j][e + 1];
                        float x2a = acc[mt][j + 4][e],  x2b = acc[mt][j + 4][e + 1];
                        float y1a = (x1a * c0 - x2a * sv0) * scale;
                        float y1b = (x1b * c1 - x2b * sv1) * scale;
                        float y2a = (x2a * c0 + x1a * sv0) * scale;
                        float y2b = (x2b * c1 + x1b * sv1) * scale;
                        uint32_t lo;
                        uint32_t hi = packsplit_h(y1a, y1b, lo);
                        *(uint32_t*)(dh + obase + d) = hi;
                        *(uint32_t*)(dl + obase + d) = lo;
                        hi = packsplit_h(y2a, y2b, lo);
                        *(uint32_t*)(dh + obase + d + 32) = hi;
                        *(uint32_t*)(dl + obase + d + 32) = lo;
                    }
                } else {
#pragma unroll
                    for (int j = 0; j < 8; ++j) {
                        int d = j * 8 + (lane & 3) * 2;
                        uint32_t lo;
                        uint32_t hi = packsplit_h(acc[mt][j][e], acc[mt][j][e + 1], lo);
                        *(uint32_t*)(dh + obase + d) = hi;
                        *(uint32_t*)(dl + obase + d) = lo;
                    }
                }
            }
        }
    }
}

// ---------------------------------------------------------------------------
// Tensor-core flash attention (fp16 hi/lo, 3-pass — unchanged).
// Q parked in stage-1 smem -> 72KB -> 3 CTAs/SM. ctx written fp16 hi only.
// ---------------------------------------------------------------------------
#define LDK 72

__global__ __launch_bounds__(128, 3) void flash_tc(
    const int* __restrict__ doc,
    const __half* __restrict__ qhi, const __half* __restrict__ qlo,
    const __half* __restrict__ khi, const __half* __restrict__ klo,
    const __half* __restrict__ vhi, const __half* __restrict__ vlo,
    __half* __restrict__ cp)
{
    extern __shared__ __align__(16) char smraw[];
    __half* sT  = (__half*)smraw;      // 2 stages x (Kh|Kl|Vh|Vl)
    __shared__ int qdoc[64];
    __shared__ int kdoc[2][64];

    const int tid  = threadIdx.x;
    const int lane = tid & 31;
    const int w    = tid >> 5;
    const int qb = blockIdx.x, h = blockIdx.y, b = blockIdx.z;
    const int kvh = h >> 2;
    const int q0  = qb * 64;
    const int TILE = 64 * LDK;

    __half* sQh = sT + 4 * TILE;
    __half* sQl = sT + 5 * TILE;

    {
        const __half* srch = qhi + ((size_t)(b * S_ + q0)) * 2048 + h * 64;
        const __half* srcl = qlo + ((size_t)(b * S_ + q0)) * 2048 + h * 64;
        uint32_t dh = smem_u32(sQh), dl = smem_u32(sQl);
        for (int i = tid; i < 512; i += 128) {
            int r = i >> 3, c = i & 7;
            uint32_t off = (uint32_t)(r * LDK + c * 8) * 2;
            cp16(dh + off, srch + (size_t)r * 2048 + c * 8);
            cp16(dl + off, srcl + (size_t)r * 2048 + c * 8);
        }
        if (tid < 64) qdoc[tid] = doc[b * S_ + q0 + tid];
    }
    cp_commit();

    const int kb0 = g_dstart[b * 8 + doc[b * S_ + q0]] >> 6;

    auto load_kv = [&](int kb, int buf) {
        const size_t row0 = (size_t)(b * S_ + kb * 64);
        const __half* s0 = khi + row0 * 512 + kvh * 64;
        const __half* s1 = klo + row0 * 512 + kvh * 64;
        const __half* s2 = vhi + row0 * 512 + kvh * 64;
        const __half* s3 = vlo + row0 * 512 + kvh * 64;
        uint32_t d0 = smem_u32(sT + buf * 4 * TILE);
        const uint32_t tb = (uint32_t)TILE * 2;
        for (int i = tid; i < 512; i += 128) {
            int r = i >> 3, c = i & 7;
            uint32_t off = (uint32_t)(r * LDK + c * 8) * 2;
            size_t go = (size_t)r * 512 + c * 8;
            cp16(d0 + off,          s0 + go);
            cp16(d0 + tb + off,     s1 + go);
            cp16(d0 + 2 * tb + off, s2 + go);
            cp16(d0 + 3 * tb + off, s3 + go);
        }
        if (tid < 64) kdoc[buf][tid] = doc[b * S_ + kb * 64 + tid];
    };

    load_kv(kb0, 0);
    cp_commit();
    cp_wait<1>();
    __syncthreads();

    uint32_t qah[4][4], qal[4][4];
    {
        int row = w * 16 + (lane & 15);
        int col = (lane >> 4) * 8;
#pragma unroll
        for (int s = 0; s < 4; ++s) {
            ldm4(qah[s], smem_u32(sQh + row * LDK + col + s * 16));
            ldm4(qal[s], smem_u32(sQl + row * LDK + col + s * 16));
        }
    }
    __syncthreads();   // all warps have Q frags; stage-1 may be overwritten

    const int g   = lane >> 2;
    const int r0g = q0 + w * 16 + g;
    const int r1g = r0g + 8;
    const int qd0 = qdoc[w * 16 + g];
    const int qd1 = qdoc[w * 16 + g + 8];

    float m0 = -1e30f, m1 = -1e30f, l0 = 0.f, l1 = 0.f;
    float O[8][4];
#pragma unroll
    for (int j = 0; j < 8; ++j)
#pragma unroll
        for (int e = 0; e < 4; ++e) O[j][e] = 0.f;

    for (int kb = kb0; kb <= qb; ++kb) {
        const int buf = (kb - kb0) & 1;
        cp_wait<0>();
        __syncthreads();
        if (kb < qb) { load_kv(kb + 1, buf ^ 1); cp_commit(); }

        const __half* Kh = sT + buf * 4 * TILE;
        const __half* Kl = Kh + TILE;
        const __half* Vh = Kl + TILE;
        const __half* Vl = Vh + TILE;

        float Sf[8][4];
#pragma unroll
        for (int j = 0; j < 8; ++j) {
            Sf[j][0] = Sf[j][1] = Sf[j][2] = Sf[j][3] = 0.f;
            uint32_t bh[2][4], bl[2][4];
            int row = j * 8 + (lane & 7);
            int col = (lane >> 3) * 8;
            ldm4(bh[0], smem_u32(Kh + row * LDK + col));
            ldm4(bh[1], smem_u32(Kh + row * LDK + col + 32));
            ldm4(bl[0], smem_u32(Kl + row * LDK + col));
            ldm4(bl[1], smem_u32(Kl + row * LDK + col + 32));
#pragma unroll
            for (int s = 0; s < 4; ++s) {
                int ch = s >> 1, wh = (s & 1) * 2;
                mma16816(Sf[j], qah[s], bh[ch][wh], bh[ch][wh + 1]);
                mma16816(Sf[j], qah[s], bl[ch][wh], bl[ch][wh + 1]);
                mma16816(Sf[j], qal[s], bh[ch][wh], bh[ch][wh + 1]);
            }
        }

        const int kbase = kb * 64;
#pragma unroll
        for (int j = 0; j < 8; ++j) {
            int cl  = j * 8 + (lane & 3) * 2;
            int c0g = kbase + cl, c1g = c0g + 1;
            int kd0 = kdoc[buf][cl], kd1 = kdoc[buf][cl + 1];
            if (c0g > r0g || kd0 != qd0) Sf[j][0] = -1e30f;
            if (c1g > r0g || kd1 != qd0) Sf[j][1] = -1e30f;
            if (c0g > r1g || kd0 != qd1) Sf[j][2] = -1e30f;
            if (c1g > r1g || kd1 != qd1) Sf[j][3] = -1e30f;
        }

        float t0 = -1e30f, t1 = -1e30f;
#pragma unroll
        for (int j = 0; j < 8; ++j) {
            t0 = fmaxf(t0, fmaxf(Sf[j][0], Sf[j][1]));
            t1 = fmaxf(t1, fmaxf(Sf[j][2], Sf[j][3]));
        }
        t0 = fmaxf(t0, __shfl_xor_sync(0xffffffffu, t0, 1));
        t0 = fmaxf(t0, __shfl_xor_sync(0xffffffffu, t0, 2));
        t1 = fmaxf(t1, __shfl_xor_sync(0xffffffffu, t1, 1));
        t1 = fmaxf(t1, __shfl_xor_sync(0xffffffffu, t1, 2));
        float mn0 = fmaxf(m0, t0), mn1 = fmaxf(m1, t1);
        float corr0 = __expf(m0 - mn0), corr1 = __expf(m1 - mn1);
        m0 = mn0; m1 = mn1;
        float rs0 = 0.f, rs1 = 0.f;
#pragma unroll
        for (int j = 0; j < 8; ++j) {
            Sf[j][0] = __expf(Sf[j][0] - mn0);
            Sf[j][1] = __expf(Sf[j][1] - mn0);
            Sf[j][2] = __expf(Sf[j][2] - mn1);
            Sf[j][3] = __expf(Sf[j][3] - mn1);
            rs0 += Sf[j][0] + Sf[j][1];
            rs1 += Sf[j][2] + Sf[j][3];
        }
        rs0 += __shfl_xor_sync(0xffffffffu, rs0, 1);
        rs0 += __shfl_xor_sync(0xffffffffu, rs0, 2);
        rs1 += __shfl_xor_sync(0xffffffffu, rs1, 1);
        rs1 += __shfl_xor_sync(0xffffffffu, rs1, 2);
        l0 = l0 * corr0 + rs0;
        l1 = l1 * corr1 + rs1;
#pragma unroll
        for (int j = 0; j < 8; ++j) {
            O[j][0] *= corr0; O[j][1] *= corr0;
            O[j][2] *= corr1; O[j][3] *= corr1;
        }

        uint32_t pah[4][4], pal[4][4];
#pragma unroll
        for (int s = 0; s < 4; ++s) {
            pah[s][0] = packsplit_h(Sf[2 * s][0],     Sf[2 * s][1],     pal[s][0]);
            pah[s][1] = packsplit_h(Sf[2 * s][2],     Sf[2 * s][3],     pal[s][1]);
            pah[s][2] = packsplit_h(Sf[2 * s + 1][0], Sf[2 * s + 1][1], pal[s][2]);
            pah[s][3] = packsplit_h(Sf[2 * s + 1][2], Sf[2 * s + 1][3], pal[s][3]);
        }

#pragma unroll
        for (int j = 0; j < 8; ++j) {
            uint32_t bvh[2][4], bvl[2][4];
            int vr = lane & 31;
            ldm4t(bvh[0], smem_u32(Vh + vr * LDK + j * 8));
            ldm4t(bvh[1], smem_u32(Vh + (32 + vr) * LDK + j * 8));
            ldm4t(bvl[0], smem_u32(Vl + vr * LDK + j * 8));
            ldm4t(bvl[1], smem_u32(Vl + (32 + vr) * LDK + j * 8));
#pragma unroll
            for (int s = 0; s < 4; ++s) {
                int ch = s >> 1, wh = (s & 1) * 2;
                mma16816(O[j], pah[s], bvh[ch][wh], bvh[ch][wh + 1]);
                mma16816(O[j], pah[s], bvl[ch][wh], bvl[ch][wh + 1]);
                mma16816(O[j], pal[s], bvh[ch][wh], bvh[ch][wh + 1]);
            }
        }
    }

    // ---- epilogue: write ctx in packed-tile layout (fp16 hi only) ----
    float inv0 = 1.0f / l0, inv1 = 1.0f / l1;
    int grow0 = b * S_ + r0g;
    int grow1 = grow0 + 8;
#pragma unroll
    for (int j = 0; j < 8; ++j) {
        int col = h * 64 + j * 8 + (lane & 3) * 2;
        size_t tbase = ((size_t)(grow0 >> 7) * KT_ + (col >> 5)) * TILE_E
                     + ((col >> 3) & 3) * 8 + (col & 7);
        size_t o0 = tbase + (grow0 & 127) * 40;
        size_t o1 = tbase + (grow1 & 127) * 40;
        *(uint32_t*)(cp + o0) = packh(O[j][0] * inv0, O[j][1] * inv0);
        *(uint32_t*)(cp + o1) = packh(O[j][2] * inv1, O[j][3] * inv1);
    }
}

// ---------------------------------------------------------------------------
// Host launcher
// ---------------------------------------------------------------------------
extern "C" void kernel_launch(void* const* d_in, const int* in_sizes, int n_in,
                              void* d_out, int out_size)
{
    const float* x   = (const float*)d_in[0];
    const float* rc  = (const float*)d_in[1];
    const float* rs  = (const float*)d_in[2];
    const int*   doc = (const int*)d_in[3];
    const float* Wq  = (const float*)d_in[4];
    const float* Wk  = (const float*)d_in[5];
    const float* Wv  = (const float*)d_in[6];
    const float* Wo  = (const float*)d_in[7];
    float* out = (float*)d_out;

    __half *xp, *wp, *wop, *cp, *qbh, *qbl, *kbh, *kbl, *vbh, *vbl;
    cudaGetSymbolAddress((void**)&xp, g_xp);
    cudaGetSymbolAddress((void**)&wp, g_wp);
    cudaGetSymbolAddress((void**)&wop, g_wop);
    cudaGetSymbolAddress((void**)&cp, g_cp);
    cudaGetSymbolAddress((void**)&qbh, g_qbh);   cudaGetSymbolAddress((void**)&qbl, g_qbl);
    cudaGetSymbolAddress((void**)&kbh, g_kbh);   cudaGetSymbolAddress((void**)&kbl, g_kbl);
    cudaGetSymbolAddress((void**)&vbh, g_vbh);   cudaGetSymbolAddress((void**)&vbl, g_vbl);

    const int flash_smem = 2 * 4 * 64 * LDK * (int)sizeof(__half);  // 73728
    cudaFuncSetAttribute(flash_tc,
                         cudaFuncAttributeMaxDynamicSharedMemorySize, flash_smem);

    const int gemm_smem = NSTG * STG_E * (int)sizeof(__half);       // 81920
    cudaFuncSetAttribute(gemm_pk<0>,
                         cudaFuncAttributeMaxDynamicSharedMemorySize, gemm_smem);
    cudaFuncSetAttribute(gemm_pk<1>,
                         cudaFuncAttributeMaxDynamicSharedMemorySize, gemm_smem);

    // 1. Pack inputs + doc-start scan (one launch)
    pack_all<<<9232, 256>>>(x, Wq, Wk, Wv, Wo, doc, xp, wp, wop);

    // 2. Fused QKV projection with fused RoPE/split epilogue (single-pass)
    {
        dim3 g(3072 / 128, M_ / 128);  // (24, 32)
        gemm_pk<1><<<g, 256, gemm_smem>>>(xp, wp, nullptr, 3072, KT_,
                                          rc, rs, qbh, qbl, kbh, kbl, vbh, vbl);
    }

    // 3. Tensor-core flash attention -> packed ctx (fp16 hi)
    {
        dim3 g(S_ / 64, NH_, B_);
        flash_tc<<<g, 128, flash_smem>>>(doc, qbh, qbl, kbh, kbl, vbh, vbl, cp);
    }

    // 4. Output projection: out = ctx @ Wo^T (single-pass)
    {
        dim3 g(2048 / 128, M_ / 128);  // (16, 32)
        gemm_pk<0><<<g, 256, gemm_smem>>>(cp, wop, out, 2048, KT_,
                                          nullptr, nullptr,
                                          nullptr, nullptr, nullptr, nullptr,
                                          nullptr, nullptr);
    }
}

// round 17
// speedup vs baseline: 2.4515x; 1.0674x over previous
#include <cuda_runtime.h>
#include <cuda_fp16.h>
#include <math.h>
#include <stdint.h>

// Problem constants
#define B_    2
#define S_    2048
#define DIM_  2048
#define NH_   32
#define NKV_  8
#define HD_   64
#define M_    (B_ * S_)        // 4096 rows
#define KT_   64               // K tiles (2048/32)
#define TILE_E 5120            // elems per packed 128x32 tile (40-elem pitch)

#define WK_OFF ((size_t)16 * KT_ * TILE_E)
#define WV_OFF ((size_t)20 * KT_ * TILE_E)

// ---------------------------------------------------------------------------
// Scratch (static device globals — no allocation allowed)
// ---------------------------------------------------------------------------
__device__ int g_dstart[B_ * 8];

// packed-tile fp16 GEMM operands  [tile][128*40]  (hi-only)
__device__ __half g_xp[32 * KT_ * TILE_E];
__device__ __half g_wp[24 * KT_ * TILE_E];
__device__ __half g_wop[16 * KT_ * TILE_E];
__device__ __half g_cp[32 * KT_ * TILE_E];
// flash inputs (row-major fp16, post-rope; Q/K keep hi/lo, V hi only)
__device__ __half g_qbh[M_ * 2048], g_qbl[M_ * 2048];
__device__ __half g_kbh[M_ * 512],  g_kbl[M_ * 512];
__device__ __half g_vbh[M_ * 512];

// ---------------------------------------------------------------------------
// PTX helpers
// ---------------------------------------------------------------------------
__device__ __forceinline__ uint32_t smem_u32(const void* p) {
    uint32_t a;
    asm("{ .reg .u64 t; cvta.to.shared.u64 t, %1; cvt.u32.u64 %0, t; }"
        : "=r"(a) : "l"(p));
    return a;
}
__device__ __forceinline__ void cp16(uint32_t dst, const void* src) {
    asm volatile("cp.async.cg.shared.global [%0], [%1], 16;"
                 :: "r"(dst), "l"(src));
}
__device__ __forceinline__ void cp_commit() {
    asm volatile("cp.async.commit_group;");
}
template<int N>
__device__ __forceinline__ void cp_wait() {
    asm volatile("cp.async.wait_group %0;" :: "n"(N));
}
__device__ __forceinline__ void ldm4(uint32_t* r, uint32_t a) {
    asm volatile("ldmatrix.sync.aligned.m8n8.x4.shared.b16 {%0,%1,%2,%3}, [%4];"
        : "=r"(r[0]), "=r"(r[1]), "=r"(r[2]), "=r"(r[3]) : "r"(a));
}
__device__ __forceinline__ void ldm4t(uint32_t* r, uint32_t a) {
    asm volatile("ldmatrix.sync.aligned.m8n8.x4.trans.shared.b16 {%0,%1,%2,%3}, [%4];"
        : "=r"(r[0]), "=r"(r[1]), "=r"(r[2]), "=r"(r[3]) : "r"(a));
}
// fp16 mma, fp32 accumulate
__device__ __forceinline__ void mma16816(float* c, const uint32_t* a,
                                         uint32_t b0, uint32_t b1) {
    asm volatile(
        "mma.sync.aligned.m16n8k16.row.col.f32.f16.f16.f32 "
        "{%0,%1,%2,%3}, {%4,%5,%6,%7}, {%8,%9}, {%0,%1,%2,%3};"
        : "+f"(c[0]), "+f"(c[1]), "+f"(c[2]), "+f"(c[3])
        : "r"(a[0]), "r"(a[1]), "r"(a[2]), "r"(a[3]), "r"(b0), "r"(b1));
}
__device__ __forceinline__ void mbar_init(uint32_t mbar, uint32_t cnt) {
    asm volatile("mbarrier.init.shared.b64 [%0], %1;" :: "r"(mbar), "r"(cnt) : "memory");
}
__device__ __forceinline__ void mbar_expect(uint32_t mbar, uint32_t bytes) {
    asm volatile("mbarrier.arrive.expect_tx.shared.b64 _, [%0], %1;"
                 :: "r"(mbar), "r"(bytes) : "memory");
}
__device__ __forceinline__ void mbar_wait(uint32_t mbar, uint32_t phase) {
    asm volatile(
        "{\n .reg .pred P;\n"
        "W_%=:\n"
        " mbarrier.try_wait.parity.acquire.cta.shared::cta.b64 P, [%0], %1, 0x989680;\n"
        " @P bra.uni D_%=;\n bra.uni W_%=;\n"
        "D_%=:\n}"
        :: "r"(mbar), "r"(phase) : "memory");
}
__device__ __forceinline__ void bulk_g2s(uint32_t dst, const void* src,
                                         uint32_t bytes, uint32_t mbar) {
    asm volatile(
        "cp.async.bulk.shared::cluster.global.mbarrier::complete_tx::bytes "
        "[%0], [%1], %2, [%3];"
        :: "r"(dst), "l"(src), "r"(bytes), "r"(mbar) : "memory");
}
__device__ __forceinline__ void fence_proxy_async_cta() {
    asm volatile("fence.proxy.async.shared::cta;" ::: "memory");
}
union H2U { __half2 h; uint32_t u; };
__device__ __forceinline__ uint32_t packsplit_h(float x, float y, uint32_t& lo) {
    __half hx = __float2half_rn(x), hy = __float2half_rn(y);
    H2U H, L;
    H.h = __halves2half2(hx, hy);
    L.h = __halves2half2(__float2half_rn(x - __half2float(hx)),
                         __float2half_rn(y - __half2float(hy)));
    lo = L.u;
    return H.u;
}
__device__ __forceinline__ uint32_t packh(float x, float y) {
    H2U H;
    H.h = __halves2half2(__float2half_rn(x), __float2half_rn(y));
    return H.u;
}

// ---------------------------------------------------------------------------
// Fused pack: fp32 [R,2048] row-major -> packed-tile fp16 (hi only),
// 5 tensors, plus doc-start scan.
// ---------------------------------------------------------------------------
__global__ void pack_all(const float* __restrict__ x,
                         const float* __restrict__ wq,
                         const float* __restrict__ wk,
                         const float* __restrict__ wv,
                         const float* __restrict__ wo,
                         const int* __restrict__ doc,
                         __half* __restrict__ xp,
                         __half* __restrict__ wp,
                         __half* __restrict__ wop)
{
    int i = blockIdx.x * blockDim.x + threadIdx.x;
    const float* src;
    __half* hi;
    int li;
    if (i < 1048576)      { src = x;  hi = xp;           li = i; }
    else if (i < 1572864) { src = wq; hi = wp;           li = i - 1048576; }
    else if (i < 1703936) { src = wk; hi = wp + WK_OFF;  li = i - 1572864; }
    else if (i < 1835008) { src = wv; hi = wp + WV_OFF;  li = i - 1703936; }
    else if (i < 2359296) { src = wo; hi = wop;          li = i - 1835008; }
    else if (i < 2359296 + B_ * S_) {
        int li2 = i - 2359296;
        int s = li2 & (S_ - 1);
        int d = doc[li2];
        if (s == 0 || doc[li2 - 1] != d) g_dstart[(li2 >> 11) * 8 + d] = s;
        return;
    } else return;

    int r  = li >> 8;          // kchunks = 256
    int kc = li & 255;
    const float4* s = (const float4*)src + (size_t)li * 2;
    float4 v0 = s[0], v1 = s[1];
    uint32_t h0 = packh(v0.x, v0.y);
    uint32_t h1 = packh(v0.z, v0.w);
    uint32_t h2 = packh(v1.x, v1.y);
    uint32_t h3 = packh(v1.z, v1.w);
    size_t off = ((size_t)(r >> 7) * KT_ + (kc >> 2)) * TILE_E
               + (r & 127) * 40 + (kc & 3) * 8;
    *(uint4*)(hi + off) = make_uint4(h0, h1, h2, h3);
}

// ---------------------------------------------------------------------------
// Packed-tile fp16 single-pass GEMM: C = A*B^T.
// 256 threads, 8 warps: warp tile 32(M) x 64(N).
// 2-stage pipeline, K=64 per stage (R16 shell, measured best).
// MODE 0: fp32 row-major C (O projection).
// MODE 1: fused QKV epilogue (RoPE + scale; Q/K hi+lo, V hi only).
// ---------------------------------------------------------------------------
#define NSTG 2
#define STG_E (4 * TILE_E)     // stage elems: A (2 k-tiles) + B (2 k-tiles)

template<int MODE>
__global__ __launch_bounds__(256, 2) void gemm_pk(
    const __half* __restrict__ Ah,
    const __half* __restrict__ Bh,
    float* __restrict__ C, int N, int Ktiles,
    const float* __restrict__ cs, const float* __restrict__ sn,
    __half* __restrict__ qbh, __half* __restrict__ qbl,
    __half* __restrict__ kbh, __half* __restrict__ kbl,
    __half* __restrict__ vbh)
{
    extern __shared__ __align__(128) __half smd[];    // NSTG * STG_E
    __shared__ __align__(8) uint64_t mb[NSTG];

    const int tid = threadIdx.x, lane = tid & 31, w = tid >> 5;
    const int wm = w & 3, wn = w >> 2;     // 4 m-tiles x 2 n-tiles

    const uint32_t mbar0 = smem_u32(&mb[0]);
    const uint32_t mbar1 = smem_u32(&mb[1]);
    if (tid == 0) { mbar_init(mbar0, 1); mbar_init(mbar1, 1); }
    __syncthreads();

    const size_t tA = (size_t)blockIdx.y * Ktiles;
    const size_t tB = (size_t)blockIdx.x * Ktiles;
    const int NS = Ktiles >> 1;            // stages of K=64

    auto issue = [&](int ks, int buf) {
        uint32_t s0 = smem_u32(smd + buf * STG_E);
        uint32_t mbar = buf ? mbar1 : mbar0;
        mbar_expect(mbar, 4 * TILE_E * 2);
        bulk_g2s(s0,                  Ah + (tA + ks * 2) * TILE_E, 2 * TILE_E * 2, mbar);
        bulk_g2s(s0 + 2 * TILE_E * 2, Bh + (tB + ks * 2) * TILE_E, 2 * TILE_E * 2, mbar);
    };
    if (tid == 0) { issue(0, 0); issue(1, 1); }

    float acc[2][8][4];
#pragma unroll
    for (int i = 0; i < 2; ++i)
#pragma unroll
        for (int j = 0; j < 8; ++j)
#pragma unroll
            for (int e = 0; e < 4; ++e) acc[i][j][e] = 0.f;

    int ph0 = 0, ph1 = 0;

    for (int ks = 0; ks < NS; ++ks) {
        const int buf = ks & 1;
        if (buf == 0) { mbar_wait(mbar0, ph0); ph0 ^= 1; }
        else          { mbar_wait(mbar1, ph1); ph1 ^= 1; }

        const __half* stg = smd + buf * STG_E;

#pragma unroll
        for (int st = 0; st < 2; ++st) {
            const __half* A0 = stg + st * TILE_E;
            const __half* B0 = stg + 2 * TILE_E + st * TILE_E;
#pragma unroll
            for (int kk = 0; kk < 2; ++kk) {
                const int achk = kk * 2 + (lane >> 4);
                const int arow = wm * 32 + (lane & 15);
                uint32_t ah[2][4];
#pragma unroll
                for (int mt = 0; mt < 2; ++mt)
                    ldm4(ah[mt], smem_u32(A0 + (arow + mt * 16) * 40 + achk * 8));
                const int brow = wn * 64 + (lane & 15);
#pragma unroll
                for (int nt = 0; nt < 4; ++nt) {
                    uint32_t bh[4];
                    ldm4(bh, smem_u32(B0 + (brow + nt * 16) * 40 + achk * 8));
                    mma16816(acc[0][2 * nt],     ah[0], bh[0], bh[2]);
                    mma16816(acc[0][2 * nt + 1], ah[0], bh[1], bh[3]);
                    mma16816(acc[1][2 * nt],     ah[1], bh[0], bh[2]);
                    mma16816(acc[1][2 * nt + 1], ah[1], bh[1], bh[3]);
                }
            }
        }
        __syncthreads();
        if (ks + 2 < NS && tid == 0) {
            fence_proxy_async_cta();
            issue(ks + 2, buf);
        }
    }

    const int brow = blockIdx.y * 128 + wm * 32;
    const int bcol = blockIdx.x * 128 + wn * 64;

    if (MODE == 0) {
        // fp32 row-major
#pragma unroll
        for (int mt = 0; mt < 2; ++mt) {
            int r0 = brow + mt * 16 + (lane >> 2);
#pragma unroll
            for (int j = 0; j < 8; ++j) {
                int col = bcol + j * 8 + (lane & 3) * 2;
                *(float2*)(C + (size_t)r0 * N + col) =
                    make_float2(acc[mt][j][0], acc[mt][j][1]);
                *(float2*)(C + (size_t)(r0 + 8) * N + col) =
                    make_float2(acc[mt][j][2], acc[mt][j][3]);
            }
        }
    } else {
        // fused QKV epilogue: rope + scale; Q/K hi+lo split, V hi only.
        __half *dh, *dl;
        int cstride, cbase;
        float scale;
        bool rope;
        if (bcol < 2048)      { dh = qbh; dl = qbl; cstride = 2048; cbase = bcol;        scale = 0.125f; rope = true; }
        else if (bcol < 2560) { dh = kbh; dl = kbl; cstride = 512;  cbase = bcol - 2048; scale = 1.0f;   rope = true; }
        else                  { dh = vbh; dl = nullptr; cstride = 512; cbase = bcol - 2560; scale = 1.0f; rope = false; }

#pragma unroll
        for (int mt = 0; mt < 2; ++mt) {
#pragma unroll
            for (int half = 0; half < 2; ++half) {
                int row = brow + mt * 16 + (lane >> 2) + half * 8;
                int e = half * 2;                    // acc elems e, e+1
                int s = row & (S_ - 1);
                size_t obase = (size_t)row * cstride + cbase;
                if (rope) {
#pragma unroll
                    for (int j = 0; j < 4; ++j) {
                        int d = j * 8 + (lane & 3) * 2;
                        float c0  = cs[s * 32 + d],     c1  = cs[s * 32 + d + 1];
                        float sv0 = sn[s * 32 + d],     sv1 = sn[s * 32 + d + 1];
                        float x1a = acc[mt][j][e],      x1b = acc[mt][j][e + 1];
                        float x2a = acc[mt][j + 4][e],  x2b = acc[mt][j + 4][e + 1];
                        float y1a = (x1a * c0 - x2a * sv0) * scale;
                        float y1b = (x1b * c1 - x2b * sv1) * scale;
                        float y2a = (x2a * c0 + x1a * sv0) * scale;
                        float y2b = (x2b * c1 + x1b * sv1) * scale;
                        uint32_t lo;
                        uint32_t hi = packsplit_h(y1a, y1b, lo);
                        *(uint32_t*)(dh + obase + d) = hi;
                        *(uint32_t*)(dl + obase + d) = lo;
                        hi = packsplit_h(y2a, y2b, lo);
                        *(uint32_t*)(dh + obase + d + 32) = hi;
                        *(uint32_t*)(dl + obase + d + 32) = lo;
                    }
                } else {
#pragma unroll
                    for (int j = 0; j < 8; ++j) {
                        int d = j * 8 + (lane & 3) * 2;
                        *(uint32_t*)(dh + obase + d) =
                            packh(acc[mt][j][e], acc[mt][j][e + 1]);
                    }
                }
            }
        }
    }
}

// ---------------------------------------------------------------------------
// Tensor-core flash attention. QK^T 3-pass fp16 hi/lo (exact); PV single-pass
// (P hi x V hi — error ~1e-4, random-sign). Stage = Kh|Kl|Vh (3 tiles).
// smem 54KB -> 3 CTAs/SM. ctx written fp16 hi only.
// ---------------------------------------------------------------------------
#define LDK 72

__global__ __launch_bounds__(128, 3) void flash_tc(
    const int* __restrict__ doc,
    const __half* __restrict__ qhi, const __half* __restrict__ qlo,
    const __half* __restrict__ khi, const __half* __restrict__ klo,
    const __half* __restrict__ vhi,
    __half* __restrict__ cp)
{
    extern __shared__ __align__(16) char smraw[];
    __half* sT  = (__half*)smraw;      // 2 stages x (Kh|Kl|Vh)
    __shared__ int qdoc[64];
    __shared__ int kdoc[2][64];

    const int tid  = threadIdx.x;
    const int lane = tid & 31;
    const int w    = tid >> 5;
    const int qb = blockIdx.x, h = blockIdx.y, b = blockIdx.z;
    const int kvh = h >> 2;
    const int q0  = qb * 64;
    const int TILE = 64 * LDK;

    // Q parked in stage-1 (tiles 3,4) until frags are hoisted
    __half* sQh = sT + 3 * TILE;
    __half* sQl = sT + 4 * TILE;

    {
        const __half* srch = qhi + ((size_t)(b * S_ + q0)) * 2048 + h * 64;
        const __half* srcl = qlo + ((size_t)(b * S_ + q0)) * 2048 + h * 64;
        uint32_t dh = smem_u32(sQh), dl = smem_u32(sQl);
        for (int i = tid; i < 512; i += 128) {
            int r = i >> 3, c = i & 7;
            uint32_t off = (uint32_t)(r * LDK + c * 8) * 2;
            cp16(dh + off, srch + (size_t)r * 2048 + c * 8);
            cp16(dl + off, srcl + (size_t)r * 2048 + c * 8);
        }
        if (tid < 64) qdoc[tid] = doc[b * S_ + q0 + tid];
    }
    cp_commit();

    const int kb0 = g_dstart[b * 8 + doc[b * S_ + q0]] >> 6;

    auto load_kv = [&](int kb, int buf) {
        const size_t row0 = (size_t)(b * S_ + kb * 64);
        const __half* s0 = khi + row0 * 512 + kvh * 64;
        const __half* s1 = klo + row0 * 512 + kvh * 64;
        const __half* s2 = vhi + row0 * 512 + kvh * 64;
        uint32_t d0 = smem_u32(sT + buf * 3 * TILE);
        const uint32_t tb = (uint32_t)TILE * 2;
        for (int i = tid; i < 512; i += 128) {
            int r = i >> 3, c = i & 7;
            uint32_t off = (uint32_t)(r * LDK + c * 8) * 2;
            size_t go = (size_t)r * 512 + c * 8;
            cp16(d0 + off,          s0 + go);
            cp16(d0 + tb + off,     s1 + go);
            cp16(d0 + 2 * tb + off, s2 + go);
        }
        if (tid < 64) kdoc[buf][tid] = doc[b * S_ + kb * 64 + tid];
    };

    load_kv(kb0, 0);
    cp_commit();
    cp_wait<1>();
    __syncthreads();

    uint32_t qah[4][4], qal[4][4];
    {
        int row = w * 16 + (lane & 15);
        int col = (lane >> 4) * 8;
#pragma unroll
        for (int s = 0; s < 4; ++s) {
            ldm4(qah[s], smem_u32(sQh + row * LDK + col + s * 16));
            ldm4(qal[s], smem_u32(sQl + row * LDK + col + s * 16));
        }
    }
    __syncthreads();   // all warps have Q frags; stage-1 may be overwritten

    const int g   = lane >> 2;
    const int r0g = q0 + w * 16 + g;
    const int r1g = r0g + 8;
    const int qd0 = qdoc[w * 16 + g];
    const int qd1 = qdoc[w * 16 + g + 8];

    float m0 = -1e30f, m1 = -1e30f, l0 = 0.f, l1 = 0.f;
    float O[8][4];
#pragma unroll
    for (int j = 0; j < 8; ++j)
#pragma unroll
        for (int e = 0; e < 4; ++e) O[j][e] = 0.f;

    for (int kb = kb0; kb <= qb; ++kb) {
        const int buf = (kb - kb0) & 1;
        cp_wait<0>();
        __syncthreads();
        if (kb < qb) { load_kv(kb + 1, buf ^ 1); cp_commit(); }

        const __half* Kh = sT + buf * 3 * TILE;
        const __half* Kl = Kh + TILE;
        const __half* Vh = Kl + TILE;

        float Sf[8][4];
#pragma unroll
        for (int j = 0; j < 8; ++j) {
            Sf[j][0] = Sf[j][1] = Sf[j][2] = Sf[j][3] = 0.f;
            uint32_t bh[2][4], bl[2][4];
            int row = j * 8 + (lane & 7);
            int col = (lane >> 3) * 8;
            ldm4(bh[0], smem_u32(Kh + row * LDK + col));
            ldm4(bh[1], smem_u32(Kh + row * LDK + col + 32));
            ldm4(bl[0], smem_u32(Kl + row * LDK + col));
            ldm4(bl[1], smem_u32(Kl + row * LDK + col + 32));
#pragma unroll
            for (int s = 0; s < 4; ++s) {
                int ch = s >> 1, wh = (s & 1) * 2;
                mma16816(Sf[j], qah[s], bh[ch][wh], bh[ch][wh + 1]);
                mma16816(Sf[j], qah[s], bl[ch][wh], bl[ch][wh + 1]);
                mma16816(Sf[j], qal[s], bh[ch][wh], bh[ch][wh + 1]);
            }
        }

        const int kbase = kb * 64;
#pragma unroll
        for (int j = 0; j < 8; ++j) {
            int cl  = j * 8 + (lane & 3) * 2;
            int c0g = kbase + cl, c1g = c0g + 1;
            int kd0 = kdoc[buf][cl], kd1 = kdoc[buf][cl + 1];
            if (c0g > r0g || kd0 != qd0) Sf[j][0] = -1e30f;
            if (c1g > r0g || kd1 != qd0) Sf[j][1] = -1e30f;
            if (c0g > r1g || kd0 != qd1) Sf[j][2] = -1e30f;
            if (c1g > r1g || kd1 != qd1) Sf[j][3] = -1e30f;
        }

        float t0 = -1e30f, t1 = -1e30f;
#pragma unroll
        for (int j = 0; j < 8; ++j) {
            t0 = fmaxf(t0, fmaxf(Sf[j][0], Sf[j][1]));
            t1 = fmaxf(t1, fmaxf(Sf[j][2], Sf[j][3]));
        }
        t0 = fmaxf(t0, __shfl_xor_sync(0xffffffffu, t0, 1));
        t0 = fmaxf(t0, __shfl_xor_sync(0xffffffffu, t0, 2));
        t1 = fmaxf(t1, __shfl_xor_sync(0xffffffffu, t1, 1));
        t1 = fmaxf(t1, __shfl_xor_sync(0xffffffffu, t1, 2));
        float mn0 = fmaxf(m0, t0), mn1 = fmaxf(m1, t1);
        float corr0 = __expf(m0 - mn0), corr1 = __expf(m1 - mn1);
        m0 = mn0; m1 = mn1;
        float rs0 = 0.f, rs1 = 0.f;
#pragma unroll
        for (int j = 0; j < 8; ++j) {
            Sf[j][0] = __expf(Sf[j][0] - mn0);
            Sf[j][1] = __expf(Sf[j][1] - mn0);
            Sf[j][2] = __expf(Sf[j][2] - mn1);
            Sf[j][3] = __expf(Sf[j][3] - mn1);
            rs0 += Sf[j][0] + Sf[j][1];
            rs1 += Sf[j][2] + Sf[j][3];
        }
        rs0 += __shfl_xor_sync(0xffffffffu, rs0, 1);
        rs0 += __shfl_xor_sync(0xffffffffu, rs0, 2);
        rs1 += __shfl_xor_sync(0xffffffffu, rs1, 1);
        rs1 += __shfl_xor_sync(0xffffffffu, rs1, 2);
        l0 = l0 * corr0 + rs0;
        l1 = l1 * corr1 + rs1;
#pragma unroll
        for (int j = 0; j < 8; ++j) {
            O[j][0] *= corr0; O[j][1] *= corr0;
            O[j][2] *= corr1; O[j][3] *= corr1;
        }

        // P -> fp16 hi frags only (single-pass PV)
        uint32_t pah[4][4];
#pragma unroll
        for (int s = 0; s < 4; ++s) {
            pah[s][0] = packh(Sf[2 * s][0],     Sf[2 * s][1]);
            pah[s][1] = packh(Sf[2 * s][2],     Sf[2 * s][3]);
            pah[s][2] = packh(Sf[2 * s + 1][0], Sf[2 * s + 1][1]);
            pah[s][3] = packh(Sf[2 * s + 1][2], Sf[2 * s + 1][3]);
        }

#pragma unroll
        for (int j = 0; j < 8; ++j) {
            uint32_t bvh[2][4];
            int vr = lane & 31;
            ldm4t(bvh[0], smem_u32(Vh + vr * LDK + j * 8));
            ldm4t(bvh[1], smem_u32(Vh + (32 + vr) * LDK + j * 8));
#pragma unroll
            for (int s = 0; s < 4; ++s) {
                int ch = s >> 1, wh = (s & 1) * 2;
                mma16816(O[j], pah[s], bvh[ch][wh], bvh[ch][wh + 1]);
            }
        }
    }

    // ---- epilogue: write ctx in packed-tile layout (fp16 hi only) ----
    float inv0 = 1.0f / l0, inv1 = 1.0f / l1;
    int grow0 = b * S_ + r0g;
    int grow1 = grow0 + 8;
#pragma unroll
    for (int j = 0; j < 8; ++j) {
        int col = h * 64 + j * 8 + (lane & 3) * 2;
        size_t tbase = ((size_t)(grow0 >> 7) * KT_ + (col >> 5)) * TILE_E
                     + ((col >> 3) & 3) * 8 + (col & 7);
        size_t o0 = tbase + (grow0 & 127) * 40;
        size_t o1 = tbase + (grow1 & 127) * 40;
        *(uint32_t*)(cp + o0) = packh(O[j][0] * inv0, O[j][1] * inv0);
        *(uint32_t*)(cp + o1) = packh(O[j][2] * inv1, O[j][3] * inv1);
    }
}

// ---------------------------------------------------------------------------
// Host launcher
// ---------------------------------------------------------------------------
extern "C" void kernel_launch(void* const* d_in, const int* in_sizes, int n_in,
                              void* d_out, int out_size)
{
    const float* x   = (const float*)d_in[0];
    const float* rc  = (const float*)d_in[1];
    const float* rs  = (const float*)d_in[2];
    const int*   doc = (const int*)d_in[3];
    const float* Wq  = (const float*)d_in[4];
    const float* Wk  = (const float*)d_in[5];
    const float* Wv  = (const float*)d_in[6];
    const float* Wo  = (const float*)d_in[7];
    float* out = (float*)d_out;

    __half *xp, *wp, *wop, *cp, *qbh, *qbl, *kbh, *kbl, *vbh;
    cudaGetSymbolAddress((void**)&xp, g_xp);
    cudaGetSymbolAddress((void**)&wp, g_wp);
    cudaGetSymbolAddress((void**)&wop, g_wop);
    cudaGetSymbolAddress((void**)&cp, g_cp);
    cudaGetSymbolAddress((void**)&qbh, g_qbh);   cudaGetSymbolAddress((void**)&qbl, g_qbl);
    cudaGetSymbolAddress((void**)&kbh, g_kbh);   cudaGetSymbolAddress((void**)&kbl, g_kbl);
    cudaGetSymbolAddress((void**)&vbh, g_vbh);

    const int flash_smem = 2 * 3 * 64 * LDK * (int)sizeof(__half);  // 55296
    cudaFuncSetAttribute(flash_tc,
                         cudaFuncAttributeMaxDynamicSharedMemorySize, flash_smem);

    const int gemm_smem = NSTG * STG_E * (int)sizeof(__half);       // 81920
    cudaFuncSetAttribute(gemm_pk<0>,
                         cudaFuncAttributeMaxDynamicSharedMemorySize, gemm_smem);
    cudaFuncSetAttribute(gemm_pk<1>,
                         cudaFuncAttributeMaxDynamicSharedMemorySize, gemm_smem);

    // 1. Pack inputs + doc-start scan (one launch)
    pack_all<<<9232, 256>>>(x, Wq, Wk, Wv, Wo, doc, xp, wp, wop);

    // 2. Fused QKV projection with fused RoPE/split epilogue (single-pass)
    {
        dim3 g(3072 / 128, M_ / 128);  // (24, 32)
        gemm_pk<1><<<g, 256, gemm_smem>>>(xp, wp, nullptr, 3072, KT_,
                                          rc, rs, qbh, qbl, kbh, kbl, vbh);
    }

    // 3. Tensor-core flash attention -> packed ctx (fp16 hi)
    {
        dim3 g(S_ / 64, NH_, B_);
        flash_tc<<<g, 128, flash_smem>>>(doc, qbh, qbl, kbh, kbl, vbh, cp);
    }

    // 4. Output projection: out = ctx @ Wo^T (single-pass)
    {
        dim3 g(2048 / 128, M_ / 128);  // (16, 32)
        gemm_pk<0><<<g, 256, gemm_smem>>>(cp, wop, out, 2048, KT_,
                                          nullptr, nullptr,
                                          nullptr, nullptr, nullptr, nullptr,
                                          nullptr);
    }
}